// round 9
// baseline (speedup 1.0000x reference)
#include <cuda_runtime.h>
#include <cuda_bf16.h>
#include <cfloat>
#include <cstdint>

#define BB_   64
#define NN_   512
#define DIM_  256
#define HH_   8
#define DHH_  64
#define INNER_ 512
#define SCALE_ 0.125f

// ---------------------------------------------------------------------------
// Scratch
// ---------------------------------------------------------------------------
__device__ float g_G[BB_*NN_*INNER_];
__device__ unsigned char g_mask[BB_*NN_];
__device__ int g_mask_mode;

__device__ __nv_bfloat16 g_xh[BB_*NN_*DIM_];
__device__ __nv_bfloat16 g_xl[BB_*NN_*DIM_];
__device__ __nv_bfloat16 g_Wch[2048*DIM_];
__device__ __nv_bfloat16 g_Wcl[2048*DIM_];
__device__ __nv_bfloat16 g_Qh[BB_*HH_*NN_*DHH_];
__device__ __nv_bfloat16 g_Ql[BB_*HH_*NN_*DHH_];
__device__ __nv_bfloat16 g_Kh[BB_*HH_*NN_*DHH_];
__device__ __nv_bfloat16 g_Kl[BB_*HH_*NN_*DHH_];
__device__ __nv_bfloat16 g_Vh[BB_*HH_*NN_*DHH_];
__device__ __nv_bfloat16 g_Vl[BB_*HH_*NN_*DHH_];
__device__ __nv_bfloat16 g_Eh[BB_*NN_*INNER_];
__device__ __nv_bfloat16 g_El[BB_*NN_*INNER_];
__device__ __nv_bfloat16 g_Woh[DIM_*INNER_];
__device__ __nv_bfloat16 g_Wol[DIM_*INNER_];

// ---------------------------------------------------------------------------
// Helpers
// ---------------------------------------------------------------------------
__device__ __forceinline__ uint32_t smem_u32(const void* p) {
  uint32_t a;
  asm("{ .reg .u64 t; cvta.to.shared.u64 t, %1; cvt.u32.u64 %0, t; }"
      : "=r"(a) : "l"(p));
  return a;
}
__device__ __forceinline__ void cp16(uint32_t saddr, const void* g) {
  asm volatile("cp.async.cg.shared.global [%0], [%1], 16;"
               :: "r"(saddr), "l"(g));
}
#define CP_COMMIT() asm volatile("cp.async.commit_group;" ::: "memory")
#define CP_WAIT(n)  asm volatile("cp.async.wait_group %0;" :: "n"(n) : "memory")

__device__ __forceinline__ void ldsm_x4(uint32_t addr, uint32_t& r0,
                                        uint32_t& r1, uint32_t& r2, uint32_t& r3) {
  asm volatile("ldmatrix.sync.aligned.m8n8.x4.shared.b16 {%0,%1,%2,%3}, [%4];"
               : "=r"(r0), "=r"(r1), "=r"(r2), "=r"(r3) : "r"(addr));
}
__device__ __forceinline__ void ldsm_x4_t(uint32_t addr, uint32_t& r0,
                                          uint32_t& r1, uint32_t& r2, uint32_t& r3) {
  asm volatile("ldmatrix.sync.aligned.m8n8.x4.trans.shared.b16 {%0,%1,%2,%3}, [%4];"
               : "=r"(r0), "=r"(r1), "=r"(r2), "=r"(r3) : "r"(addr));
}
__device__ __forceinline__ void mma_bf16(float* c, const uint32_t* a,
                                         const uint32_t* b) {
  asm volatile(
    "mma.sync.aligned.m16n8k16.row.col.f32.bf16.bf16.f32 "
    "{%0,%1,%2,%3}, {%4,%5,%6,%7}, {%8,%9}, {%0,%1,%2,%3};"
    : "+f"(c[0]), "+f"(c[1]), "+f"(c[2]), "+f"(c[3])
    : "r"(a[0]), "r"(a[1]), "r"(a[2]), "r"(a[3]), "r"(b[0]), "r"(b[1]));
}
__device__ __forceinline__ void split2(float v, __nv_bfloat16& h, __nv_bfloat16& l) {
  h = __float2bfloat16(v);
  l = __float2bfloat16(v - __bfloat162float(h));
}
__device__ __forceinline__ uint32_t pack2(__nv_bfloat16 a, __nv_bfloat16 b) {
  return (uint32_t)*(uint16_t*)&a | ((uint32_t)*(uint16_t*)&b << 16);
}

// ---------------------------------------------------------------------------
// Mask detection + conversion (proven)
// ---------------------------------------------------------------------------
__global__ void detect_mask_kernel(const unsigned int* __restrict__ m)
{
  __shared__ int s_not01, s_notf;
  if (threadIdx.x == 0) { s_not01 = 0; s_notf = 0; }
  __syncthreads();
  int a = 0, b = 0;
  for (int i = threadIdx.x; i < 8192; i += 256) {
    unsigned v = m[i];
    if (v != 0u && v != 1u) a = 1;
    if (v != 0u && v != 0x3F800000u) b = 1;
  }
  if (a) atomicOr(&s_not01, 1);
  if (b) atomicOr(&s_notf, 1);
  __syncthreads();
  if (threadIdx.x == 0)
    g_mask_mode = (!s_not01) ? 0 : ((!s_notf) ? 1 : 2);
}

__global__ void convert_mask_kernel(const void* __restrict__ m)
{
  int idx = blockIdx.x * blockDim.x + threadIdx.x;
  if (idx >= BB_*NN_) return;
  int mode = g_mask_mode;
  unsigned char r;
  if (mode == 0)      r = ((const int*)m)[idx] != 0;
  else if (mode == 1) r = ((const unsigned int*)m)[idx] != 0u;
  else                r = ((const unsigned char*)m)[idx] != 0;
  g_mask[idx] = r;
}

// ---------------------------------------------------------------------------
// Split conversions (proven)
// ---------------------------------------------------------------------------
__global__ void split_x_kernel(const float* __restrict__ x)
{
  int i = (blockIdx.x * 256 + threadIdx.x) * 4;
  float4 v = *(const float4*)(x + i);
  __nv_bfloat16 h[4], l[4];
  split2(v.x, h[0], l[0]); split2(v.y, h[1], l[1]);
  split2(v.z, h[2], l[2]); split2(v.w, h[3], l[3]);
  *(uint2*)(g_xh + i) = *(uint2*)h;
  *(uint2*)(g_xl + i) = *(uint2*)l;
}

__global__ void split_W_kernel(const float* __restrict__ Wq,
                               const float* __restrict__ Wkv,
                               const float* __restrict__ Wg)
{
  int idx = blockIdx.x * 256 + threadIdx.x;
  int k = idx & 255, n = idx >> 8;
  int seg = n >> 9, col = n & 511;
  float v;
  if (seg == 0)      v = Wq[k*512 + col];
  else if (seg == 1) v = Wkv[k*1024 + col];
  else if (seg == 2) v = Wkv[k*1024 + 512 + col];
  else               v = Wg[k*512 + col];
  __nv_bfloat16 h, l; split2(v, h, l);
  g_Wch[n*256 + k] = h; g_Wcl[n*256 + k] = l;
}

__global__ void split_Wo_kernel(const float* __restrict__ Wo)
{
  int idx = blockIdx.x * 256 + threadIdx.x;
  int n = idx >> 9, k = idx & 511;
  float v = Wo[k*256 + n];
  __nv_bfloat16 h, l; split2(v, h, l);
  g_Woh[n*512 + k] = h; g_Wol[n*512 + k] = l;
}

// ---------------------------------------------------------------------------
// Tile loaders
// ---------------------------------------------------------------------------
#define TSTRIDE 72
#define GTILE (128*TSTRIDE)
#define ATILE (64*TSTRIDE)

__device__ __forceinline__ void cpa_tile128_512(
    __nv_bfloat16* dst, const __nv_bfloat16* __restrict__ src, int ldk, int tid)
{
#pragma unroll
  for (int it = 0; it < 2; it++) {
    int u = it*512 + tid;
    int row = u >> 3, c8 = (u & 7) * 8;
    cp16(smem_u32(dst + row*TSTRIDE + c8), src + row*ldk + c8);
  }
}

// 64-row tile with 512 threads: exactly one cp16 per thread
__device__ __forceinline__ void cpa_tile64_512(
    __nv_bfloat16* dst, const __nv_bfloat16* __restrict__ src, int tid)
{
  int row = tid >> 3, c8 = (tid & 7) * 8;
  cp16(smem_u32(dst + row*TSTRIDE + c8), src + row*64 + c8);
}

// ---------------------------------------------------------------------------
// Dense GEMM core: block 128x128, 16 warps (4m x 4n), warp tile 32x32.
// ---------------------------------------------------------------------------
struct FragC { float c[2][4][4]; };

template <int KCHUNKS>
__device__ __forceinline__ void gemm_core(
    __nv_bfloat16* smb,
    const __nv_bfloat16* gAh, const __nv_bfloat16* gAl,
    const __nv_bfloat16* gBh, const __nv_bfloat16* gBl,
    int m0, int n0blk, int ldk, int tid, FragC& f)
{
  const int lane = tid & 31, wid = tid >> 5;
  const int wm = wid & 3, wn = wid >> 2;
  const int lrow = (lane & 7) + ((lane >> 3) & 1) * 8;
  const int lcol = (lane >> 4) * 8;

  uint32_t abase[2][2], bbase[2][2];
#pragma unroll
  for (int s = 0; s < 2; s++) {
    __nv_bfloat16* st = smb + s*4*GTILE;
    abase[s][0] = smem_u32(st)           + ((wm*32 + lrow)*TSTRIDE + lcol)*2;
    abase[s][1] = smem_u32(st + GTILE)   + ((wm*32 + lrow)*TSTRIDE + lcol)*2;
    bbase[s][0] = smem_u32(st + 2*GTILE) + ((wn*32 + lrow)*TSTRIDE + lcol)*2;
    bbase[s][1] = smem_u32(st + 3*GTILE) + ((wn*32 + lrow)*TSTRIDE + lcol)*2;
  }

#pragma unroll
  for (int mt = 0; mt < 2; mt++)
#pragma unroll
    for (int nt = 0; nt < 4; nt++)
#pragma unroll
      for (int q = 0; q < 4; q++) f.c[mt][nt][q] = 0.f;

  {
    __nv_bfloat16* st = smb;
    cpa_tile128_512(st,           gAh + m0*ldk,    ldk, tid);
    cpa_tile128_512(st + GTILE,   gAl + m0*ldk,    ldk, tid);
    cpa_tile128_512(st + 2*GTILE, gBh + n0blk*ldk, ldk, tid);
    cpa_tile128_512(st + 3*GTILE, gBl + n0blk*ldk, ldk, tid);
    CP_COMMIT();
  }

  for (int kc = 0; kc < KCHUNKS; kc++) {
    if (kc + 1 < KCHUNKS) {
      __nv_bfloat16* st = smb + ((kc+1)&1)*4*GTILE;
      int co = (kc+1)*64;
      cpa_tile128_512(st,           gAh + m0*ldk + co,    ldk, tid);
      cpa_tile128_512(st + GTILE,   gAl + m0*ldk + co,    ldk, tid);
      cpa_tile128_512(st + 2*GTILE, gBh + n0blk*ldk + co, ldk, tid);
      cpa_tile128_512(st + 3*GTILE, gBl + n0blk*ldk + co, ldk, tid);
      CP_COMMIT();
      CP_WAIT(1);
    } else {
      CP_WAIT(0);
    }
    __syncthreads();

    const int s = kc & 1;
#pragma unroll
    for (int ks = 0; ks < 4; ks++) {
      uint32_t ah[2][4], al[2][4];
#pragma unroll
      for (int mt = 0; mt < 2; mt++) {
        uint32_t off = (mt*16*TSTRIDE + ks*16)*2;
        ldsm_x4(abase[s][0] + off, ah[mt][0], ah[mt][1], ah[mt][2], ah[mt][3]);
        ldsm_x4(abase[s][1] + off, al[mt][0], al[mt][1], al[mt][2], al[mt][3]);
      }
      uint32_t bh[4][2], bl[4][2];
#pragma unroll
      for (int np = 0; np < 2; np++) {
        uint32_t off = (np*16*TSTRIDE + ks*16)*2;
        uint32_t r0, r1, r2, r3;
        ldsm_x4(bbase[s][0] + off, r0, r1, r2, r3);
        bh[2*np][0] = r0; bh[2*np+1][0] = r1; bh[2*np][1] = r2; bh[2*np+1][1] = r3;
        ldsm_x4(bbase[s][1] + off, r0, r1, r2, r3);
        bl[2*np][0] = r0; bl[2*np+1][0] = r1; bl[2*np][1] = r2; bl[2*np+1][1] = r3;
      }
#pragma unroll
      for (int mt = 0; mt < 2; mt++)
#pragma unroll
        for (int nt = 0; nt < 4; nt++) {
          mma_bf16(f.c[mt][nt], ah[mt], bh[nt]);
          mma_bf16(f.c[mt][nt], ah[mt], bl[nt]);
          mma_bf16(f.c[mt][nt], al[mt], bh[nt]);
        }
    }
    __syncthreads();
  }
}

// ---------------------------------------------------------------------------
// Projection GEMM (512 threads)
// ---------------------------------------------------------------------------
__global__ __launch_bounds__(512) void proj_mma_kernel(const float* __restrict__ bg)
{
  extern __shared__ __nv_bfloat16 smb[];
  const int tid = threadIdx.x;
  const int c0 = blockIdx.x * 128;
  const int m0 = blockIdx.y * 128;

  FragC f;
  gemm_core<4>(smb, g_xh, g_xl, g_Wch, g_Wcl, m0, c0, 256, tid, f);

  const int lane = tid & 31, wid = tid >> 5;
  const int wm = wid & 3, wn = wid >> 2;
  const int q2 = (lane & 3) * 2, r4 = lane >> 2;
  const int seg = c0 >> 9;
  const int lbase = c0 - seg*512 + wn*32;

#pragma unroll
  for (int mt = 0; mt < 2; mt++) {
#pragma unroll
    for (int h2 = 0; h2 < 2; h2++) {
      const int m = m0 + wm*32 + mt*16 + r4 + h2*8;
      const int bidx = m >> 9, n = m & 511;
      if (seg == 3) {
        float* dst = g_G + m*512 + lbase;
#pragma unroll
        for (int nt = 0; nt < 4; nt++) {
          int cc = nt*8 + q2;
          float2 v;
          v.x = f.c[mt][nt][h2*2+0] + bg[lbase + cc];
          v.y = f.c[mt][nt][h2*2+1] + bg[lbase + cc + 1];
          *(float2*)(dst + cc) = v;
        }
      } else {
        const int hh = lbase >> 6;
        const int dbase = lbase & 63;
        __nv_bfloat16 *bh_, *bl_;
        if (seg == 0)      { bh_ = g_Qh; bl_ = g_Ql; }
        else if (seg == 1) { bh_ = g_Kh; bl_ = g_Kl; }
        else               { bh_ = g_Vh; bl_ = g_Vl; }
        const int off = (((bidx*8 + hh)*512 + n)*64) + dbase;
#pragma unroll
        for (int nt = 0; nt < 4; nt++) {
          int dd = nt*8 + q2;
          __nv_bfloat16 h0, l0, h1, l1;
          split2(f.c[mt][nt][h2*2+0], h0, l0);
          split2(f.c[mt][nt][h2*2+1], h1, l1);
          *(uint32_t*)(bh_ + off + dd) = pack2(h0, h1);
          *(uint32_t*)(bl_ + off + dd) = pack2(l0, l1);
        }
      }
    }
  }
}

// ---------------------------------------------------------------------------
// Output GEMM (512 threads)
// ---------------------------------------------------------------------------
__global__ __launch_bounds__(512) void out_mma_kernel(
    const float* __restrict__ bo, float* __restrict__ Y)
{
  extern __shared__ __nv_bfloat16 smb[];
  const int tid = threadIdx.x;
  const int n0 = blockIdx.x * 128;
  const int m0 = blockIdx.y * 128;

  FragC f;
  gemm_core<8>(smb, g_Eh, g_El, g_Woh, g_Wol, m0, n0, 512, tid, f);

  const int lane = tid & 31, wid = tid >> 5;
  const int wm = wid & 3, wn = wid >> 2;
  const int q2 = (lane & 3) * 2, r4 = lane >> 2;

#pragma unroll
  for (int mt = 0; mt < 2; mt++) {
#pragma unroll
    for (int h2 = 0; h2 < 2; h2++) {
      const int m = m0 + wm*32 + mt*16 + r4 + h2*8;
      float* dst = Y + m*256 + n0 + wn*32;
      const float* bop = bo + n0 + wn*32;
#pragma unroll
      for (int nt = 0; nt < 4; nt++) {
        int cc = nt*8 + q2;
        float2 v;
        v.x = f.c[mt][nt][h2*2+0] + bop[cc];
        v.y = f.c[mt][nt][h2*2+1] + bop[cc + 1];
        *(float2*)(dst + cc) = v;
      }
    }
  }
}

// ---------------------------------------------------------------------------
// Flash attention, Mq=128: block = (b, h, 128 q-rows), 16 warps (8m x 2n).
// smem (bf16 elems): Qh@0, Ql@G, Ph@2G, Pl@3G (G=GTILE, 128-row tiles);
//   KV stage s at 4G + s*4*ATILE: [Kh, Kl, Vh, Vl] (64-row tiles)
//   red floats after: redM[2][128], redL[2][128]
// ---------------------------------------------------------------------------
__global__ __launch_bounds__(512, 1) void attn_flash_kernel(
    const float* __restrict__ bias)
{
  extern __shared__ __nv_bfloat16 smb[];
  __nv_bfloat16* Qh = smb;
  __nv_bfloat16* Ql = smb + GTILE;
  __nv_bfloat16* Ph = smb + 2*GTILE;
  __nv_bfloat16* Pl = smb + 3*GTILE;
  __nv_bfloat16* KV = smb + 4*GTILE;
  float* redM = (float*)(smb + 4*GTILE + 8*ATILE);   // [2][128]
  float* redL = redM + 256;                          // [2][128]

  const int tid = threadIdx.x;
  const int lane = tid & 31, wid = tid >> 5;
  const int wn = wid & 1, wm = wid >> 1;             // wm 0..7, wn 0..1
  const int lrow = (lane & 7) + ((lane >> 3) & 1) * 8;
  const int lcol = (lane >> 4) * 8;
  const int r4 = lane >> 2, q2 = (lane & 3) * 2;
  const int it0 = blockIdx.x * 128;
  const int h = blockIdx.y, b = blockIdx.z;

  const int bh_off = (b*8 + h) * 512 * 64;
  const __nv_bfloat16* Khs = g_Kh + bh_off;
  const __nv_bfloat16* Kls = g_Kl + bh_off;
  const __nv_bfloat16* Vhs = g_Vh + bh_off;
  const __nv_bfloat16* Vls = g_Vl + bh_off;

  // prefetch Q (128 rows) + chunk 0 of K,V
  cpa_tile128_512(Qh, g_Qh + bh_off + it0*64, 64, tid);
  cpa_tile128_512(Ql, g_Ql + bh_off + it0*64, 64, tid);
  cpa_tile64_512(KV,           Khs, tid);
  cpa_tile64_512(KV + ATILE,   Kls, tid);
  cpa_tile64_512(KV + 2*ATILE, Vhs, tid);
  cpa_tile64_512(KV + 3*ATILE, Vls, tid);
  CP_COMMIT();

  const uint32_t qh_base = smem_u32(Qh) + ((wm*16 + lrow)*TSTRIDE + lcol)*2;
  const uint32_t ql_base = smem_u32(Ql) + ((wm*16 + lrow)*TSTRIDE + lcol)*2;
  const uint32_t ph_base = smem_u32(Ph) + ((wm*16 + lrow)*TSTRIDE + lcol)*2;
  const uint32_t pl_base = smem_u32(Pl) + ((wm*16 + lrow)*TSTRIDE + lcol)*2;
  uint32_t kb[2][2], vb[2][2];
#pragma unroll
  for (int s = 0; s < 2; s++) {
    __nv_bfloat16* st = KV + s*4*ATILE;
    kb[s][0] = smem_u32(st)           + ((wn*32 + lrow)*TSTRIDE + lcol)*2;
    kb[s][1] = smem_u32(st + ATILE)   + ((wn*32 + lrow)*TSTRIDE + lcol)*2;
    vb[s][0] = smem_u32(st + 2*ATILE) + (lrow*TSTRIDE + wn*32 + lcol)*2;
    vb[s][1] = smem_u32(st + 3*ATILE) + (lrow*TSTRIDE + wn*32 + lcol)*2;
  }

  const int row0 = wm*16 + r4;
  const int row1 = row0 + 8;
  const unsigned char* mrow = g_mask + b*512;
  const bool mi0 = mrow[it0 + row0] != 0;
  const bool mi1 = mrow[it0 + row1] != 0;
  const float* brow0 = bias + (h*512 + it0 + row0)*512;
  const float* brow1 = bias + (h*512 + it0 + row1)*512;

  float m0r = -FLT_MAX, m1r = -FLT_MAX, l0r = 0.f, l1r = 0.f;
  float o[4][4];
#pragma unroll
  for (int nf = 0; nf < 4; nf++)
#pragma unroll
    for (int q = 0; q < 4; q++) o[nf][q] = 0.f;

  for (int jt = 0; jt < 8; jt++) {
    if (jt < 7) {
      __nv_bfloat16* st = KV + ((jt+1)&1)*4*ATILE;
      const int co = (jt+1)*64*64;
      cpa_tile64_512(st,           Khs + co, tid);
      cpa_tile64_512(st + ATILE,   Kls + co, tid);
      cpa_tile64_512(st + 2*ATILE, Vhs + co, tid);
      cpa_tile64_512(st + 3*ATILE, Vls + co, tid);
      CP_COMMIT();
      CP_WAIT(1);
    } else {
      CP_WAIT(0);
    }
    __syncthreads();

    const int s = jt & 1;
    float c[4][4];
#pragma unroll
    for (int nf = 0; nf < 4; nf++)
#pragma unroll
      for (int q = 0; q < 4; q++) c[nf][q] = 0.f;

#pragma unroll
    for (int ks = 0; ks < 4; ks++) {
      uint32_t ah[4], al[4];
      ldsm_x4(qh_base + ks*32, ah[0], ah[1], ah[2], ah[3]);
      ldsm_x4(ql_base + ks*32, al[0], al[1], al[2], al[3]);
#pragma unroll
      for (int np = 0; np < 2; np++) {
        uint32_t off = (np*16*TSTRIDE + ks*16)*2;
        uint32_t r0, r1, r2, r3;
        ldsm_x4(kb[s][0] + off, r0, r1, r2, r3);
        uint32_t bh0[2] = {r0, r2}, bh1[2] = {r1, r3};
        ldsm_x4(kb[s][1] + off, r0, r1, r2, r3);
        uint32_t bl0[2] = {r0, r2}, bl1[2] = {r1, r3};
        mma_bf16(c[2*np],   ah, bh0); mma_bf16(c[2*np],   ah, bl0);
        mma_bf16(c[2*np],   al, bh0);
        mma_bf16(c[2*np+1], ah, bh1); mma_bf16(c[2*np+1], ah, bl1);
        mma_bf16(c[2*np+1], al, bh1);
      }
    }

    const int colbase = jt*64 + wn*32;
    float rm0 = -FLT_MAX, rm1 = -FLT_MAX;
#pragma unroll
    for (int nf = 0; nf < 4; nf++) {
      const int col = colbase + nf*8 + q2;
      float2 b0 = *(const float2*)&brow0[col];
      float2 b1 = *(const float2*)&brow1[col];
      bool mjA = mrow[col] != 0, mjB = mrow[col+1] != 0;
      c[nf][0] = (mi0 && mjA) ? c[nf][0]*SCALE_ + b0.x : -FLT_MAX;
      c[nf][1] = (mi0 && mjB) ? c[nf][1]*SCALE_ + b0.y : -FLT_MAX;
      c[nf][2] = (mi1 && mjA) ? c[nf][2]*SCALE_ + b1.x : -FLT_MAX;
      c[nf][3] = (mi1 && mjB) ? c[nf][3]*SCALE_ + b1.y : -FLT_MAX;
      rm0 = fmaxf(rm0, fmaxf(c[nf][0], c[nf][1]));
      rm1 = fmaxf(rm1, fmaxf(c[nf][2], c[nf][3]));
    }
    rm0 = fmaxf(rm0, __shfl_xor_sync(0xffffffffu, rm0, 1));
    rm0 = fmaxf(rm0, __shfl_xor_sync(0xffffffffu, rm0, 2));
    rm1 = fmaxf(rm1, __shfl_xor_sync(0xffffffffu, rm1, 1));
    rm1 = fmaxf(rm1, __shfl_xor_sync(0xffffffffu, rm1, 2));
    if ((lane & 3) == 0) {
      redM[wn*128 + row0] = rm0;
      redM[wn*128 + row1] = rm1;
    }
    __syncthreads();
    const float mc0 = fmaxf(redM[row0], redM[128 + row0]);
    const float mc1 = fmaxf(redM[row1], redM[128 + row1]);
    const float mn0 = fmaxf(m0r, mc0), mn1 = fmaxf(m1r, mc1);
    const float fs0 = __expf(m0r - mn0), fs1 = __expf(m1r - mn1);

    float ls0 = 0.f, ls1 = 0.f;
#pragma unroll
    for (int nf = 0; nf < 4; nf++) {
      c[nf][0] = __expf(c[nf][0] - mn0);
      c[nf][1] = __expf(c[nf][1] - mn0);
      c[nf][2] = __expf(c[nf][2] - mn1);
      c[nf][3] = __expf(c[nf][3] - mn1);
      ls0 += c[nf][0] + c[nf][1];
      ls1 += c[nf][2] + c[nf][3];
    }
    ls0 += __shfl_xor_sync(0xffffffffu, ls0, 1);
    ls0 += __shfl_xor_sync(0xffffffffu, ls0, 2);
    ls1 += __shfl_xor_sync(0xffffffffu, ls1, 1);
    ls1 += __shfl_xor_sync(0xffffffffu, ls1, 2);
    if ((lane & 3) == 0) {
      redL[wn*128 + row0] = ls0;
      redL[wn*128 + row1] = ls1;
    }

#pragma unroll
    for (int nf = 0; nf < 4; nf++) {
      o[nf][0] *= fs0; o[nf][1] *= fs0;
      o[nf][2] *= fs1; o[nf][3] *= fs1;
      const int pcol = wn*32 + nf*8 + q2;
      __nv_bfloat16 h0, lo0, h1, lo1;
      split2(c[nf][0], h0, lo0); split2(c[nf][1], h1, lo1);
      *(uint32_t*)(Ph + row0*TSTRIDE + pcol) = pack2(h0, h1);
      *(uint32_t*)(Pl + row0*TSTRIDE + pcol) = pack2(lo0, lo1);
      split2(c[nf][2], h0, lo0); split2(c[nf][3], h1, lo1);
      *(uint32_t*)(Ph + row1*TSTRIDE + pcol) = pack2(h0, h1);
      *(uint32_t*)(Pl + row1*TSTRIDE + pcol) = pack2(lo0, lo1);
    }
    __syncthreads();
    l0r = l0r*fs0 + redL[row0] + redL[128 + row0];
    l1r = l1r*fs1 + redL[row1] + redL[128 + row1];
    m0r = mn0; m1r = mn1;

#pragma unroll
    for (int ks = 0; ks < 4; ks++) {
      uint32_t ah[4], al[4];
      ldsm_x4(ph_base + ks*32, ah[0], ah[1], ah[2], ah[3]);
      ldsm_x4(pl_base + ks*32, al[0], al[1], al[2], al[3]);
#pragma unroll
      for (int np = 0; np < 2; np++) {
        uint32_t off = (ks*16*TSTRIDE + np*16)*2;
        uint32_t r0, r1, r2, r3;
        ldsm_x4_t(vb[s][0] + off, r0, r1, r2, r3);
        uint32_t bh0[2] = {r0, r1}, bh1[2] = {r2, r3};
        ldsm_x4_t(vb[s][1] + off, r0, r1, r2, r3);
        uint32_t bl0[2] = {r0, r1}, bl1[2] = {r2, r3};
        mma_bf16(o[2*np],   ah, bh0); mma_bf16(o[2*np],   ah, bl0);
        mma_bf16(o[2*np],   al, bh0);
        mma_bf16(o[2*np+1], ah, bh1); mma_bf16(o[2*np+1], ah, bl1);
        mma_bf16(o[2*np+1], al, bh1);
      }
    }
    // all warps must finish reading this V stage before next prefetch
    __syncthreads();
  }

  const float inv0 = 1.0f / l0r;
  const float inv1 = 1.0f / l1r;
#pragma unroll
  for (int nf = 0; nf < 4; nf++) {
    const int d = wn*32 + nf*8 + q2;
#pragma unroll
    for (int h2 = 0; h2 < 2; h2++) {
      const int row = (h2 == 0) ? row0 : row1;
      const float inv = (h2 == 0) ? inv0 : inv1;
      const int idx = (b*512 + it0 + row)*512 + h*64 + d;
      float2 gv = *(const float2*)(g_G + idx);
      float e0 = o[nf][h2*2+0] * inv * gv.x;
      float e1 = o[nf][h2*2+1] * inv * gv.y;
      __nv_bfloat16 eh0, el0, eh1, el1;
      split2(e0, eh0, el0); split2(e1, eh1, el1);
      *(uint32_t*)(g_Eh + idx) = pack2(eh0, eh1);
      *(uint32_t*)(g_El + idx) = pack2(el0, el1);
    }
  }
}

// ---------------------------------------------------------------------------
extern "C" void kernel_launch(void* const* d_in, const int* in_sizes, int n_in,
                              void* d_out, int out_size)
{
  const float* x   = (const float*)d_in[0];
  const void*  mask = d_in[1];
  const float* bias = (const float*)d_in[2];
  const float* Wq  = (const float*)d_in[3];
  const float* Wkv = (const float*)d_in[4];
  const float* Wo  = (const float*)d_in[5];
  const float* bo  = (const float*)d_in[6];
  const float* Wg  = (const float*)d_in[7];
  const float* bg  = (const float*)d_in[8];
  float* Y = (float*)d_out;

  const int SMEM_ATTN = (4*GTILE + 8*ATILE)*2 + 512*4;  // 147456 + 2048
  const int SMEM_MMA  = 8 * GTILE * 2;                   // 147456
  cudaFuncSetAttribute(attn_flash_kernel, cudaFuncAttributeMaxDynamicSharedMemorySize,
                       SMEM_ATTN);
  cudaFuncSetAttribute(proj_mma_kernel, cudaFuncAttributeMaxDynamicSharedMemorySize,
                       SMEM_MMA);
  cudaFuncSetAttribute(out_mma_kernel, cudaFuncAttributeMaxDynamicSharedMemorySize,
                       SMEM_MMA);

  detect_mask_kernel<<<1, 256>>>((const unsigned int*)mask);
  convert_mask_kernel<<<128, 256>>>(mask);
  split_x_kernel<<<8192, 256>>>(x);
  split_W_kernel<<<2048, 256>>>(Wq, Wkv, Wg);
  split_Wo_kernel<<<512, 256>>>(Wo);
  proj_mma_kernel<<<dim3(16, 256), 512, SMEM_MMA>>>(bg);
  attn_flash_kernel<<<dim3(4, 8, 64), 512, SMEM_ATTN>>>(bias);
  out_mma_kernel<<<dim3(2, 256), 512, SMEM_MMA>>>(bo, Y);
}

// round 10
// speedup vs baseline: 1.1060x; 1.1060x over previous
#include <cuda_runtime.h>
#include <cuda_bf16.h>
#include <cfloat>
#include <cstdint>

#define BB_   64
#define NN_   512
#define DIM_  256
#define HH_   8
#define DHH_  64
#define INNER_ 512
#define SCALE_ 0.125f

// ---------------------------------------------------------------------------
// Scratch
// ---------------------------------------------------------------------------
__device__ float g_G[BB_*NN_*INNER_];
__device__ unsigned char g_mask[BB_*NN_];
__device__ int g_mask_mode;

__device__ __nv_bfloat16 g_xh[BB_*NN_*DIM_];
__device__ __nv_bfloat16 g_xl[BB_*NN_*DIM_];
__device__ __nv_bfloat16 g_Wch[2048*DIM_];
__device__ __nv_bfloat16 g_Wcl[2048*DIM_];
__device__ __nv_bfloat16 g_Qh[BB_*HH_*NN_*DHH_];
__device__ __nv_bfloat16 g_Ql[BB_*HH_*NN_*DHH_];
__device__ __nv_bfloat16 g_Kh[BB_*HH_*NN_*DHH_];
__device__ __nv_bfloat16 g_Kl[BB_*HH_*NN_*DHH_];
__device__ __nv_bfloat16 g_Vh[BB_*HH_*NN_*DHH_];
__device__ __nv_bfloat16 g_Vl[BB_*HH_*NN_*DHH_];
__device__ __nv_bfloat16 g_Eh[BB_*NN_*INNER_];
__device__ __nv_bfloat16 g_El[BB_*NN_*INNER_];
__device__ __nv_bfloat16 g_Woh[DIM_*INNER_];
__device__ __nv_bfloat16 g_Wol[DIM_*INNER_];

// ---------------------------------------------------------------------------
// Helpers
// ---------------------------------------------------------------------------
__device__ __forceinline__ uint32_t smem_u32(const void* p) {
  uint32_t a;
  asm("{ .reg .u64 t; cvta.to.shared.u64 t, %1; cvt.u32.u64 %0, t; }"
      : "=r"(a) : "l"(p));
  return a;
}
__device__ __forceinline__ void cp16(uint32_t saddr, const void* g) {
  asm volatile("cp.async.cg.shared.global [%0], [%1], 16;"
               :: "r"(saddr), "l"(g));
}
#define CP_COMMIT() asm volatile("cp.async.commit_group;" ::: "memory")
#define CP_WAIT(n)  asm volatile("cp.async.wait_group %0;" :: "n"(n) : "memory")

__device__ __forceinline__ void ldsm_x4(uint32_t addr, uint32_t& r0,
                                        uint32_t& r1, uint32_t& r2, uint32_t& r3) {
  asm volatile("ldmatrix.sync.aligned.m8n8.x4.shared.b16 {%0,%1,%2,%3}, [%4];"
               : "=r"(r0), "=r"(r1), "=r"(r2), "=r"(r3) : "r"(addr));
}
__device__ __forceinline__ void ldsm_x4_t(uint32_t addr, uint32_t& r0,
                                          uint32_t& r1, uint32_t& r2, uint32_t& r3) {
  asm volatile("ldmatrix.sync.aligned.m8n8.x4.trans.shared.b16 {%0,%1,%2,%3}, [%4];"
               : "=r"(r0), "=r"(r1), "=r"(r2), "=r"(r3) : "r"(addr));
}
__device__ __forceinline__ void mma_bf16(float* c, const uint32_t* a,
                                         const uint32_t* b) {
  asm volatile(
    "mma.sync.aligned.m16n8k16.row.col.f32.bf16.bf16.f32 "
    "{%0,%1,%2,%3}, {%4,%5,%6,%7}, {%8,%9}, {%0,%1,%2,%3};"
    : "+f"(c[0]), "+f"(c[1]), "+f"(c[2]), "+f"(c[3])
    : "r"(a[0]), "r"(a[1]), "r"(a[2]), "r"(a[3]), "r"(b[0]), "r"(b[1]));
}
__device__ __forceinline__ void split2(float v, __nv_bfloat16& h, __nv_bfloat16& l) {
  h = __float2bfloat16(v);
  l = __float2bfloat16(v - __bfloat162float(h));
}
__device__ __forceinline__ uint32_t pack2(__nv_bfloat16 a, __nv_bfloat16 b) {
  return (uint32_t)*(uint16_t*)&a | ((uint32_t)*(uint16_t*)&b << 16);
}
// split two floats into packed hi and packed lo
__device__ __forceinline__ void split2pack(float v0, float v1,
                                           uint32_t& ph, uint32_t& pl) {
  __nv_bfloat16 h0, l0, h1, l1;
  split2(v0, h0, l0); split2(v1, h1, l1);
  ph = pack2(h0, h1); pl = pack2(l0, l1);
}

// ---------------------------------------------------------------------------
// Mask detection + conversion (proven)
// ---------------------------------------------------------------------------
__global__ void detect_mask_kernel(const unsigned int* __restrict__ m)
{
  __shared__ int s_not01, s_notf;
  if (threadIdx.x == 0) { s_not01 = 0; s_notf = 0; }
  __syncthreads();
  int a = 0, b = 0;
  for (int i = threadIdx.x; i < 8192; i += 256) {
    unsigned v = m[i];
    if (v != 0u && v != 1u) a = 1;
    if (v != 0u && v != 0x3F800000u) b = 1;
  }
  if (a) atomicOr(&s_not01, 1);
  if (b) atomicOr(&s_notf, 1);
  __syncthreads();
  if (threadIdx.x == 0)
    g_mask_mode = (!s_not01) ? 0 : ((!s_notf) ? 1 : 2);
}

__global__ void convert_mask_kernel(const void* __restrict__ m)
{
  int idx = blockIdx.x * blockDim.x + threadIdx.x;
  if (idx >= BB_*NN_) return;
  int mode = g_mask_mode;
  unsigned char r;
  if (mode == 0)      r = ((const int*)m)[idx] != 0;
  else if (mode == 1) r = ((const unsigned int*)m)[idx] != 0u;
  else                r = ((const unsigned char*)m)[idx] != 0;
  g_mask[idx] = r;
}

// ---------------------------------------------------------------------------
// Split conversions (proven)
// ---------------------------------------------------------------------------
__global__ void split_x_kernel(const float* __restrict__ x)
{
  int i = (blockIdx.x * 256 + threadIdx.x) * 4;
  float4 v = *(const float4*)(x + i);
  __nv_bfloat16 h[4], l[4];
  split2(v.x, h[0], l[0]); split2(v.y, h[1], l[1]);
  split2(v.z, h[2], l[2]); split2(v.w, h[3], l[3]);
  *(uint2*)(g_xh + i) = *(uint2*)h;
  *(uint2*)(g_xl + i) = *(uint2*)l;
}

__global__ void split_W_kernel(const float* __restrict__ Wq,
                               const float* __restrict__ Wkv,
                               const float* __restrict__ Wg)
{
  int idx = blockIdx.x * 256 + threadIdx.x;
  int k = idx & 255, n = idx >> 8;
  int seg = n >> 9, col = n & 511;
  float v;
  if (seg == 0)      v = Wq[k*512 + col];
  else if (seg == 1) v = Wkv[k*1024 + col];
  else if (seg == 2) v = Wkv[k*1024 + 512 + col];
  else               v = Wg[k*512 + col];
  __nv_bfloat16 h, l; split2(v, h, l);
  g_Wch[n*256 + k] = h; g_Wcl[n*256 + k] = l;
}

__global__ void split_Wo_kernel(const float* __restrict__ Wo)
{
  int idx = blockIdx.x * 256 + threadIdx.x;
  int n = idx >> 9, k = idx & 511;
  float v = Wo[k*256 + n];
  __nv_bfloat16 h, l; split2(v, h, l);
  g_Woh[n*512 + k] = h; g_Wol[n*512 + k] = l;
}

// ---------------------------------------------------------------------------
// Tile loaders
// ---------------------------------------------------------------------------
#define TSTRIDE 72
#define GTILE (128*TSTRIDE)
#define ATILE (64*TSTRIDE)

__device__ __forceinline__ void cpa_tile128_512(
    __nv_bfloat16* dst, const __nv_bfloat16* __restrict__ src, int ldk, int tid)
{
#pragma unroll
  for (int it = 0; it < 2; it++) {
    int u = it*512 + tid;
    int row = u >> 3, c8 = (u & 7) * 8;
    cp16(smem_u32(dst + row*TSTRIDE + c8), src + row*ldk + c8);
  }
}

__device__ __forceinline__ void cpa_tile64(
    __nv_bfloat16* dst, const __nv_bfloat16* __restrict__ src, int tid)
{
#pragma unroll
  for (int it = 0; it < 2; it++) {
    int u = it*256 + tid;
    int row = u >> 3, c8 = (u & 7) * 8;
    cp16(smem_u32(dst + row*TSTRIDE + c8), src + row*64 + c8);
  }
}

// ---------------------------------------------------------------------------
// Dense GEMM core (proven R8): block 128x128, 16 warps, warp tile 32x32.
// ---------------------------------------------------------------------------
struct FragC { float c[2][4][4]; };

template <int KCHUNKS>
__device__ __forceinline__ void gemm_core(
    __nv_bfloat16* smb,
    const __nv_bfloat16* gAh, const __nv_bfloat16* gAl,
    const __nv_bfloat16* gBh, const __nv_bfloat16* gBl,
    int m0, int n0blk, int ldk, int tid, FragC& f)
{
  const int lane = tid & 31, wid = tid >> 5;
  const int wm = wid & 3, wn = wid >> 2;
  const int lrow = (lane & 7) + ((lane >> 3) & 1) * 8;
  const int lcol = (lane >> 4) * 8;

  uint32_t abase[2][2], bbase[2][2];
#pragma unroll
  for (int s = 0; s < 2; s++) {
    __nv_bfloat16* st = smb + s*4*GTILE;
    abase[s][0] = smem_u32(st)           + ((wm*32 + lrow)*TSTRIDE + lcol)*2;
    abase[s][1] = smem_u32(st + GTILE)   + ((wm*32 + lrow)*TSTRIDE + lcol)*2;
    bbase[s][0] = smem_u32(st + 2*GTILE) + ((wn*32 + lrow)*TSTRIDE + lcol)*2;
    bbase[s][1] = smem_u32(st + 3*GTILE) + ((wn*32 + lrow)*TSTRIDE + lcol)*2;
  }

#pragma unroll
  for (int mt = 0; mt < 2; mt++)
#pragma unroll
    for (int nt = 0; nt < 4; nt++)
#pragma unroll
      for (int q = 0; q < 4; q++) f.c[mt][nt][q] = 0.f;

  {
    __nv_bfloat16* st = smb;
    cpa_tile128_512(st,           gAh + m0*ldk,    ldk, tid);
    cpa_tile128_512(st + GTILE,   gAl + m0*ldk,    ldk, tid);
    cpa_tile128_512(st + 2*GTILE, gBh + n0blk*ldk, ldk, tid);
    cpa_tile128_512(st + 3*GTILE, gBl + n0blk*ldk, ldk, tid);
    CP_COMMIT();
  }

  for (int kc = 0; kc < KCHUNKS; kc++) {
    if (kc + 1 < KCHUNKS) {
      __nv_bfloat16* st = smb + ((kc+1)&1)*4*GTILE;
      int co = (kc+1)*64;
      cpa_tile128_512(st,           gAh + m0*ldk + co,    ldk, tid);
      cpa_tile128_512(st + GTILE,   gAl + m0*ldk + co,    ldk, tid);
      cpa_tile128_512(st + 2*GTILE, gBh + n0blk*ldk + co, ldk, tid);
      cpa_tile128_512(st + 3*GTILE, gBl + n0blk*ldk + co, ldk, tid);
      CP_COMMIT();
      CP_WAIT(1);
    } else {
      CP_WAIT(0);
    }
    __syncthreads();

    const int s = kc & 1;
#pragma unroll
    for (int ks = 0; ks < 4; ks++) {
      uint32_t ah[2][4], al[2][4];
#pragma unroll
      for (int mt = 0; mt < 2; mt++) {
        uint32_t off = (mt*16*TSTRIDE + ks*16)*2;
        ldsm_x4(abase[s][0] + off, ah[mt][0], ah[mt][1], ah[mt][2], ah[mt][3]);
        ldsm_x4(abase[s][1] + off, al[mt][0], al[mt][1], al[mt][2], al[mt][3]);
      }
      uint32_t bh[4][2], bl[4][2];
#pragma unroll
      for (int np = 0; np < 2; np++) {
        uint32_t off = (np*16*TSTRIDE + ks*16)*2;
        uint32_t r0, r1, r2, r3;
        ldsm_x4(bbase[s][0] + off, r0, r1, r2, r3);
        bh[2*np][0] = r0; bh[2*np+1][0] = r1; bh[2*np][1] = r2; bh[2*np+1][1] = r3;
        ldsm_x4(bbase[s][1] + off, r0, r1, r2, r3);
        bl[2*np][0] = r0; bl[2*np+1][0] = r1; bl[2*np][1] = r2; bl[2*np+1][1] = r3;
      }
#pragma unroll
      for (int mt = 0; mt < 2; mt++)
#pragma unroll
        for (int nt = 0; nt < 4; nt++) {
          mma_bf16(f.c[mt][nt], ah[mt], bh[nt]);
          mma_bf16(f.c[mt][nt], ah[mt], bl[nt]);
          mma_bf16(f.c[mt][nt], al[mt], bh[nt]);
        }
    }
    __syncthreads();
  }
}

// ---------------------------------------------------------------------------
// Projection GEMM (512 threads) — proven R8
// ---------------------------------------------------------------------------
__global__ __launch_bounds__(512) void proj_mma_kernel(const float* __restrict__ bg)
{
  extern __shared__ __nv_bfloat16 smb[];
  const int tid = threadIdx.x;
  const int c0 = blockIdx.x * 128;
  const int m0 = blockIdx.y * 128;

  FragC f;
  gemm_core<4>(smb, g_xh, g_xl, g_Wch, g_Wcl, m0, c0, 256, tid, f);

  const int lane = tid & 31, wid = tid >> 5;
  const int wm = wid & 3, wn = wid >> 2;
  const int q2 = (lane & 3) * 2, r4 = lane >> 2;
  const int seg = c0 >> 9;
  const int lbase = c0 - seg*512 + wn*32;

#pragma unroll
  for (int mt = 0; mt < 2; mt++) {
#pragma unroll
    for (int h2 = 0; h2 < 2; h2++) {
      const int m = m0 + wm*32 + mt*16 + r4 + h2*8;
      const int bidx = m >> 9, n = m & 511;
      if (seg == 3) {
        float* dst = g_G + m*512 + lbase;
#pragma unroll
        for (int nt = 0; nt < 4; nt++) {
          int cc = nt*8 + q2;
          float2 v;
          v.x = f.c[mt][nt][h2*2+0] + bg[lbase + cc];
          v.y = f.c[mt][nt][h2*2+1] + bg[lbase + cc + 1];
          *(float2*)(dst + cc) = v;
        }
      } else {
        const int hh = lbase >> 6;
        const int dbase = lbase & 63;
        __nv_bfloat16 *bh_, *bl_;
        if (seg == 0)      { bh_ = g_Qh; bl_ = g_Ql; }
        else if (seg == 1) { bh_ = g_Kh; bl_ = g_Kl; }
        else               { bh_ = g_Vh; bl_ = g_Vl; }
        const int off = (((bidx*8 + hh)*512 + n)*64) + dbase;
#pragma unroll
        for (int nt = 0; nt < 4; nt++) {
          int dd = nt*8 + q2;
          uint32_t ph, pl;
          split2pack(f.c[mt][nt][h2*2+0], f.c[mt][nt][h2*2+1], ph, pl);
          *(uint32_t*)(bh_ + off + dd) = ph;
          *(uint32_t*)(bl_ + off + dd) = pl;
        }
      }
    }
  }
}

// ---------------------------------------------------------------------------
// Output GEMM (512 threads) — proven R8
// ---------------------------------------------------------------------------
__global__ __launch_bounds__(512) void out_mma_kernel(
    const float* __restrict__ bo, float* __restrict__ Y)
{
  extern __shared__ __nv_bfloat16 smb[];
  const int tid = threadIdx.x;
  const int n0 = blockIdx.x * 128;
  const int m0 = blockIdx.y * 128;

  FragC f;
  gemm_core<8>(smb, g_Eh, g_El, g_Woh, g_Wol, m0, n0, 512, tid, f);

  const int lane = tid & 31, wid = tid >> 5;
  const int wm = wid & 3, wn = wid >> 2;
  const int q2 = (lane & 3) * 2, r4 = lane >> 2;

#pragma unroll
  for (int mt = 0; mt < 2; mt++) {
#pragma unroll
    for (int h2 = 0; h2 < 2; h2++) {
      const int m = m0 + wm*32 + mt*16 + r4 + h2*8;
      float* dst = Y + m*256 + n0 + wn*32;
      const float* bop = bo + n0 + wn*32;
#pragma unroll
      for (int nt = 0; nt < 4; nt++) {
        int cc = nt*8 + q2;
        float2 v;
        v.x = f.c[mt][nt][h2*2+0] + bop[cc];
        v.y = f.c[mt][nt][h2*2+1] + bop[cc + 1];
        *(float2*)(dst + cc) = v;
      }
    }
  }
}

// ---------------------------------------------------------------------------
// Flash attention v2-style: block = (b, h, 64 q-rows), 8 warps (4m x 2n).
// Per-warp independent online softmax over its 32-col slice; P stays in
// registers (C-fragment == A-fragment layout); cross-warp merge at the end.
// smem (bf16 elems): Qh@0, Ql@ATILE; KV stage s at (2+s*4)*ATILE:
//   [Kh, Kl, Vh, Vl]. Merge buffers alias KV region after the loop.
// ---------------------------------------------------------------------------
__global__ __launch_bounds__(256, 2) void attn_flash_kernel(
    const float* __restrict__ bias)
{
  extern __shared__ __nv_bfloat16 smb[];
  __nv_bfloat16* Qh = smb;
  __nv_bfloat16* Ql = smb + ATILE;
  __nv_bfloat16* KV = smb + 2*ATILE;

  const int tid = threadIdx.x;
  const int lane = tid & 31, wid = tid >> 5;
  const int wm = wid & 3, wn = wid >> 2;
  const int lrow = (lane & 7) + ((lane >> 3) & 1) * 8;
  const int lcol = (lane >> 4) * 8;
  const int r4 = lane >> 2, q2 = (lane & 3) * 2;
  const int it0 = blockIdx.x * 64;
  const int h = blockIdx.y, b = blockIdx.z;

  const int bh_off = (b*8 + h) * 512 * 64;
  const __nv_bfloat16* Khs = g_Kh + bh_off;
  const __nv_bfloat16* Kls = g_Kl + bh_off;
  const __nv_bfloat16* Vhs = g_Vh + bh_off;
  const __nv_bfloat16* Vls = g_Vl + bh_off;

  cpa_tile64(Qh, g_Qh + bh_off + it0*64, tid);
  cpa_tile64(Ql, g_Ql + bh_off + it0*64, tid);
  cpa_tile64(KV,           Khs, tid);
  cpa_tile64(KV + ATILE,   Kls, tid);
  cpa_tile64(KV + 2*ATILE, Vhs, tid);
  cpa_tile64(KV + 3*ATILE, Vls, tid);
  CP_COMMIT();

  const uint32_t qh_base = smem_u32(Qh) + ((wm*16 + lrow)*TSTRIDE + lcol)*2;
  const uint32_t ql_base = smem_u32(Ql) + ((wm*16 + lrow)*TSTRIDE + lcol)*2;
  uint32_t kb[2][2], vb[2][2];
#pragma unroll
  for (int s = 0; s < 2; s++) {
    __nv_bfloat16* st = KV + s*4*ATILE;
    kb[s][0] = smem_u32(st)           + ((wn*32 + lrow)*TSTRIDE + lcol)*2;
    kb[s][1] = smem_u32(st + ATILE)   + ((wn*32 + lrow)*TSTRIDE + lcol)*2;
    // V B-operand: k-rows = this warp's own 32 cols (wn*32 ..), n = d 0..63
    vb[s][0] = smem_u32(st + 2*ATILE) + ((wn*32 + lrow)*TSTRIDE + lcol)*2;
    vb[s][1] = smem_u32(st + 3*ATILE) + ((wn*32 + lrow)*TSTRIDE + lcol)*2;
  }

  const int row0 = wm*16 + r4;
  const int row1 = row0 + 8;
  const unsigned char* mrow = g_mask + b*512;
  const bool mi0 = mrow[it0 + row0] != 0;
  const bool mi1 = mrow[it0 + row1] != 0;
  const float* brow0 = bias + (h*512 + it0 + row0)*512;
  const float* brow1 = bias + (h*512 + it0 + row1)*512;

  float m0r = -FLT_MAX, m1r = -FLT_MAX, l0r = 0.f, l1r = 0.f;
  float o[8][4];
#pragma unroll
  for (int nf = 0; nf < 8; nf++)
#pragma unroll
    for (int q = 0; q < 4; q++) o[nf][q] = 0.f;

  for (int jt = 0; jt < 8; jt++) {
    if (jt < 7) {
      __nv_bfloat16* st = KV + ((jt+1)&1)*4*ATILE;
      const int co = (jt+1)*64*64;
      cpa_tile64(st,           Khs + co, tid);
      cpa_tile64(st + ATILE,   Kls + co, tid);
      cpa_tile64(st + 2*ATILE, Vhs + co, tid);
      cpa_tile64(st + 3*ATILE, Vls + co, tid);
      CP_COMMIT();
      CP_WAIT(1);
    } else {
      CP_WAIT(0);
    }
    __syncthreads();

    const int s = jt & 1;
    // ---- S = Q K^T chunk (warp's 32 cols) ----
    float c[4][4];
#pragma unroll
    for (int nf = 0; nf < 4; nf++)
#pragma unroll
      for (int q = 0; q < 4; q++) c[nf][q] = 0.f;

#pragma unroll
    for (int ks = 0; ks < 4; ks++) {
      uint32_t ah[4], al[4];
      ldsm_x4(qh_base + ks*32, ah[0], ah[1], ah[2], ah[3]);
      ldsm_x4(ql_base + ks*32, al[0], al[1], al[2], al[3]);
#pragma unroll
      for (int np = 0; np < 2; np++) {
        uint32_t off = (np*16*TSTRIDE + ks*16)*2;
        uint32_t r0, r1, r2, r3;
        ldsm_x4(kb[s][0] + off, r0, r1, r2, r3);
        uint32_t bh0[2] = {r0, r2}, bh1[2] = {r1, r3};
        ldsm_x4(kb[s][1] + off, r0, r1, r2, r3);
        uint32_t bl0[2] = {r0, r2}, bl1[2] = {r1, r3};
        mma_bf16(c[2*np],   ah, bh0); mma_bf16(c[2*np],   ah, bl0);
        mma_bf16(c[2*np],   al, bh0);
        mma_bf16(c[2*np+1], ah, bh1); mma_bf16(c[2*np+1], ah, bl1);
        mma_bf16(c[2*np+1], al, bh1);
      }
    }

    // ---- scale + bias + mask; per-warp row max over its 32 cols ----
    const int colbase = jt*64 + wn*32;
    float rm0 = -FLT_MAX, rm1 = -FLT_MAX;
#pragma unroll
    for (int nf = 0; nf < 4; nf++) {
      const int col = colbase + nf*8 + q2;
      float2 b0 = *(const float2*)&brow0[col];
      float2 b1 = *(const float2*)&brow1[col];
      bool mjA = mrow[col] != 0, mjB = mrow[col+1] != 0;
      c[nf][0] = (mi0 && mjA) ? c[nf][0]*SCALE_ + b0.x : -FLT_MAX;
      c[nf][1] = (mi0 && mjB) ? c[nf][1]*SCALE_ + b0.y : -FLT_MAX;
      c[nf][2] = (mi1 && mjA) ? c[nf][2]*SCALE_ + b1.x : -FLT_MAX;
      c[nf][3] = (mi1 && mjB) ? c[nf][3]*SCALE_ + b1.y : -FLT_MAX;
      rm0 = fmaxf(rm0, fmaxf(c[nf][0], c[nf][1]));
      rm1 = fmaxf(rm1, fmaxf(c[nf][2], c[nf][3]));
    }
    rm0 = fmaxf(rm0, __shfl_xor_sync(0xffffffffu, rm0, 1));
    rm0 = fmaxf(rm0, __shfl_xor_sync(0xffffffffu, rm0, 2));
    rm1 = fmaxf(rm1, __shfl_xor_sync(0xffffffffu, rm1, 1));
    rm1 = fmaxf(rm1, __shfl_xor_sync(0xffffffffu, rm1, 2));

    const float mn0 = fmaxf(m0r, rm0), mn1 = fmaxf(m1r, rm1);
    const float fs0 = __expf(m0r - mn0), fs1 = __expf(m1r - mn1);

    // ---- P = exp(s - m'); row sums (per-warp) ----
    float ls0 = 0.f, ls1 = 0.f;
#pragma unroll
    for (int nf = 0; nf < 4; nf++) {
      c[nf][0] = __expf(c[nf][0] - mn0);
      c[nf][1] = __expf(c[nf][1] - mn0);
      c[nf][2] = __expf(c[nf][2] - mn1);
      c[nf][3] = __expf(c[nf][3] - mn1);
      ls0 += c[nf][0] + c[nf][1];
      ls1 += c[nf][2] + c[nf][3];
    }
    ls0 += __shfl_xor_sync(0xffffffffu, ls0, 1);
    ls0 += __shfl_xor_sync(0xffffffffu, ls0, 2);
    ls1 += __shfl_xor_sync(0xffffffffu, ls1, 1);
    ls1 += __shfl_xor_sync(0xffffffffu, ls1, 2);
    l0r = l0r*fs0 + ls0;
    l1r = l1r*fs1 + ls1;
    m0r = mn0; m1r = mn1;

    // ---- rescale O; pack P into A-fragments (register reuse, no smem) ----
#pragma unroll
    for (int nf = 0; nf < 8; nf++) {
      o[nf][0] *= fs0; o[nf][1] *= fs0;
      o[nf][2] *= fs1; o[nf][3] *= fs1;
    }
    uint32_t aph[2][4], apl[2][4];
#pragma unroll
    for (int ks2 = 0; ks2 < 2; ks2++) {
      // a0: row r4, k q2..q2+1 (cols nf=2*ks2); a1: row r4+8 same cols
      split2pack(c[2*ks2][0],   c[2*ks2][1],   aph[ks2][0], apl[ks2][0]);
      split2pack(c[2*ks2][2],   c[2*ks2][3],   aph[ks2][1], apl[ks2][1]);
      // a2/a3: k q2+8 (cols nf=2*ks2+1)
      split2pack(c[2*ks2+1][0], c[2*ks2+1][1], aph[ks2][2], apl[ks2][2]);
      split2pack(c[2*ks2+1][2], c[2*ks2+1][3], aph[ks2][3], apl[ks2][3]);
    }

    // ---- O += P V (warp's own k=32 slice, n=64 d cols) ----
#pragma unroll
    for (int ks2 = 0; ks2 < 2; ks2++) {
      uint32_t bh[8][2], bl[8][2];
#pragma unroll
      for (int np = 0; np < 4; np++) {
        uint32_t off = (ks2*16*TSTRIDE + np*16)*2;
        uint32_t r0, r1, r2, r3;
        ldsm_x4_t(vb[s][0] + off, r0, r1, r2, r3);
        bh[2*np][0] = r0; bh[2*np][1] = r1; bh[2*np+1][0] = r2; bh[2*np+1][1] = r3;
        ldsm_x4_t(vb[s][1] + off, r0, r1, r2, r3);
        bl[2*np][0] = r0; bl[2*np][1] = r1; bl[2*np+1][0] = r2; bl[2*np+1][1] = r3;
      }
#pragma unroll
      for (int nf = 0; nf < 8; nf++) {
        mma_bf16(o[nf], aph[ks2], bh[nf]);
        mma_bf16(o[nf], aph[ks2], bl[nf]);
        mma_bf16(o[nf], apl[ks2], bh[nf]);
      }
    }
    // all warps must finish reading this KV stage before next prefetch
    __syncthreads();
  }

  // ---- cross-warp merge (wn=0 <- wn=1), gate, split-store ----
  // merge buffers alias the KV region (loop done, barrier passed)
  float* O1  = (float*)KV;          // [64][68]
  float* m1s = O1 + 64*68;          // [64]
  float* l1s = m1s + 64;            // [64]

  if (wn == 1) {
#pragma unroll
    for (int nf = 0; nf < 8; nf++) {
      const int d = nf*8 + q2;
      *(float2*)&O1[row0*68 + d] = make_float2(o[nf][0], o[nf][1]);
      *(float2*)&O1[row1*68 + d] = make_float2(o[nf][2], o[nf][3]);
    }
    if ((lane & 3) == 0) {
      m1s[row0] = m0r; l1s[row0] = l0r;
      m1s[row1] = m1r; l1s[row1] = l1r;
    }
  }
  __syncthreads();

  if (wn == 0) {
    const float mo0 = m1s[row0], lo0 = l1s[row0];
    const float mo1 = m1s[row1], lo1 = l1s[row1];
    const float mf0 = fmaxf(m0r, mo0), mf1 = fmaxf(m1r, mo1);
    const float a0 = __expf(m0r - mf0), b0s = __expf(mo0 - mf0);
    const float a1 = __expf(m1r - mf1), b1s = __expf(mo1 - mf1);
    const float inv0 = 1.0f / (l0r*a0 + lo0*b0s);
    const float inv1 = 1.0f / (l1r*a1 + lo1*b1s);

#pragma unroll
    for (int nf = 0; nf < 8; nf++) {
      const int d = nf*8 + q2;
      const int idx0 = (b*512 + it0 + row0)*512 + h*64 + d;
      const int idx1 = (b*512 + it0 + row1)*512 + h*64 + d;
      float2 p0 = *(float2*)&O1[row0*68 + d];
      float2 p1 = *(float2*)&O1[row1*68 + d];
      float2 gv0 = *(const float2*)(g_G + idx0);
      float2 gv1 = *(const float2*)(g_G + idx1);
      float e00 = (o[nf][0]*a0 + p0.x*b0s) * inv0 * gv0.x;
      float e01 = (o[nf][1]*a0 + p0.y*b0s) * inv0 * gv0.y;
      float e10 = (o[nf][2]*a1 + p1.x*b1s) * inv1 * gv1.x;
      float e11 = (o[nf][3]*a1 + p1.y*b1s) * inv1 * gv1.y;
      uint32_t ph, pl;
      split2pack(e00, e01, ph, pl);
      *(uint32_t*)(g_Eh + idx0) = ph;
      *(uint32_t*)(g_El + idx0) = pl;
      split2pack(e10, e11, ph, pl);
      *(uint32_t*)(g_Eh + idx1) = ph;
      *(uint32_t*)(g_El + idx1) = pl;
    }
  }
}

// ---------------------------------------------------------------------------
extern "C" void kernel_launch(void* const* d_in, const int* in_sizes, int n_in,
                              void* d_out, int out_size)
{
  const float* x   = (const float*)d_in[0];
  const void*  mask = d_in[1];
  const float* bias = (const float*)d_in[2];
  const float* Wq  = (const float*)d_in[3];
  const float* Wkv = (const float*)d_in[4];
  const float* Wo  = (const float*)d_in[5];
  const float* bo  = (const float*)d_in[6];
  const float* Wg  = (const float*)d_in[7];
  const float* bg  = (const float*)d_in[8];
  float* Y = (float*)d_out;

  const int SMEM_ATTN = 10*ATILE*2;               // 92160 B -> 2 CTAs/SM
  const int SMEM_MMA  = 8 * GTILE * 2;            // 147456 B
  cudaFuncSetAttribute(attn_flash_kernel, cudaFuncAttributeMaxDynamicSharedMemorySize,
                       SMEM_ATTN);
  cudaFuncSetAttribute(proj_mma_kernel, cudaFuncAttributeMaxDynamicSharedMemorySize,
                       SMEM_MMA);
  cudaFuncSetAttribute(out_mma_kernel, cudaFuncAttributeMaxDynamicSharedMemorySize,
                       SMEM_MMA);

  detect_mask_kernel<<<1, 256>>>((const unsigned int*)mask);
  convert_mask_kernel<<<128, 256>>>(mask);
  split_x_kernel<<<8192, 256>>>(x);
  split_W_kernel<<<2048, 256>>>(Wq, Wkv, Wg);
  split_Wo_kernel<<<512, 256>>>(Wo);
  proj_mma_kernel<<<dim3(16, 256), 512, SMEM_MMA>>>(bg);
  attn_flash_kernel<<<dim3(8, 8, 64), 256, SMEM_ATTN>>>(bias);
  out_mma_kernel<<<dim3(2, 256), 512, SMEM_MMA>>>(bo, Y);
}

// round 12
// speedup vs baseline: 1.1671x; 1.0553x over previous
#include <cuda_runtime.h>
#include <cuda_bf16.h>
#include <cuda_fp16.h>
#include <cfloat>
#include <cstdint>

#define BB_   64
#define NN_   512
#define DIM_  256
#define HH_   8
#define DHH_  64
#define INNER_ 512
#define SCALE_ 0.125f

// ---------------------------------------------------------------------------
// Scratch
// ---------------------------------------------------------------------------
__device__ float g_G[BB_*NN_*INNER_];
__device__ unsigned char g_mask[BB_*NN_];
__device__ int g_mask_mode;

__device__ __nv_bfloat16 g_xh[BB_*NN_*DIM_];
__device__ __nv_bfloat16 g_xl[BB_*NN_*DIM_];
__device__ __nv_bfloat16 g_Wch[2048*DIM_];
__device__ __nv_bfloat16 g_Wcl[2048*DIM_];
__device__ __nv_bfloat16 g_Qh[BB_*HH_*NN_*DHH_];
__device__ __nv_bfloat16 g_Ql[BB_*HH_*NN_*DHH_];
__device__ __nv_bfloat16 g_Kh[BB_*HH_*NN_*DHH_];
__device__ __nv_bfloat16 g_Kl[BB_*HH_*NN_*DHH_];
__device__ __half        g_Vh[BB_*HH_*NN_*DHH_];   // fp16 split V
__device__ __half        g_Vl[BB_*HH_*NN_*DHH_];
__device__ __nv_bfloat16 g_Eh[BB_*NN_*INNER_];
__device__ __nv_bfloat16 g_El[BB_*NN_*INNER_];
__device__ __nv_bfloat16 g_Woh[DIM_*INNER_];
__device__ __nv_bfloat16 g_Wol[DIM_*INNER_];

// ---------------------------------------------------------------------------
// Helpers
// ---------------------------------------------------------------------------
__device__ __forceinline__ uint32_t smem_u32(const void* p) {
  uint32_t a;
  asm("{ .reg .u64 t; cvta.to.shared.u64 t, %1; cvt.u32.u64 %0, t; }"
      : "=r"(a) : "l"(p));
  return a;
}
__device__ __forceinline__ void cp16(uint32_t saddr, const void* g) {
  asm volatile("cp.async.cg.shared.global [%0], [%1], 16;"
               :: "r"(saddr), "l"(g));
}
#define CP_COMMIT() asm volatile("cp.async.commit_group;" ::: "memory")
#define CP_WAIT(n)  asm volatile("cp.async.wait_group %0;" :: "n"(n) : "memory")

__device__ __forceinline__ void ldsm_x4(uint32_t addr, uint32_t& r0,
                                        uint32_t& r1, uint32_t& r2, uint32_t& r3) {
  asm volatile("ldmatrix.sync.aligned.m8n8.x4.shared.b16 {%0,%1,%2,%3}, [%4];"
               : "=r"(r0), "=r"(r1), "=r"(r2), "=r"(r3) : "r"(addr));
}
__device__ __forceinline__ void ldsm_x4_t(uint32_t addr, uint32_t& r0,
                                          uint32_t& r1, uint32_t& r2, uint32_t& r3) {
  asm volatile("ldmatrix.sync.aligned.m8n8.x4.trans.shared.b16 {%0,%1,%2,%3}, [%4];"
               : "=r"(r0), "=r"(r1), "=r"(r2), "=r"(r3) : "r"(addr));
}
__device__ __forceinline__ void mma_bf16(float* c, const uint32_t* a,
                                         const uint32_t* b) {
  asm volatile(
    "mma.sync.aligned.m16n8k16.row.col.f32.bf16.bf16.f32 "
    "{%0,%1,%2,%3}, {%4,%5,%6,%7}, {%8,%9}, {%0,%1,%2,%3};"
    : "+f"(c[0]), "+f"(c[1]), "+f"(c[2]), "+f"(c[3])
    : "r"(a[0]), "r"(a[1]), "r"(a[2]), "r"(a[3]), "r"(b[0]), "r"(b[1]));
}
__device__ __forceinline__ void mma_f16(float* c, const uint32_t* a,
                                        const uint32_t* b) {
  asm volatile(
    "mma.sync.aligned.m16n8k16.row.col.f32.f16.f16.f32 "
    "{%0,%1,%2,%3}, {%4,%5,%6,%7}, {%8,%9}, {%0,%1,%2,%3};"
    : "+f"(c[0]), "+f"(c[1]), "+f"(c[2]), "+f"(c[3])
    : "r"(a[0]), "r"(a[1]), "r"(a[2]), "r"(a[3]), "r"(b[0]), "r"(b[1]));
}
__device__ __forceinline__ void split2(float v, __nv_bfloat16& h, __nv_bfloat16& l) {
  h = __float2bfloat16(v);
  l = __float2bfloat16(v - __bfloat162float(h));
}
__device__ __forceinline__ uint32_t pack2(__nv_bfloat16 a, __nv_bfloat16 b) {
  return (uint32_t)*(uint16_t*)&a | ((uint32_t)*(uint16_t*)&b << 16);
}
__device__ __forceinline__ void split2pack(float v0, float v1,
                                           uint32_t& ph, uint32_t& pl) {
  __nv_bfloat16 h0, l0, h1, l1;
  split2(v0, h0, l0); split2(v1, h1, l1);
  ph = pack2(h0, h1); pl = pack2(l0, l1);
}
// fp16 split: hi + residual
__device__ __forceinline__ void split2packh(float v0, float v1,
                                            uint32_t& ph, uint32_t& pl) {
  __half h0 = __float2half_rn(v0), h1 = __float2half_rn(v1);
  __half l0 = __float2half_rn(v0 - __half2float(h0));
  __half l1 = __float2half_rn(v1 - __half2float(h1));
  ph = (uint32_t)*(uint16_t*)&h0 | ((uint32_t)*(uint16_t*)&h1 << 16);
  pl = (uint32_t)*(uint16_t*)&l0 | ((uint32_t)*(uint16_t*)&l1 << 16);
}
__device__ __forceinline__ uint32_t pack2f16(float a, float b) {
  __half2 hh = __floats2half2_rn(a, b);
  return *(uint32_t*)&hh;
}

// ---------------------------------------------------------------------------
// Mask detection + conversion (proven)
// ---------------------------------------------------------------------------
__global__ void detect_mask_kernel(const unsigned int* __restrict__ m)
{
  __shared__ int s_not01, s_notf;
  if (threadIdx.x == 0) { s_not01 = 0; s_notf = 0; }
  __syncthreads();
  int a = 0, b = 0;
  for (int i = threadIdx.x; i < 8192; i += 256) {
    unsigned v = m[i];
    if (v != 0u && v != 1u) a = 1;
    if (v != 0u && v != 0x3F800000u) b = 1;
  }
  if (a) atomicOr(&s_not01, 1);
  if (b) atomicOr(&s_notf, 1);
  __syncthreads();
  if (threadIdx.x == 0)
    g_mask_mode = (!s_not01) ? 0 : ((!s_notf) ? 1 : 2);
}

__global__ void convert_mask_kernel(const void* __restrict__ m)
{
  int idx = blockIdx.x * blockDim.x + threadIdx.x;
  if (idx >= BB_*NN_) return;
  int mode = g_mask_mode;
  unsigned char r;
  if (mode == 0)      r = ((const int*)m)[idx] != 0;
  else if (mode == 1) r = ((const unsigned int*)m)[idx] != 0u;
  else                r = ((const unsigned char*)m)[idx] != 0;
  g_mask[idx] = r;
}

// ---------------------------------------------------------------------------
// Fused split conversions
// ---------------------------------------------------------------------------
__global__ void split_all_kernel(const float* __restrict__ x,
                                 const float* __restrict__ Wq,
                                 const float* __restrict__ Wkv,
                                 const float* __restrict__ Wg,
                                 const float* __restrict__ Wo)
{
  int bid = blockIdx.x;
  if (bid < 8192) {
    int i = (bid * 256 + threadIdx.x) * 4;
    float4 v = *(const float4*)(x + i);
    __nv_bfloat16 h[4], l[4];
    split2(v.x, h[0], l[0]); split2(v.y, h[1], l[1]);
    split2(v.z, h[2], l[2]); split2(v.w, h[3], l[3]);
    *(uint2*)(g_xh + i) = *(uint2*)h;
    *(uint2*)(g_xl + i) = *(uint2*)l;
  } else if (bid < 10240) {
    int idx = (bid - 8192) * 256 + threadIdx.x;
    int k = idx & 255, n = idx >> 8;
    int seg = n >> 9, col = n & 511;
    float v;
    if (seg == 0)      v = Wq[k*512 + col];
    else if (seg == 1) v = Wkv[k*1024 + col];
    else if (seg == 2) v = Wkv[k*1024 + 512 + col];
    else               v = Wg[k*512 + col];
    __nv_bfloat16 h, l; split2(v, h, l);
    g_Wch[n*256 + k] = h; g_Wcl[n*256 + k] = l;
  } else {
    int idx = (bid - 10240) * 256 + threadIdx.x;
    int n = idx >> 9, k = idx & 511;
    float v = Wo[k*256 + n];
    __nv_bfloat16 h, l; split2(v, h, l);
    g_Woh[n*512 + k] = h; g_Wol[n*512 + k] = l;
  }
}

// ---------------------------------------------------------------------------
// Tile loaders
// ---------------------------------------------------------------------------
#define TSTRIDE 72
#define GTILE (128*TSTRIDE)
#define ATILE (64*TSTRIDE)

__device__ __forceinline__ void cpa_tile128_512(
    __nv_bfloat16* dst, const __nv_bfloat16* __restrict__ src, int ldk, int tid)
{
#pragma unroll
  for (int it = 0; it < 2; it++) {
    int u = it*512 + tid;
    int row = u >> 3, c8 = (u & 7) * 8;
    cp16(smem_u32(dst + row*TSTRIDE + c8), src + row*ldk + c8);
  }
}

__device__ __forceinline__ void cpa_tile64(
    __nv_bfloat16* dst, const __nv_bfloat16* __restrict__ src, int tid)
{
#pragma unroll
  for (int it = 0; it < 2; it++) {
    int u = it*256 + tid;
    int row = u >> 3, c8 = (u & 7) * 8;
    cp16(smem_u32(dst + row*TSTRIDE + c8), src + row*64 + c8);
  }
}

// ---------------------------------------------------------------------------
// Dense GEMM core: block 128x128, 16 warps, warp tile 32x32.
// 3-stage cp.async, single barrier per chunk in the SAFE order:
//   wait(chunk kc) -> __syncthreads -> compute kc -> prefetch kc+2
// The barrier publishes chunk kc (all threads waited before it) AND
// guarantees compute(kc-1) finished before its stage is overwritten
// (prefetch comes after the barrier).
// ---------------------------------------------------------------------------
struct FragC { float c[2][4][4]; };

template <int KCHUNKS>
__device__ __forceinline__ void gemm_core(
    __nv_bfloat16* smb,
    const __nv_bfloat16* gAh, const __nv_bfloat16* gAl,
    const __nv_bfloat16* gBh, const __nv_bfloat16* gBl,
    int m0, int n0blk, int ldk, int tid, FragC& f)
{
  const int lane = tid & 31, wid = tid >> 5;
  const int wm = wid & 3, wn = wid >> 2;
  const int lrow = (lane & 7) + ((lane >> 3) & 1) * 8;
  const int lcol = (lane >> 4) * 8;

  uint32_t abase[3][2], bbase[3][2];
#pragma unroll
  for (int s = 0; s < 3; s++) {
    __nv_bfloat16* st = smb + s*4*GTILE;
    abase[s][0] = smem_u32(st)           + ((wm*32 + lrow)*TSTRIDE + lcol)*2;
    abase[s][1] = smem_u32(st + GTILE)   + ((wm*32 + lrow)*TSTRIDE + lcol)*2;
    bbase[s][0] = smem_u32(st + 2*GTILE) + ((wn*32 + lrow)*TSTRIDE + lcol)*2;
    bbase[s][1] = smem_u32(st + 3*GTILE) + ((wn*32 + lrow)*TSTRIDE + lcol)*2;
  }

#pragma unroll
  for (int mt = 0; mt < 2; mt++)
#pragma unroll
    for (int nt = 0; nt < 4; nt++)
#pragma unroll
      for (int q = 0; q < 4; q++) f.c[mt][nt][q] = 0.f;

  // prologue: chunks 0,1 -> stages 0,1 (two groups)
#pragma unroll
  for (int pc = 0; pc < 2; pc++) {
    __nv_bfloat16* st = smb + pc*4*GTILE;
    int co = pc*64;
    cpa_tile128_512(st,           gAh + m0*ldk + co,    ldk, tid);
    cpa_tile128_512(st + GTILE,   gAl + m0*ldk + co,    ldk, tid);
    cpa_tile128_512(st + 2*GTILE, gBh + n0blk*ldk + co, ldk, tid);
    cpa_tile128_512(st + 3*GTILE, gBl + n0blk*ldk + co, ldk, tid);
    CP_COMMIT();
  }

  for (int kc = 0; kc < KCHUNKS; kc++) {
    if (kc + 1 < KCHUNKS) { CP_WAIT(1); } else { CP_WAIT(0); }
    __syncthreads();   // publish chunk kc; protect stage being prefetched below

    const int s = kc % 3;
#pragma unroll
    for (int ks = 0; ks < 4; ks++) {
      uint32_t ah[2][4], al[2][4];
#pragma unroll
      for (int mt = 0; mt < 2; mt++) {
        uint32_t off = (mt*16*TSTRIDE + ks*16)*2;
        ldsm_x4(abase[s][0] + off, ah[mt][0], ah[mt][1], ah[mt][2], ah[mt][3]);
        ldsm_x4(abase[s][1] + off, al[mt][0], al[mt][1], al[mt][2], al[mt][3]);
      }
      uint32_t bh[4][2], bl[4][2];
#pragma unroll
      for (int np = 0; np < 2; np++) {
        uint32_t off = (np*16*TSTRIDE + ks*16)*2;
        uint32_t r0, r1, r2, r3;
        ldsm_x4(bbase[s][0] + off, r0, r1, r2, r3);
        bh[2*np][0] = r0; bh[2*np+1][0] = r1; bh[2*np][1] = r2; bh[2*np+1][1] = r3;
        ldsm_x4(bbase[s][1] + off, r0, r1, r2, r3);
        bl[2*np][0] = r0; bl[2*np+1][0] = r1; bl[2*np][1] = r2; bl[2*np+1][1] = r3;
      }
#pragma unroll
      for (int mt = 0; mt < 2; mt++)
#pragma unroll
        for (int nt = 0; nt < 4; nt++) {
          mma_bf16(f.c[mt][nt], ah[mt], bh[nt]);
          mma_bf16(f.c[mt][nt], ah[mt], bl[nt]);
          mma_bf16(f.c[mt][nt], al[mt], bh[nt]);
        }
    }

    if (kc + 2 < KCHUNKS) {
      int sidx = (kc+2) % 3;
      __nv_bfloat16* st = smb + sidx*4*GTILE;
      int co = (kc+2)*64;
      cpa_tile128_512(st,           gAh + m0*ldk + co,    ldk, tid);
      cpa_tile128_512(st + GTILE,   gAl + m0*ldk + co,    ldk, tid);
      cpa_tile128_512(st + 2*GTILE, gBh + n0blk*ldk + co, ldk, tid);
      cpa_tile128_512(st + 3*GTILE, gBl + n0blk*ldk + co, ldk, tid);
      CP_COMMIT();
    }
  }
}

// ---------------------------------------------------------------------------
// Projection GEMM (512 threads). Scatters split bf16 Q/K, fp16 V, fp32 gates.
// ---------------------------------------------------------------------------
__global__ __launch_bounds__(512) void proj_mma_kernel(const float* __restrict__ bg)
{
  extern __shared__ __nv_bfloat16 smb[];
  const int tid = threadIdx.x;
  const int c0 = blockIdx.x * 128;
  const int m0 = blockIdx.y * 128;

  FragC f;
  gemm_core<4>(smb, g_xh, g_xl, g_Wch, g_Wcl, m0, c0, 256, tid, f);

  const int lane = tid & 31, wid = tid >> 5;
  const int wm = wid & 3, wn = wid >> 2;
  const int q2 = (lane & 3) * 2, r4 = lane >> 2;
  const int seg = c0 >> 9;
  const int lbase = c0 - seg*512 + wn*32;

#pragma unroll
  for (int mt = 0; mt < 2; mt++) {
#pragma unroll
    for (int h2 = 0; h2 < 2; h2++) {
      const int m = m0 + wm*32 + mt*16 + r4 + h2*8;
      const int bidx = m >> 9, n = m & 511;
      if (seg == 3) {
        float* dst = g_G + m*512 + lbase;
#pragma unroll
        for (int nt = 0; nt < 4; nt++) {
          int cc = nt*8 + q2;
          float2 v;
          v.x = f.c[mt][nt][h2*2+0] + bg[lbase + cc];
          v.y = f.c[mt][nt][h2*2+1] + bg[lbase + cc + 1];
          *(float2*)(dst + cc) = v;
        }
      } else if (seg == 2) {
        const int hh = lbase >> 6;
        const int dbase = lbase & 63;
        const int off = (((bidx*8 + hh)*512 + n)*64) + dbase;
#pragma unroll
        for (int nt = 0; nt < 4; nt++) {
          int dd = nt*8 + q2;
          uint32_t ph, pl;
          split2packh(f.c[mt][nt][h2*2+0], f.c[mt][nt][h2*2+1], ph, pl);
          *(uint32_t*)(g_Vh + off + dd) = ph;
          *(uint32_t*)(g_Vl + off + dd) = pl;
        }
      } else {
        const int hh = lbase >> 6;
        const int dbase = lbase & 63;
        __nv_bfloat16* bh_ = (seg == 0) ? g_Qh : g_Kh;
        __nv_bfloat16* bl_ = (seg == 0) ? g_Ql : g_Kl;
        const int off = (((bidx*8 + hh)*512 + n)*64) + dbase;
#pragma unroll
        for (int nt = 0; nt < 4; nt++) {
          int dd = nt*8 + q2;
          uint32_t ph, pl;
          split2pack(f.c[mt][nt][h2*2+0], f.c[mt][nt][h2*2+1], ph, pl);
          *(uint32_t*)(bh_ + off + dd) = ph;
          *(uint32_t*)(bl_ + off + dd) = pl;
        }
      }
    }
  }
}

// ---------------------------------------------------------------------------
// Output GEMM (512 threads)
// ---------------------------------------------------------------------------
__global__ __launch_bounds__(512) void out_mma_kernel(
    const float* __restrict__ bo, float* __restrict__ Y)
{
  extern __shared__ __nv_bfloat16 smb[];
  const int tid = threadIdx.x;
  const int n0 = blockIdx.x * 128;
  const int m0 = blockIdx.y * 128;

  FragC f;
  gemm_core<8>(smb, g_Eh, g_El, g_Woh, g_Wol, m0, n0, 512, tid, f);

  const int lane = tid & 31, wid = tid >> 5;
  const int wm = wid & 3, wn = wid >> 2;
  const int q2 = (lane & 3) * 2, r4 = lane >> 2;

#pragma unroll
  for (int mt = 0; mt < 2; mt++) {
#pragma unroll
    for (int h2 = 0; h2 < 2; h2++) {
      const int m = m0 + wm*32 + mt*16 + r4 + h2*8;
      float* dst = Y + m*256 + n0 + wn*32;
      const float* bop = bo + n0 + wn*32;
#pragma unroll
      for (int nt = 0; nt < 4; nt++) {
        int cc = nt*8 + q2;
        float2 v;
        v.x = f.c[mt][nt][h2*2+0] + bop[cc];
        v.y = f.c[mt][nt][h2*2+1] + bop[cc + 1];
        *(float2*)(dst + cc) = v;
      }
    }
  }
}

// ---------------------------------------------------------------------------
// Flash attention v2-style (R10-proven barrier structure) + fp16 2-product PV.
// ---------------------------------------------------------------------------
__global__ __launch_bounds__(256, 2) void attn_flash_kernel(
    const float* __restrict__ bias)
{
  extern __shared__ __nv_bfloat16 smb[];
  __nv_bfloat16* Qh = smb;
  __nv_bfloat16* Ql = smb + ATILE;
  __nv_bfloat16* KV = smb + 2*ATILE;

  const int tid = threadIdx.x;
  const int lane = tid & 31, wid = tid >> 5;
  const int wm = wid & 3, wn = wid >> 2;
  const int lrow = (lane & 7) + ((lane >> 3) & 1) * 8;
  const int lcol = (lane >> 4) * 8;
  const int r4 = lane >> 2, q2 = (lane & 3) * 2;
  const int it0 = blockIdx.x * 64;
  const int h = blockIdx.y, b = blockIdx.z;

  const int bh_off = (b*8 + h) * 512 * 64;
  const __nv_bfloat16* Khs = g_Kh + bh_off;
  const __nv_bfloat16* Kls = g_Kl + bh_off;
  const __nv_bfloat16* Vhs = (const __nv_bfloat16*)(g_Vh + bh_off);
  const __nv_bfloat16* Vls = (const __nv_bfloat16*)(g_Vl + bh_off);

  cpa_tile64(Qh, g_Qh + bh_off + it0*64, tid);
  cpa_tile64(Ql, g_Ql + bh_off + it0*64, tid);
  cpa_tile64(KV,           Khs, tid);
  cpa_tile64(KV + ATILE,   Kls, tid);
  cpa_tile64(KV + 2*ATILE, Vhs, tid);
  cpa_tile64(KV + 3*ATILE, Vls, tid);
  CP_COMMIT();

  const uint32_t qh_base = smem_u32(Qh) + ((wm*16 + lrow)*TSTRIDE + lcol)*2;
  const uint32_t ql_base = smem_u32(Ql) + ((wm*16 + lrow)*TSTRIDE + lcol)*2;
  uint32_t kb[2][2], vb[2][2];
#pragma unroll
  for (int s = 0; s < 2; s++) {
    __nv_bfloat16* st = KV + s*4*ATILE;
    kb[s][0] = smem_u32(st)           + ((wn*32 + lrow)*TSTRIDE + lcol)*2;
    kb[s][1] = smem_u32(st + ATILE)   + ((wn*32 + lrow)*TSTRIDE + lcol)*2;
    vb[s][0] = smem_u32(st + 2*ATILE) + ((wn*32 + lrow)*TSTRIDE + lcol)*2;
    vb[s][1] = smem_u32(st + 3*ATILE) + ((wn*32 + lrow)*TSTRIDE + lcol)*2;
  }

  const int row0 = wm*16 + r4;
  const int row1 = row0 + 8;
  const unsigned char* mrow = g_mask + b*512;
  const bool mi0 = mrow[it0 + row0] != 0;
  const bool mi1 = mrow[it0 + row1] != 0;
  const float* brow0 = bias + (h*512 + it0 + row0)*512;
  const float* brow1 = bias + (h*512 + it0 + row1)*512;

  float m0r = -FLT_MAX, m1r = -FLT_MAX, l0r = 0.f, l1r = 0.f;
  float o[8][4];
#pragma unroll
  for (int nf = 0; nf < 8; nf++)
#pragma unroll
    for (int q = 0; q < 4; q++) o[nf][q] = 0.f;

  for (int jt = 0; jt < 8; jt++) {
    if (jt < 7) {
      __nv_bfloat16* st = KV + ((jt+1)&1)*4*ATILE;
      const int co = (jt+1)*64*64;
      cpa_tile64(st,           Khs + co, tid);
      cpa_tile64(st + ATILE,   Kls + co, tid);
      cpa_tile64(st + 2*ATILE, Vhs + co, tid);
      cpa_tile64(st + 3*ATILE, Vls + co, tid);
      CP_COMMIT();
      CP_WAIT(1);
    } else {
      CP_WAIT(0);
    }
    __syncthreads();

    const int s = jt & 1;
    // ---- S = Q K^T chunk (bf16 3-product) ----
    float c[4][4];
#pragma unroll
    for (int nf = 0; nf < 4; nf++)
#pragma unroll
      for (int q = 0; q < 4; q++) c[nf][q] = 0.f;

#pragma unroll
    for (int ks = 0; ks < 4; ks++) {
      uint32_t ah[4], al[4];
      ldsm_x4(qh_base + ks*32, ah[0], ah[1], ah[2], ah[3]);
      ldsm_x4(ql_base + ks*32, al[0], al[1], al[2], al[3]);
#pragma unroll
      for (int np = 0; np < 2; np++) {
        uint32_t off = (np*16*TSTRIDE + ks*16)*2;
        uint32_t r0, r1, r2, r3;
        ldsm_x4(kb[s][0] + off, r0, r1, r2, r3);
        uint32_t bh0[2] = {r0, r2}, bh1[2] = {r1, r3};
        ldsm_x4(kb[s][1] + off, r0, r1, r2, r3);
        uint32_t bl0[2] = {r0, r2}, bl1[2] = {r1, r3};
        mma_bf16(c[2*np],   ah, bh0); mma_bf16(c[2*np],   ah, bl0);
        mma_bf16(c[2*np],   al, bh0);
        mma_bf16(c[2*np+1], ah, bh1); mma_bf16(c[2*np+1], ah, bl1);
        mma_bf16(c[2*np+1], al, bh1);
      }
    }

    // ---- scale + bias + mask; per-warp row max ----
    const int colbase = jt*64 + wn*32;
    float rm0 = -FLT_MAX, rm1 = -FLT_MAX;
#pragma unroll
    for (int nf = 0; nf < 4; nf++) {
      const int col = colbase + nf*8 + q2;
      float2 b0 = *(const float2*)&brow0[col];
      float2 b1 = *(const float2*)&brow1[col];
      bool mjA = mrow[col] != 0, mjB = mrow[col+1] != 0;
      c[nf][0] = (mi0 && mjA) ? c[nf][0]*SCALE_ + b0.x : -FLT_MAX;
      c[nf][1] = (mi0 && mjB) ? c[nf][1]*SCALE_ + b0.y : -FLT_MAX;
      c[nf][2] = (mi1 && mjA) ? c[nf][2]*SCALE_ + b1.x : -FLT_MAX;
      c[nf][3] = (mi1 && mjB) ? c[nf][3]*SCALE_ + b1.y : -FLT_MAX;
      rm0 = fmaxf(rm0, fmaxf(c[nf][0], c[nf][1]));
      rm1 = fmaxf(rm1, fmaxf(c[nf][2], c[nf][3]));
    }
    rm0 = fmaxf(rm0, __shfl_xor_sync(0xffffffffu, rm0, 1));
    rm0 = fmaxf(rm0, __shfl_xor_sync(0xffffffffu, rm0, 2));
    rm1 = fmaxf(rm1, __shfl_xor_sync(0xffffffffu, rm1, 1));
    rm1 = fmaxf(rm1, __shfl_xor_sync(0xffffffffu, rm1, 2));

    const float mn0 = fmaxf(m0r, rm0), mn1 = fmaxf(m1r, rm1);
    const float fs0 = __expf(m0r - mn0), fs1 = __expf(m1r - mn1);

    float ls0 = 0.f, ls1 = 0.f;
#pragma unroll
    for (int nf = 0; nf < 4; nf++) {
      c[nf][0] = __expf(c[nf][0] - mn0);
      c[nf][1] = __expf(c[nf][1] - mn0);
      c[nf][2] = __expf(c[nf][2] - mn1);
      c[nf][3] = __expf(c[nf][3] - mn1);
      ls0 += c[nf][0] + c[nf][1];
      ls1 += c[nf][2] + c[nf][3];
    }
    ls0 += __shfl_xor_sync(0xffffffffu, ls0, 1);
    ls0 += __shfl_xor_sync(0xffffffffu, ls0, 2);
    ls1 += __shfl_xor_sync(0xffffffffu, ls1, 1);
    ls1 += __shfl_xor_sync(0xffffffffu, ls1, 2);
    l0r = l0r*fs0 + ls0;
    l1r = l1r*fs1 + ls1;
    m0r = mn0; m1r = mn1;

    // ---- rescale O; pack P into fp16 A-fragments ----
#pragma unroll
    for (int nf = 0; nf < 8; nf++) {
      o[nf][0] *= fs0; o[nf][1] *= fs0;
      o[nf][2] *= fs1; o[nf][3] *= fs1;
    }
    uint32_t ap[2][4];
#pragma unroll
    for (int ks2 = 0; ks2 < 2; ks2++) {
      ap[ks2][0] = pack2f16(c[2*ks2][0],   c[2*ks2][1]);
      ap[ks2][1] = pack2f16(c[2*ks2][2],   c[2*ks2][3]);
      ap[ks2][2] = pack2f16(c[2*ks2+1][0], c[2*ks2+1][1]);
      ap[ks2][3] = pack2f16(c[2*ks2+1][2], c[2*ks2+1][3]);
    }

    // ---- O += P V (fp16 2-product) ----
#pragma unroll
    for (int ks2 = 0; ks2 < 2; ks2++) {
      uint32_t bh[8][2], bl[8][2];
#pragma unroll
      for (int np = 0; np < 4; np++) {
        uint32_t off = (ks2*16*TSTRIDE + np*16)*2;
        uint32_t r0, r1, r2, r3;
        ldsm_x4_t(vb[s][0] + off, r0, r1, r2, r3);
        bh[2*np][0] = r0; bh[2*np][1] = r1; bh[2*np+1][0] = r2; bh[2*np+1][1] = r3;
        ldsm_x4_t(vb[s][1] + off, r0, r1, r2, r3);
        bl[2*np][0] = r0; bl[2*np][1] = r1; bl[2*np+1][0] = r2; bl[2*np+1][1] = r3;
      }
#pragma unroll
      for (int nf = 0; nf < 8; nf++) {
        mma_f16(o[nf], ap[ks2], bh[nf]);
        mma_f16(o[nf], ap[ks2], bl[nf]);
      }
    }
    // all warps must finish reading this KV stage before next prefetch
    __syncthreads();
  }

  // ---- cross-warp merge (wn=0 <- wn=1), gate, split-store ----
  float* O1  = (float*)KV;          // [64][68]
  float* m1s = O1 + 64*68;          // [64]
  float* l1s = m1s + 64;            // [64]

  if (wn == 1) {
#pragma unroll
    for (int nf = 0; nf < 8; nf++) {
      const int d = nf*8 + q2;
      *(float2*)&O1[row0*68 + d] = make_float2(o[nf][0], o[nf][1]);
      *(float2*)&O1[row1*68 + d] = make_float2(o[nf][2], o[nf][3]);
    }
    if ((lane & 3) == 0) {
      m1s[row0] = m0r; l1s[row0] = l0r;
      m1s[row1] = m1r; l1s[row1] = l1r;
    }
  }
  __syncthreads();

  if (wn == 0) {
    const float mo0 = m1s[row0], lo0 = l1s[row0];
    const float mo1 = m1s[row1], lo1 = l1s[row1];
    const float mf0 = fmaxf(m0r, mo0), mf1 = fmaxf(m1r, mo1);
    const float a0 = __expf(m0r - mf0), b0s = __expf(mo0 - mf0);
    const float a1 = __expf(m1r - mf1), b1s = __expf(mo1 - mf1);
    const float inv0 = 1.0f / (l0r*a0 + lo0*b0s);
    const float inv1 = 1.0f / (l1r*a1 + lo1*b1s);

#pragma unroll
    for (int nf = 0; nf < 8; nf++) {
      const int d = nf*8 + q2;
      const int idx0 = (b*512 + it0 + row0)*512 + h*64 + d;
      const int idx1 = (b*512 + it0 + row1)*512 + h*64 + d;
      float2 p0 = *(float2*)&O1[row0*68 + d];
      float2 p1 = *(float2*)&O1[row1*68 + d];
      float2 gv0 = *(const float2*)(g_G + idx0);
      float2 gv1 = *(const float2*)(g_G + idx1);
      float e00 = (o[nf][0]*a0 + p0.x*b0s) * inv0 * gv0.x;
      float e01 = (o[nf][1]*a0 + p0.y*b0s) * inv0 * gv0.y;
      float e10 = (o[nf][2]*a1 + p1.x*b1s) * inv1 * gv1.x;
      float e11 = (o[nf][3]*a1 + p1.y*b1s) * inv1 * gv1.y;
      uint32_t ph, pl;
      split2pack(e00, e01, ph, pl);
      *(uint32_t*)(g_Eh + idx0) = ph;
      *(uint32_t*)(g_El + idx0) = pl;
      split2pack(e10, e11, ph, pl);
      *(uint32_t*)(g_Eh + idx1) = ph;
      *(uint32_t*)(g_El + idx1) = pl;
    }
  }
}

// ---------------------------------------------------------------------------
extern "C" void kernel_launch(void* const* d_in, const int* in_sizes, int n_in,
                              void* d_out, int out_size)
{
  const float* x   = (const float*)d_in[0];
  const void*  mask = d_in[1];
  const float* bias = (const float*)d_in[2];
  const float* Wq  = (const float*)d_in[3];
  const float* Wkv = (const float*)d_in[4];
  const float* Wo  = (const float*)d_in[5];
  const float* bo  = (const float*)d_in[6];
  const float* Wg  = (const float*)d_in[7];
  const float* bg  = (const float*)d_in[8];
  float* Y = (float*)d_out;

  const int SMEM_ATTN = 10*ATILE*2;               // 92160 B -> 2 CTAs/SM
  const int SMEM_MMA  = 12 * GTILE * 2;           // 221184 B (3-stage)
  cudaFuncSetAttribute(attn_flash_kernel, cudaFuncAttributeMaxDynamicSharedMemorySize,
                       SMEM_ATTN);
  cudaFuncSetAttribute(proj_mma_kernel, cudaFuncAttributeMaxDynamicSharedMemorySize,
                       SMEM_MMA);
  cudaFuncSetAttribute(out_mma_kernel, cudaFuncAttributeMaxDynamicSharedMemorySize,
                       SMEM_MMA);

  detect_mask_kernel<<<1, 256>>>((const unsigned int*)mask);
  convert_mask_kernel<<<128, 256>>>(mask);
  split_all_kernel<<<10752, 256>>>(x, Wq, Wkv, Wg, Wo);
  proj_mma_kernel<<<dim3(16, 256), 512, SMEM_MMA>>>(bg);
  attn_flash_kernel<<<dim3(8, 8, 64), 256, SMEM_ATTN>>>(bias);
  out_mma_kernel<<<dim3(2, 256), 512, SMEM_MMA>>>(bo, Y);
}

// round 13
// speedup vs baseline: 1.3201x; 1.1310x over previous
#include <cuda_runtime.h>
#include <cuda_bf16.h>
#include <cuda_fp16.h>
#include <cfloat>
#include <cstdint>

#define BB_   64
#define NN_   512
#define DIM_  256
#define HH_   8
#define DHH_  64
#define INNER_ 512
#define SCALE_ 0.125f

// ---------------------------------------------------------------------------
// Scratch
// ---------------------------------------------------------------------------
__device__ float g_G[BB_*NN_*INNER_];
__device__ unsigned char g_mask[BB_*NN_];
__device__ int g_mask_mode;

__device__ __half        g_xfh[BB_*NN_*DIM_];      // x fp16 split
__device__ __half        g_xfl[BB_*NN_*DIM_];
__device__ __half        g_Wcf[2048*DIM_];         // concat W^T fp16 single
__device__ __nv_bfloat16 g_Qh[BB_*HH_*NN_*DHH_];   // Q/K bf16 split (QK 3-term)
__device__ __nv_bfloat16 g_Ql[BB_*HH_*NN_*DHH_];
__device__ __nv_bfloat16 g_Kh[BB_*HH_*NN_*DHH_];
__device__ __nv_bfloat16 g_Kl[BB_*HH_*NN_*DHH_];
__device__ __half        g_Vh[BB_*HH_*NN_*DHH_];   // V fp16 split
__device__ __half        g_Vl[BB_*HH_*NN_*DHH_];
__device__ __half        g_Eh[BB_*NN_*INNER_];     // gated attn out fp16 split
__device__ __half        g_El[BB_*NN_*INNER_];
__device__ __half        g_Wof[DIM_*INNER_];       // Wo^T fp16 single

// ---------------------------------------------------------------------------
// Helpers
// ---------------------------------------------------------------------------
__device__ __forceinline__ uint32_t smem_u32(const void* p) {
  uint32_t a;
  asm("{ .reg .u64 t; cvta.to.shared.u64 t, %1; cvt.u32.u64 %0, t; }"
      : "=r"(a) : "l"(p));
  return a;
}
__device__ __forceinline__ void cp16(uint32_t saddr, const void* g) {
  asm volatile("cp.async.cg.shared.global [%0], [%1], 16;"
               :: "r"(saddr), "l"(g));
}
#define CP_COMMIT() asm volatile("cp.async.commit_group;" ::: "memory")
#define CP_WAIT(n)  asm volatile("cp.async.wait_group %0;" :: "n"(n) : "memory")

__device__ __forceinline__ void ldsm_x4(uint32_t addr, uint32_t& r0,
                                        uint32_t& r1, uint32_t& r2, uint32_t& r3) {
  asm volatile("ldmatrix.sync.aligned.m8n8.x4.shared.b16 {%0,%1,%2,%3}, [%4];"
               : "=r"(r0), "=r"(r1), "=r"(r2), "=r"(r3) : "r"(addr));
}
__device__ __forceinline__ void ldsm_x4_t(uint32_t addr, uint32_t& r0,
                                          uint32_t& r1, uint32_t& r2, uint32_t& r3) {
  asm volatile("ldmatrix.sync.aligned.m8n8.x4.trans.shared.b16 {%0,%1,%2,%3}, [%4];"
               : "=r"(r0), "=r"(r1), "=r"(r2), "=r"(r3) : "r"(addr));
}
__device__ __forceinline__ void mma_bf16(float* c, const uint32_t* a,
                                         const uint32_t* b) {
  asm volatile(
    "mma.sync.aligned.m16n8k16.row.col.f32.bf16.bf16.f32 "
    "{%0,%1,%2,%3}, {%4,%5,%6,%7}, {%8,%9}, {%0,%1,%2,%3};"
    : "+f"(c[0]), "+f"(c[1]), "+f"(c[2]), "+f"(c[3])
    : "r"(a[0]), "r"(a[1]), "r"(a[2]), "r"(a[3]), "r"(b[0]), "r"(b[1]));
}
__device__ __forceinline__ void mma_f16(float* c, const uint32_t* a,
                                        const uint32_t* b) {
  asm volatile(
    "mma.sync.aligned.m16n8k16.row.col.f32.f16.f16.f32 "
    "{%0,%1,%2,%3}, {%4,%5,%6,%7}, {%8,%9}, {%0,%1,%2,%3};"
    : "+f"(c[0]), "+f"(c[1]), "+f"(c[2]), "+f"(c[3])
    : "r"(a[0]), "r"(a[1]), "r"(a[2]), "r"(a[3]), "r"(b[0]), "r"(b[1]));
}
__device__ __forceinline__ void split2(float v, __nv_bfloat16& h, __nv_bfloat16& l) {
  h = __float2bfloat16(v);
  l = __float2bfloat16(v - __bfloat162float(h));
}
__device__ __forceinline__ uint32_t pack2(__nv_bfloat16 a, __nv_bfloat16 b) {
  return (uint32_t)*(uint16_t*)&a | ((uint32_t)*(uint16_t*)&b << 16);
}
__device__ __forceinline__ void split2pack(float v0, float v1,
                                           uint32_t& ph, uint32_t& pl) {
  __nv_bfloat16 h0, l0, h1, l1;
  split2(v0, h0, l0); split2(v1, h1, l1);
  ph = pack2(h0, h1); pl = pack2(l0, l1);
}
// fp16 split: hi + residual
__device__ __forceinline__ void split2packh(float v0, float v1,
                                            uint32_t& ph, uint32_t& pl) {
  __half h0 = __float2half_rn(v0), h1 = __float2half_rn(v1);
  __half l0 = __float2half_rn(v0 - __half2float(h0));
  __half l1 = __float2half_rn(v1 - __half2float(h1));
  ph = (uint32_t)*(uint16_t*)&h0 | ((uint32_t)*(uint16_t*)&h1 << 16);
  pl = (uint32_t)*(uint16_t*)&l0 | ((uint32_t)*(uint16_t*)&l1 << 16);
}
__device__ __forceinline__ uint32_t pack2f16(float a, float b) {
  __half2 hh = __floats2half2_rn(a, b);
  return *(uint32_t*)&hh;
}

// ---------------------------------------------------------------------------
// Mask detection + conversion (proven)
// ---------------------------------------------------------------------------
__global__ void detect_mask_kernel(const unsigned int* __restrict__ m)
{
  __shared__ int s_not01, s_notf;
  if (threadIdx.x == 0) { s_not01 = 0; s_notf = 0; }
  __syncthreads();
  int a = 0, b = 0;
  for (int i = threadIdx.x; i < 8192; i += 256) {
    unsigned v = m[i];
    if (v != 0u && v != 1u) a = 1;
    if (v != 0u && v != 0x3F800000u) b = 1;
  }
  if (a) atomicOr(&s_not01, 1);
  if (b) atomicOr(&s_notf, 1);
  __syncthreads();
  if (threadIdx.x == 0)
    g_mask_mode = (!s_not01) ? 0 : ((!s_notf) ? 1 : 2);
}

__global__ void convert_mask_kernel(const void* __restrict__ m)
{
  int idx = blockIdx.x * blockDim.x + threadIdx.x;
  if (idx >= BB_*NN_) return;
  int mode = g_mask_mode;
  unsigned char r;
  if (mode == 0)      r = ((const int*)m)[idx] != 0;
  else if (mode == 1) r = ((const unsigned int*)m)[idx] != 0u;
  else                r = ((const unsigned char*)m)[idx] != 0;
  g_mask[idx] = r;
}

// ---------------------------------------------------------------------------
// Fused split conversions: x -> fp16 split; W concat -> fp16; Wo -> fp16
// ---------------------------------------------------------------------------
__global__ void split_all_kernel(const float* __restrict__ x,
                                 const float* __restrict__ Wq,
                                 const float* __restrict__ Wkv,
                                 const float* __restrict__ Wg,
                                 const float* __restrict__ Wo)
{
  int bid = blockIdx.x;
  if (bid < 8192) {
    int i = (bid * 256 + threadIdx.x) * 4;
    float4 v = *(const float4*)(x + i);
    uint32_t h0, l0, h1, l1;
    split2packh(v.x, v.y, h0, l0);
    split2packh(v.z, v.w, h1, l1);
    *(uint2*)(g_xfh + i) = make_uint2(h0, h1);
    *(uint2*)(g_xfl + i) = make_uint2(l0, l1);
  } else if (bid < 10240) {
    int idx = (bid - 8192) * 256 + threadIdx.x;
    int k = idx & 255, n = idx >> 8;
    int seg = n >> 9, col = n & 511;
    float v;
    if (seg == 0)      v = Wq[k*512 + col];
    else if (seg == 1) v = Wkv[k*1024 + col];
    else if (seg == 2) v = Wkv[k*1024 + 512 + col];
    else               v = Wg[k*512 + col];
    g_Wcf[n*256 + k] = __float2half_rn(v);
  } else {
    int idx = (bid - 10240) * 256 + threadIdx.x;
    int n = idx >> 9, k = idx & 511;
    g_Wof[n*512 + k] = __float2half_rn(Wo[k*256 + n]);
  }
}

// ---------------------------------------------------------------------------
// Tile loaders (operate on raw 16-bit element arrays)
// ---------------------------------------------------------------------------
#define TSTRIDE 72
#define GTILE (128*TSTRIDE)
#define ATILE (64*TSTRIDE)

__device__ __forceinline__ void cpa_tile128_512(
    uint16_t* dst, const uint16_t* __restrict__ src, int ldk, int tid)
{
#pragma unroll
  for (int it = 0; it < 2; it++) {
    int u = it*512 + tid;
    int row = u >> 3, c8 = (u & 7) * 8;
    cp16(smem_u32(dst + row*TSTRIDE + c8), src + row*ldk + c8);
  }
}

__device__ __forceinline__ void cpa_tile64(
    uint16_t* dst, const uint16_t* __restrict__ src, int tid)
{
#pragma unroll
  for (int it = 0; it < 2; it++) {
    int u = it*256 + tid;
    int row = u >> 3, c8 = (u & 7) * 8;
    cp16(smem_u32(dst + row*TSTRIDE + c8), src + row*64 + c8);
  }
}

// ---------------------------------------------------------------------------
// Dense GEMM core (fp16 2-term): block 128x128, 16 warps, warp tile 32x32.
// C = Ah*B + Al*B. 3-stage cp.async, safe single-barrier order:
//   wait(kc) -> __syncthreads -> compute kc -> prefetch kc+2
// ---------------------------------------------------------------------------
struct FragC { float c[2][4][4]; };

template <int KCHUNKS>
__device__ __forceinline__ void gemm_core2(
    uint16_t* smb,
    const __half* gAh, const __half* gAl, const __half* gB,
    int m0, int n0blk, int ldk, int tid, FragC& f)
{
  const int lane = tid & 31, wid = tid >> 5;
  const int wm = wid & 3, wn = wid >> 2;
  const int lrow = (lane & 7) + ((lane >> 3) & 1) * 8;
  const int lcol = (lane >> 4) * 8;

  uint32_t abase[3][2], bbase[3];
#pragma unroll
  for (int s = 0; s < 3; s++) {
    uint16_t* st = smb + s*3*GTILE;
    abase[s][0] = smem_u32(st)           + ((wm*32 + lrow)*TSTRIDE + lcol)*2;
    abase[s][1] = smem_u32(st + GTILE)   + ((wm*32 + lrow)*TSTRIDE + lcol)*2;
    bbase[s]    = smem_u32(st + 2*GTILE) + ((wn*32 + lrow)*TSTRIDE + lcol)*2;
  }

#pragma unroll
  for (int mt = 0; mt < 2; mt++)
#pragma unroll
    for (int nt = 0; nt < 4; nt++)
#pragma unroll
      for (int q = 0; q < 4; q++) f.c[mt][nt][q] = 0.f;

#pragma unroll
  for (int pc = 0; pc < 2; pc++) {
    uint16_t* st = smb + pc*3*GTILE;
    int co = pc*64;
    cpa_tile128_512(st,           (const uint16_t*)gAh + m0*ldk + co,    ldk, tid);
    cpa_tile128_512(st + GTILE,   (const uint16_t*)gAl + m0*ldk + co,    ldk, tid);
    cpa_tile128_512(st + 2*GTILE, (const uint16_t*)gB  + n0blk*ldk + co, ldk, tid);
    CP_COMMIT();
  }

  for (int kc = 0; kc < KCHUNKS; kc++) {
    if (kc + 1 < KCHUNKS) { CP_WAIT(1); } else { CP_WAIT(0); }
    __syncthreads();

    const int s = kc % 3;
#pragma unroll
    for (int ks = 0; ks < 4; ks++) {
      uint32_t ah[2][4], al[2][4];
#pragma unroll
      for (int mt = 0; mt < 2; mt++) {
        uint32_t off = (mt*16*TSTRIDE + ks*16)*2;
        ldsm_x4(abase[s][0] + off, ah[mt][0], ah[mt][1], ah[mt][2], ah[mt][3]);
        ldsm_x4(abase[s][1] + off, al[mt][0], al[mt][1], al[mt][2], al[mt][3]);
      }
      uint32_t bb[4][2];
#pragma unroll
      for (int np = 0; np < 2; np++) {
        uint32_t off = (np*16*TSTRIDE + ks*16)*2;
        uint32_t r0, r1, r2, r3;
        ldsm_x4(bbase[s] + off, r0, r1, r2, r3);
        bb[2*np][0] = r0; bb[2*np+1][0] = r1; bb[2*np][1] = r2; bb[2*np+1][1] = r3;
      }
#pragma unroll
      for (int mt = 0; mt < 2; mt++)
#pragma unroll
        for (int nt = 0; nt < 4; nt++) {
          mma_f16(f.c[mt][nt], ah[mt], bb[nt]);
          mma_f16(f.c[mt][nt], al[mt], bb[nt]);
        }
    }

    if (kc + 2 < KCHUNKS) {
      int sidx = (kc+2) % 3;
      uint16_t* st = smb + sidx*3*GTILE;
      int co = (kc+2)*64;
      cpa_tile128_512(st,           (const uint16_t*)gAh + m0*ldk + co,    ldk, tid);
      cpa_tile128_512(st + GTILE,   (const uint16_t*)gAl + m0*ldk + co,    ldk, tid);
      cpa_tile128_512(st + 2*GTILE, (const uint16_t*)gB  + n0blk*ldk + co, ldk, tid);
      CP_COMMIT();
    }
  }
}

// ---------------------------------------------------------------------------
// Projection GEMM (512 threads). Scatters bf16 Q/K split, fp16 V split, gates.
// ---------------------------------------------------------------------------
__global__ __launch_bounds__(512) void proj_mma_kernel(const float* __restrict__ bg)
{
  extern __shared__ uint16_t smb[];
  const int tid = threadIdx.x;
  const int c0 = blockIdx.x * 128;
  const int m0 = blockIdx.y * 128;

  FragC f;
  gemm_core2<4>(smb, g_xfh, g_xfl, g_Wcf, m0, c0, 256, tid, f);

  const int lane = tid & 31, wid = tid >> 5;
  const int wm = wid & 3, wn = wid >> 2;
  const int q2 = (lane & 3) * 2, r4 = lane >> 2;
  const int seg = c0 >> 9;
  const int lbase = c0 - seg*512 + wn*32;

#pragma unroll
  for (int mt = 0; mt < 2; mt++) {
#pragma unroll
    for (int h2 = 0; h2 < 2; h2++) {
      const int m = m0 + wm*32 + mt*16 + r4 + h2*8;
      const int bidx = m >> 9, n = m & 511;
      if (seg == 3) {
        float* dst = g_G + m*512 + lbase;
#pragma unroll
        for (int nt = 0; nt < 4; nt++) {
          int cc = nt*8 + q2;
          float2 v;
          v.x = f.c[mt][nt][h2*2+0] + bg[lbase + cc];
          v.y = f.c[mt][nt][h2*2+1] + bg[lbase + cc + 1];
          *(float2*)(dst + cc) = v;
        }
      } else if (seg == 2) {
        const int hh = lbase >> 6;
        const int dbase = lbase & 63;
        const int off = (((bidx*8 + hh)*512 + n)*64) + dbase;
#pragma unroll
        for (int nt = 0; nt < 4; nt++) {
          int dd = nt*8 + q2;
          uint32_t ph, pl;
          split2packh(f.c[mt][nt][h2*2+0], f.c[mt][nt][h2*2+1], ph, pl);
          *(uint32_t*)(g_Vh + off + dd) = ph;
          *(uint32_t*)(g_Vl + off + dd) = pl;
        }
      } else {
        const int hh = lbase >> 6;
        const int dbase = lbase & 63;
        __nv_bfloat16* bh_ = (seg == 0) ? g_Qh : g_Kh;
        __nv_bfloat16* bl_ = (seg == 0) ? g_Ql : g_Kl;
        const int off = (((bidx*8 + hh)*512 + n)*64) + dbase;
#pragma unroll
        for (int nt = 0; nt < 4; nt++) {
          int dd = nt*8 + q2;
          uint32_t ph, pl;
          split2pack(f.c[mt][nt][h2*2+0], f.c[mt][nt][h2*2+1], ph, pl);
          *(uint32_t*)(bh_ + off + dd) = ph;
          *(uint32_t*)(bl_ + off + dd) = pl;
        }
      }
    }
  }
}

// ---------------------------------------------------------------------------
// Output GEMM (512 threads): Y = E @ Wo^T + bo (fp16 2-term)
// ---------------------------------------------------------------------------
__global__ __launch_bounds__(512) void out_mma_kernel(
    const float* __restrict__ bo, float* __restrict__ Y)
{
  extern __shared__ uint16_t smb[];
  const int tid = threadIdx.x;
  const int n0 = blockIdx.x * 128;
  const int m0 = blockIdx.y * 128;

  FragC f;
  gemm_core2<8>(smb, g_Eh, g_El, g_Wof, m0, n0, 512, tid, f);

  const int lane = tid & 31, wid = tid >> 5;
  const int wm = wid & 3, wn = wid >> 2;
  const int q2 = (lane & 3) * 2, r4 = lane >> 2;

#pragma unroll
  for (int mt = 0; mt < 2; mt++) {
#pragma unroll
    for (int h2 = 0; h2 < 2; h2++) {
      const int m = m0 + wm*32 + mt*16 + r4 + h2*8;
      float* dst = Y + m*256 + n0 + wn*32;
      const float* bop = bo + n0 + wn*32;
#pragma unroll
      for (int nt = 0; nt < 4; nt++) {
        int cc = nt*8 + q2;
        float2 v;
        v.x = f.c[mt][nt][h2*2+0] + bop[cc];
        v.y = f.c[mt][nt][h2*2+1] + bop[cc + 1];
        *(float2*)(dst + cc) = v;
      }
    }
  }
}

// ---------------------------------------------------------------------------
// Flash attention v2-style (R12 proven). QK bf16 3-term, PV fp16 2-product.
// Epilogue writes E as fp16 split.
// ---------------------------------------------------------------------------
__global__ __launch_bounds__(256, 2) void attn_flash_kernel(
    const float* __restrict__ bias)
{
  extern __shared__ uint16_t smbu[];
  uint16_t* Qh = smbu;
  uint16_t* Ql = smbu + ATILE;
  uint16_t* KV = smbu + 2*ATILE;

  const int tid = threadIdx.x;
  const int lane = tid & 31, wid = tid >> 5;
  const int wm = wid & 3, wn = wid >> 2;
  const int lrow = (lane & 7) + ((lane >> 3) & 1) * 8;
  const int lcol = (lane >> 4) * 8;
  const int r4 = lane >> 2, q2 = (lane & 3) * 2;
  const int it0 = blockIdx.x * 64;
  const int h = blockIdx.y, b = blockIdx.z;

  const int bh_off = (b*8 + h) * 512 * 64;
  const uint16_t* Khs = (const uint16_t*)(g_Kh + bh_off);
  const uint16_t* Kls = (const uint16_t*)(g_Kl + bh_off);
  const uint16_t* Vhs = (const uint16_t*)(g_Vh + bh_off);
  const uint16_t* Vls = (const uint16_t*)(g_Vl + bh_off);

  cpa_tile64(Qh, (const uint16_t*)(g_Qh + bh_off + it0*64), tid);
  cpa_tile64(Ql, (const uint16_t*)(g_Ql + bh_off + it0*64), tid);
  cpa_tile64(KV,           Khs, tid);
  cpa_tile64(KV + ATILE,   Kls, tid);
  cpa_tile64(KV + 2*ATILE, Vhs, tid);
  cpa_tile64(KV + 3*ATILE, Vls, tid);
  CP_COMMIT();

  const uint32_t qh_base = smem_u32(Qh) + ((wm*16 + lrow)*TSTRIDE + lcol)*2;
  const uint32_t ql_base = smem_u32(Ql) + ((wm*16 + lrow)*TSTRIDE + lcol)*2;
  uint32_t kb[2][2], vb[2][2];
#pragma unroll
  for (int s = 0; s < 2; s++) {
    uint16_t* st = KV + s*4*ATILE;
    kb[s][0] = smem_u32(st)           + ((wn*32 + lrow)*TSTRIDE + lcol)*2;
    kb[s][1] = smem_u32(st + ATILE)   + ((wn*32 + lrow)*TSTRIDE + lcol)*2;
    vb[s][0] = smem_u32(st + 2*ATILE) + ((wn*32 + lrow)*TSTRIDE + lcol)*2;
    vb[s][1] = smem_u32(st + 3*ATILE) + ((wn*32 + lrow)*TSTRIDE + lcol)*2;
  }

  const int row0 = wm*16 + r4;
  const int row1 = row0 + 8;
  const unsigned char* mrow = g_mask + b*512;
  const bool mi0 = mrow[it0 + row0] != 0;
  const bool mi1 = mrow[it0 + row1] != 0;
  const float* brow0 = bias + (h*512 + it0 + row0)*512;
  const float* brow1 = bias + (h*512 + it0 + row1)*512;

  float m0r = -FLT_MAX, m1r = -FLT_MAX, l0r = 0.f, l1r = 0.f;
  float o[8][4];
#pragma unroll
  for (int nf = 0; nf < 8; nf++)
#pragma unroll
    for (int q = 0; q < 4; q++) o[nf][q] = 0.f;

  for (int jt = 0; jt < 8; jt++) {
    if (jt < 7) {
      uint16_t* st = KV + ((jt+1)&1)*4*ATILE;
      const int co = (jt+1)*64*64;
      cpa_tile64(st,           Khs + co, tid);
      cpa_tile64(st + ATILE,   Kls + co, tid);
      cpa_tile64(st + 2*ATILE, Vhs + co, tid);
      cpa_tile64(st + 3*ATILE, Vls + co, tid);
      CP_COMMIT();
      CP_WAIT(1);
    } else {
      CP_WAIT(0);
    }
    __syncthreads();

    const int s = jt & 1;
    float c[4][4];
#pragma unroll
    for (int nf = 0; nf < 4; nf++)
#pragma unroll
      for (int q = 0; q < 4; q++) c[nf][q] = 0.f;

#pragma unroll
    for (int ks = 0; ks < 4; ks++) {
      uint32_t ah[4], al[4];
      ldsm_x4(qh_base + ks*32, ah[0], ah[1], ah[2], ah[3]);
      ldsm_x4(ql_base + ks*32, al[0], al[1], al[2], al[3]);
#pragma unroll
      for (int np = 0; np < 2; np++) {
        uint32_t off = (np*16*TSTRIDE + ks*16)*2;
        uint32_t r0, r1, r2, r3;
        ldsm_x4(kb[s][0] + off, r0, r1, r2, r3);
        uint32_t bh0[2] = {r0, r2}, bh1[2] = {r1, r3};
        ldsm_x4(kb[s][1] + off, r0, r1, r2, r3);
        uint32_t bl0[2] = {r0, r2}, bl1[2] = {r1, r3};
        mma_bf16(c[2*np],   ah, bh0); mma_bf16(c[2*np],   ah, bl0);
        mma_bf16(c[2*np],   al, bh0);
        mma_bf16(c[2*np+1], ah, bh1); mma_bf16(c[2*np+1], ah, bl1);
        mma_bf16(c[2*np+1], al, bh1);
      }
    }

    const int colbase = jt*64 + wn*32;
    float rm0 = -FLT_MAX, rm1 = -FLT_MAX;
#pragma unroll
    for (int nf = 0; nf < 4; nf++) {
      const int col = colbase + nf*8 + q2;
      float2 b0 = *(const float2*)&brow0[col];
      float2 b1 = *(const float2*)&brow1[col];
      bool mjA = mrow[col] != 0, mjB = mrow[col+1] != 0;
      c[nf][0] = (mi0 && mjA) ? c[nf][0]*SCALE_ + b0.x : -FLT_MAX;
      c[nf][1] = (mi0 && mjB) ? c[nf][1]*SCALE_ + b0.y : -FLT_MAX;
      c[nf][2] = (mi1 && mjA) ? c[nf][2]*SCALE_ + b1.x : -FLT_MAX;
      c[nf][3] = (mi1 && mjB) ? c[nf][3]*SCALE_ + b1.y : -FLT_MAX;
      rm0 = fmaxf(rm0, fmaxf(c[nf][0], c[nf][1]));
      rm1 = fmaxf(rm1, fmaxf(c[nf][2], c[nf][3]));
    }
    rm0 = fmaxf(rm0, __shfl_xor_sync(0xffffffffu, rm0, 1));
    rm0 = fmaxf(rm0, __shfl_xor_sync(0xffffffffu, rm0, 2));
    rm1 = fmaxf(rm1, __shfl_xor_sync(0xffffffffu, rm1, 1));
    rm1 = fmaxf(rm1, __shfl_xor_sync(0xffffffffu, rm1, 2));

    const float mn0 = fmaxf(m0r, rm0), mn1 = fmaxf(m1r, rm1);
    const float fs0 = __expf(m0r - mn0), fs1 = __expf(m1r - mn1);

    float ls0 = 0.f, ls1 = 0.f;
#pragma unroll
    for (int nf = 0; nf < 4; nf++) {
      c[nf][0] = __expf(c[nf][0] - mn0);
      c[nf][1] = __expf(c[nf][1] - mn0);
      c[nf][2] = __expf(c[nf][2] - mn1);
      c[nf][3] = __expf(c[nf][3] - mn1);
      ls0 += c[nf][0] + c[nf][1];
      ls1 += c[nf][2] + c[nf][3];
    }
    ls0 += __shfl_xor_sync(0xffffffffu, ls0, 1);
    ls0 += __shfl_xor_sync(0xffffffffu, ls0, 2);
    ls1 += __shfl_xor_sync(0xffffffffu, ls1, 1);
    ls1 += __shfl_xor_sync(0xffffffffu, ls1, 2);
    l0r = l0r*fs0 + ls0;
    l1r = l1r*fs1 + ls1;
    m0r = mn0; m1r = mn1;

#pragma unroll
    for (int nf = 0; nf < 8; nf++) {
      o[nf][0] *= fs0; o[nf][1] *= fs0;
      o[nf][2] *= fs1; o[nf][3] *= fs1;
    }
    uint32_t ap[2][4];
#pragma unroll
    for (int ks2 = 0; ks2 < 2; ks2++) {
      ap[ks2][0] = pack2f16(c[2*ks2][0],   c[2*ks2][1]);
      ap[ks2][1] = pack2f16(c[2*ks2][2],   c[2*ks2][3]);
      ap[ks2][2] = pack2f16(c[2*ks2+1][0], c[2*ks2+1][1]);
      ap[ks2][3] = pack2f16(c[2*ks2+1][2], c[2*ks2+1][3]);
    }

#pragma unroll
    for (int ks2 = 0; ks2 < 2; ks2++) {
      uint32_t bh[8][2], bl[8][2];
#pragma unroll
      for (int np = 0; np < 4; np++) {
        uint32_t off = (ks2*16*TSTRIDE + np*16)*2;
        uint32_t r0, r1, r2, r3;
        ldsm_x4_t(vb[s][0] + off, r0, r1, r2, r3);
        bh[2*np][0] = r0; bh[2*np][1] = r1; bh[2*np+1][0] = r2; bh[2*np+1][1] = r3;
        ldsm_x4_t(vb[s][1] + off, r0, r1, r2, r3);
        bl[2*np][0] = r0; bl[2*np][1] = r1; bl[2*np+1][0] = r2; bl[2*np+1][1] = r3;
      }
#pragma unroll
      for (int nf = 0; nf < 8; nf++) {
        mma_f16(o[nf], ap[ks2], bh[nf]);
        mma_f16(o[nf], ap[ks2], bl[nf]);
      }
    }
    __syncthreads();
  }

  // ---- cross-warp merge (wn=0 <- wn=1), gate, fp16-split store ----
  float* O1  = (float*)KV;          // [64][68]
  float* m1s = O1 + 64*68;          // [64]
  float* l1s = m1s + 64;            // [64]

  if (wn == 1) {
#pragma unroll
    for (int nf = 0; nf < 8; nf++) {
      const int d = nf*8 + q2;
      *(float2*)&O1[row0*68 + d] = make_float2(o[nf][0], o[nf][1]);
      *(float2*)&O1[row1*68 + d] = make_float2(o[nf][2], o[nf][3]);
    }
    if ((lane & 3) == 0) {
      m1s[row0] = m0r; l1s[row0] = l0r;
      m1s[row1] = m1r; l1s[row1] = l1r;
    }
  }
  __syncthreads();

  if (wn == 0) {
    const float mo0 = m1s[row0], lo0 = l1s[row0];
    const float mo1 = m1s[row1], lo1 = l1s[row1];
    const float mf0 = fmaxf(m0r, mo0), mf1 = fmaxf(m1r, mo1);
    const float a0 = __expf(m0r - mf0), b0s = __expf(mo0 - mf0);
    const float a1 = __expf(m1r - mf1), b1s = __expf(mo1 - mf1);
    const float inv0 = 1.0f / (l0r*a0 + lo0*b0s);
    const float inv1 = 1.0f / (l1r*a1 + lo1*b1s);

#pragma unroll
    for (int nf = 0; nf < 8; nf++) {
      const int d = nf*8 + q2;
      const int idx0 = (b*512 + it0 + row0)*512 + h*64 + d;
      const int idx1 = (b*512 + it0 + row1)*512 + h*64 + d;
      float2 p0 = *(float2*)&O1[row0*68 + d];
      float2 p1 = *(float2*)&O1[row1*68 + d];
      float2 gv0 = *(const float2*)(g_G + idx0);
      float2 gv1 = *(const float2*)(g_G + idx1);
      float e00 = (o[nf][0]*a0 + p0.x*b0s) * inv0 * gv0.x;
      float e01 = (o[nf][1]*a0 + p0.y*b0s) * inv0 * gv0.y;
      float e10 = (o[nf][2]*a1 + p1.x*b1s) * inv1 * gv1.x;
      float e11 = (o[nf][3]*a1 + p1.y*b1s) * inv1 * gv1.y;
      uint32_t ph, pl;
      split2packh(e00, e01, ph, pl);
      *(uint32_t*)(g_Eh + idx0) = ph;
      *(uint32_t*)(g_El + idx0) = pl;
      split2packh(e10, e11, ph, pl);
      *(uint32_t*)(g_Eh + idx1) = ph;
      *(uint32_t*)(g_El + idx1) = pl;
    }
  }
}

// ---------------------------------------------------------------------------
extern "C" void kernel_launch(void* const* d_in, const int* in_sizes, int n_in,
                              void* d_out, int out_size)
{
  const float* x   = (const float*)d_in[0];
  const void*  mask = d_in[1];
  const float* bias = (const float*)d_in[2];
  const float* Wq  = (const float*)d_in[3];
  const float* Wkv = (const float*)d_in[4];
  const float* Wo  = (const float*)d_in[5];
  const float* bo  = (const float*)d_in[6];
  const float* Wg  = (const float*)d_in[7];
  const float* bg  = (const float*)d_in[8];
  float* Y = (float*)d_out;

  const int SMEM_ATTN = 10*ATILE*2;               // 92160 B -> 2 CTAs/SM
  const int SMEM_MMA  = 9 * GTILE * 2;            // 165888 B (3-stage, 3 tiles)
  cudaFuncSetAttribute(attn_flash_kernel, cudaFuncAttributeMaxDynamicSharedMemorySize,
                       SMEM_ATTN);
  cudaFuncSetAttribute(proj_mma_kernel, cudaFuncAttributeMaxDynamicSharedMemorySize,
                       SMEM_MMA);
  cudaFuncSetAttribute(out_mma_kernel, cudaFuncAttributeMaxDynamicSharedMemorySize,
                       SMEM_MMA);

  detect_mask_kernel<<<1, 256>>>((const unsigned int*)mask);
  convert_mask_kernel<<<128, 256>>>(mask);
  split_all_kernel<<<10752, 256>>>(x, Wq, Wkv, Wg, Wo);
  proj_mma_kernel<<<dim3(16, 256), 512, SMEM_MMA>>>(bg);
  attn_flash_kernel<<<dim3(8, 8, 64), 256, SMEM_ATTN>>>(bias);
  out_mma_kernel<<<dim3(2, 256), 512, SMEM_MMA>>>(bo, Y);
}

// round 14
// speedup vs baseline: 1.3535x; 1.0253x over previous
#include <cuda_runtime.h>
#include <cuda_bf16.h>
#include <cuda_fp16.h>
#include <cfloat>
#include <cstdint>

#define BB_   64
#define NN_   512
#define DIM_  256
#define HH_   8
#define DHH_  64
#define INNER_ 512
#define SCALE_ 0.125f

// ---------------------------------------------------------------------------
// Scratch
// ---------------------------------------------------------------------------
__device__ float g_G[BB_*NN_*INNER_];
__device__ unsigned char g_mask[BB_*NN_];
__device__ int g_mask_mode;

__device__ __half        g_xfh[BB_*NN_*DIM_];      // x fp16 split
__device__ __half        g_xfl[BB_*NN_*DIM_];
__device__ __half        g_Wcf[2048*DIM_];         // concat W^T fp16 single
__device__ __nv_bfloat16 g_Qh[BB_*HH_*NN_*DHH_];   // Q/K bf16 split (QK 3-term)
__device__ __nv_bfloat16 g_Ql[BB_*HH_*NN_*DHH_];
__device__ __nv_bfloat16 g_Kh[BB_*HH_*NN_*DHH_];
__device__ __nv_bfloat16 g_Kl[BB_*HH_*NN_*DHH_];
__device__ __half        g_Vh[BB_*HH_*NN_*DHH_];   // V fp16 split
__device__ __half        g_Vl[BB_*HH_*NN_*DHH_];
__device__ __half        g_Eh[BB_*NN_*INNER_];     // gated attn out fp16 split
__device__ __half        g_El[BB_*NN_*INNER_];
__device__ __half        g_Wof[DIM_*INNER_];       // Wo^T fp16 single

// ---------------------------------------------------------------------------
// Helpers
// ---------------------------------------------------------------------------
__device__ __forceinline__ uint32_t smem_u32(const void* p) {
  uint32_t a;
  asm("{ .reg .u64 t; cvta.to.shared.u64 t, %1; cvt.u32.u64 %0, t; }"
      : "=r"(a) : "l"(p));
  return a;
}
__device__ __forceinline__ void cp16(uint32_t saddr, const void* g) {
  asm volatile("cp.async.cg.shared.global [%0], [%1], 16;"
               :: "r"(saddr), "l"(g));
}
#define CP_COMMIT() asm volatile("cp.async.commit_group;" ::: "memory")
#define CP_WAIT(n)  asm volatile("cp.async.wait_group %0;" :: "n"(n) : "memory")

__device__ __forceinline__ void ldsm_x4(uint32_t addr, uint32_t& r0,
                                        uint32_t& r1, uint32_t& r2, uint32_t& r3) {
  asm volatile("ldmatrix.sync.aligned.m8n8.x4.shared.b16 {%0,%1,%2,%3}, [%4];"
               : "=r"(r0), "=r"(r1), "=r"(r2), "=r"(r3) : "r"(addr));
}
__device__ __forceinline__ void ldsm_x4_t(uint32_t addr, uint32_t& r0,
                                          uint32_t& r1, uint32_t& r2, uint32_t& r3) {
  asm volatile("ldmatrix.sync.aligned.m8n8.x4.trans.shared.b16 {%0,%1,%2,%3}, [%4];"
               : "=r"(r0), "=r"(r1), "=r"(r2), "=r"(r3) : "r"(addr));
}
__device__ __forceinline__ void mma_bf16(float* c, const uint32_t* a,
                                         const uint32_t* b) {
  asm volatile(
    "mma.sync.aligned.m16n8k16.row.col.f32.bf16.bf16.f32 "
    "{%0,%1,%2,%3}, {%4,%5,%6,%7}, {%8,%9}, {%0,%1,%2,%3};"
    : "+f"(c[0]), "+f"(c[1]), "+f"(c[2]), "+f"(c[3])
    : "r"(a[0]), "r"(a[1]), "r"(a[2]), "r"(a[3]), "r"(b[0]), "r"(b[1]));
}
__device__ __forceinline__ void mma_f16(float* c, const uint32_t* a,
                                        const uint32_t* b) {
  asm volatile(
    "mma.sync.aligned.m16n8k16.row.col.f32.f16.f16.f32 "
    "{%0,%1,%2,%3}, {%4,%5,%6,%7}, {%8,%9}, {%0,%1,%2,%3};"
    : "+f"(c[0]), "+f"(c[1]), "+f"(c[2]), "+f"(c[3])
    : "r"(a[0]), "r"(a[1]), "r"(a[2]), "r"(a[3]), "r"(b[0]), "r"(b[1]));
}
__device__ __forceinline__ void split2(float v, __nv_bfloat16& h, __nv_bfloat16& l) {
  h = __float2bfloat16(v);
  l = __float2bfloat16(v - __bfloat162float(h));
}
__device__ __forceinline__ uint32_t pack2(__nv_bfloat16 a, __nv_bfloat16 b) {
  return (uint32_t)*(uint16_t*)&a | ((uint32_t)*(uint16_t*)&b << 16);
}
__device__ __forceinline__ void split2pack(float v0, float v1,
                                           uint32_t& ph, uint32_t& pl) {
  __nv_bfloat16 h0, l0, h1, l1;
  split2(v0, h0, l0); split2(v1, h1, l1);
  ph = pack2(h0, h1); pl = pack2(l0, l1);
}
__device__ __forceinline__ void split2packh(float v0, float v1,
                                            uint32_t& ph, uint32_t& pl) {
  __half h0 = __float2half_rn(v0), h1 = __float2half_rn(v1);
  __half l0 = __float2half_rn(v0 - __half2float(h0));
  __half l1 = __float2half_rn(v1 - __half2float(h1));
  ph = (uint32_t)*(uint16_t*)&h0 | ((uint32_t)*(uint16_t*)&h1 << 16);
  pl = (uint32_t)*(uint16_t*)&l0 | ((uint32_t)*(uint16_t*)&l1 << 16);
}
__device__ __forceinline__ uint32_t pack2f16(float a, float b) {
  __half2 hh = __floats2half2_rn(a, b);
  return *(uint32_t*)&hh;
}

// ---------------------------------------------------------------------------
// Mask detection + conversion (proven)
// ---------------------------------------------------------------------------
__global__ void detect_mask_kernel(const unsigned int* __restrict__ m)
{
  __shared__ int s_not01, s_notf;
  if (threadIdx.x == 0) { s_not01 = 0; s_notf = 0; }
  __syncthreads();
  int a = 0, b = 0;
  for (int i = threadIdx.x; i < 8192; i += 256) {
    unsigned v = m[i];
    if (v != 0u && v != 1u) a = 1;
    if (v != 0u && v != 0x3F800000u) b = 1;
  }
  if (a) atomicOr(&s_not01, 1);
  if (b) atomicOr(&s_notf, 1);
  __syncthreads();
  if (threadIdx.x == 0)
    g_mask_mode = (!s_not01) ? 0 : ((!s_notf) ? 1 : 2);
}

__global__ void convert_mask_kernel(const void* __restrict__ m)
{
  int idx = blockIdx.x * blockDim.x + threadIdx.x;
  if (idx >= BB_*NN_) return;
  int mode = g_mask_mode;
  unsigned char r;
  if (mode == 0)      r = ((const int*)m)[idx] != 0;
  else if (mode == 1) r = ((const unsigned int*)m)[idx] != 0u;
  else                r = ((const unsigned char*)m)[idx] != 0;
  g_mask[idx] = r;
}

// ---------------------------------------------------------------------------
// Fused split conversions
// ---------------------------------------------------------------------------
__global__ void split_all_kernel(const float* __restrict__ x,
                                 const float* __restrict__ Wq,
                                 const float* __restrict__ Wkv,
                                 const float* __restrict__ Wg,
                                 const float* __restrict__ Wo)
{
  int bid = blockIdx.x;
  if (bid < 8192) {
    int i = (bid * 256 + threadIdx.x) * 4;
    float4 v = *(const float4*)(x + i);
    uint32_t h0, l0, h1, l1;
    split2packh(v.x, v.y, h0, l0);
    split2packh(v.z, v.w, h1, l1);
    *(uint2*)(g_xfh + i) = make_uint2(h0, h1);
    *(uint2*)(g_xfl + i) = make_uint2(l0, l1);
  } else if (bid < 10240) {
    int idx = (bid - 8192) * 256 + threadIdx.x;
    int k = idx & 255, n = idx >> 8;
    int seg = n >> 9, col = n & 511;
    float v;
    if (seg == 0)      v = Wq[k*512 + col];
    else if (seg == 1) v = Wkv[k*1024 + col];
    else if (seg == 2) v = Wkv[k*1024 + 512 + col];
    else               v = Wg[k*512 + col];
    g_Wcf[n*256 + k] = __float2half_rn(v);
  } else {
    int idx = (bid - 10240) * 256 + threadIdx.x;
    int n = idx >> 9, k = idx & 511;
    g_Wof[n*512 + k] = __float2half_rn(Wo[k*256 + n]);
  }
}

// ---------------------------------------------------------------------------
// Tile loaders
// ---------------------------------------------------------------------------
#define TSTRIDE 72
#define ATILE (64*TSTRIDE)
#define BTILE (128*TSTRIDE)
#define GSTAGE (2*ATILE + BTILE)   // Ah + Al + B per stage = 18432 elems

// 64-row tile, 256 threads, arbitrary ldk
__device__ __forceinline__ void cpa_t64(
    uint16_t* dst, const uint16_t* __restrict__ src, int ldk, int tid)
{
#pragma unroll
  for (int it = 0; it < 2; it++) {
    int u = it*256 + tid;
    int row = u >> 3, c8 = (u & 7) * 8;
    cp16(smem_u32(dst + row*TSTRIDE + c8), src + row*ldk + c8);
  }
}
// 128-row tile, 256 threads
__device__ __forceinline__ void cpa_t128(
    uint16_t* dst, const uint16_t* __restrict__ src, int ldk, int tid)
{
#pragma unroll
  for (int it = 0; it < 4; it++) {
    int u = it*256 + tid;
    int row = u >> 3, c8 = (u & 7) * 8;
    cp16(smem_u32(dst + row*TSTRIDE + c8), src + row*ldk + c8);
  }
}
// 64-row tile, 256 threads, ldk=64 (attention)
__device__ __forceinline__ void cpa_tile64(
    uint16_t* dst, const uint16_t* __restrict__ src, int tid)
{
#pragma unroll
  for (int it = 0; it < 2; it++) {
    int u = it*256 + tid;
    int row = u >> 3, c8 = (u & 7) * 8;
    cp16(smem_u32(dst + row*TSTRIDE + c8), src + row*64 + c8);
  }
}

// ---------------------------------------------------------------------------
// Dense GEMM core (fp16 2-term): block 64x128, 8 warps (2m x 4n),
// warp tile 32x32. 2-stage cp.async, R8-proven double-barrier structure.
// 2 CTAs/SM (37 KB/stage, 74 KB total smem, 98 regs).
// ---------------------------------------------------------------------------
struct FragC { float c[2][4][4]; };

template <int KCHUNKS>
__device__ __forceinline__ void gemm_core2(
    uint16_t* smb,
    const __half* gAh, const __half* gAl, const __half* gB,
    int m0, int n0blk, int ldk, int tid, FragC& f)
{
  const int lane = tid & 31, wid = tid >> 5;
  const int wm = wid & 1, wn = wid >> 1;      // wm 0..1, wn 0..3
  const int lrow = (lane & 7) + ((lane >> 3) & 1) * 8;
  const int lcol = (lane >> 4) * 8;

  uint32_t abase[2][2], bbase[2];
#pragma unroll
  for (int s = 0; s < 2; s++) {
    uint16_t* st = smb + s*GSTAGE;
    abase[s][0] = smem_u32(st)           + ((wm*32 + lrow)*TSTRIDE + lcol)*2;
    abase[s][1] = smem_u32(st + ATILE)   + ((wm*32 + lrow)*TSTRIDE + lcol)*2;
    bbase[s]    = smem_u32(st + 2*ATILE) + ((wn*32 + lrow)*TSTRIDE + lcol)*2;
  }

#pragma unroll
  for (int mt = 0; mt < 2; mt++)
#pragma unroll
    for (int nt = 0; nt < 4; nt++)
#pragma unroll
      for (int q = 0; q < 4; q++) f.c[mt][nt][q] = 0.f;

  // prefetch chunk 0 -> stage 0
  {
    uint16_t* st = smb;
    cpa_t64 (st,           (const uint16_t*)gAh + m0*ldk,    ldk, tid);
    cpa_t64 (st + ATILE,   (const uint16_t*)gAl + m0*ldk,    ldk, tid);
    cpa_t128(st + 2*ATILE, (const uint16_t*)gB  + n0blk*ldk, ldk, tid);
    CP_COMMIT();
  }

  for (int kc = 0; kc < KCHUNKS; kc++) {
    if (kc + 1 < KCHUNKS) {
      uint16_t* st = smb + ((kc+1)&1)*GSTAGE;
      int co = (kc+1)*64;
      cpa_t64 (st,           (const uint16_t*)gAh + m0*ldk + co,    ldk, tid);
      cpa_t64 (st + ATILE,   (const uint16_t*)gAl + m0*ldk + co,    ldk, tid);
      cpa_t128(st + 2*ATILE, (const uint16_t*)gB  + n0blk*ldk + co, ldk, tid);
      CP_COMMIT();
      CP_WAIT(1);
    } else {
      CP_WAIT(0);
    }
    __syncthreads();

    const int s = kc & 1;
#pragma unroll
    for (int ks = 0; ks < 4; ks++) {
      uint32_t ah[2][4], al[2][4];
#pragma unroll
      for (int mt = 0; mt < 2; mt++) {
        uint32_t off = (mt*16*TSTRIDE + ks*16)*2;
        ldsm_x4(abase[s][0] + off, ah[mt][0], ah[mt][1], ah[mt][2], ah[mt][3]);
        ldsm_x4(abase[s][1] + off, al[mt][0], al[mt][1], al[mt][2], al[mt][3]);
      }
      uint32_t bb[4][2];
#pragma unroll
      for (int np = 0; np < 2; np++) {
        uint32_t off = (np*16*TSTRIDE + ks*16)*2;
        uint32_t r0, r1, r2, r3;
        ldsm_x4(bbase[s] + off, r0, r1, r2, r3);
        bb[2*np][0] = r0; bb[2*np+1][0] = r1; bb[2*np][1] = r2; bb[2*np+1][1] = r3;
      }
#pragma unroll
      for (int mt = 0; mt < 2; mt++)
#pragma unroll
        for (int nt = 0; nt < 4; nt++) {
          mma_f16(f.c[mt][nt], ah[mt], bb[nt]);
          mma_f16(f.c[mt][nt], al[mt], bb[nt]);
        }
    }
    __syncthreads();
  }
}

// ---------------------------------------------------------------------------
// Projection GEMM (256 threads, block 64x128)
// ---------------------------------------------------------------------------
__global__ __launch_bounds__(256, 2) void proj_mma_kernel(const float* __restrict__ bg)
{
  extern __shared__ uint16_t smb[];
  const int tid = threadIdx.x;
  const int c0 = blockIdx.x * 128;
  const int m0 = blockIdx.y * 64;

  FragC f;
  gemm_core2<4>(smb, g_xfh, g_xfl, g_Wcf, m0, c0, 256, tid, f);

  const int lane = tid & 31, wid = tid >> 5;
  const int wm = wid & 1, wn = wid >> 1;
  const int q2 = (lane & 3) * 2, r4 = lane >> 2;
  const int seg = c0 >> 9;
  const int lbase = c0 - seg*512 + wn*32;

#pragma unroll
  for (int mt = 0; mt < 2; mt++) {
#pragma unroll
    for (int h2 = 0; h2 < 2; h2++) {
      const int m = m0 + wm*32 + mt*16 + r4 + h2*8;
      const int bidx = m >> 9, n = m & 511;
      if (seg == 3) {
        float* dst = g_G + m*512 + lbase;
#pragma unroll
        for (int nt = 0; nt < 4; nt++) {
          int cc = nt*8 + q2;
          float2 v;
          v.x = f.c[mt][nt][h2*2+0] + bg[lbase + cc];
          v.y = f.c[mt][nt][h2*2+1] + bg[lbase + cc + 1];
          *(float2*)(dst + cc) = v;
        }
      } else if (seg == 2) {
        const int hh = lbase >> 6;
        const int dbase = lbase & 63;
        const int off = (((bidx*8 + hh)*512 + n)*64) + dbase;
#pragma unroll
        for (int nt = 0; nt < 4; nt++) {
          int dd = nt*8 + q2;
          uint32_t ph, pl;
          split2packh(f.c[mt][nt][h2*2+0], f.c[mt][nt][h2*2+1], ph, pl);
          *(uint32_t*)(g_Vh + off + dd) = ph;
          *(uint32_t*)(g_Vl + off + dd) = pl;
        }
      } else {
        const int hh = lbase >> 6;
        const int dbase = lbase & 63;
        __nv_bfloat16* bh_ = (seg == 0) ? g_Qh : g_Kh;
        __nv_bfloat16* bl_ = (seg == 0) ? g_Ql : g_Kl;
        const int off = (((bidx*8 + hh)*512 + n)*64) + dbase;
#pragma unroll
        for (int nt = 0; nt < 4; nt++) {
          int dd = nt*8 + q2;
          uint32_t ph, pl;
          split2pack(f.c[mt][nt][h2*2+0], f.c[mt][nt][h2*2+1], ph, pl);
          *(uint32_t*)(bh_ + off + dd) = ph;
          *(uint32_t*)(bl_ + off + dd) = pl;
        }
      }
    }
  }
}

// ---------------------------------------------------------------------------
// Output GEMM (256 threads, block 64x128)
// ---------------------------------------------------------------------------
__global__ __launch_bounds__(256, 2) void out_mma_kernel(
    const float* __restrict__ bo, float* __restrict__ Y)
{
  extern __shared__ uint16_t smb[];
  const int tid = threadIdx.x;
  const int n0 = blockIdx.x * 128;
  const int m0 = blockIdx.y * 64;

  FragC f;
  gemm_core2<8>(smb, g_Eh, g_El, g_Wof, m0, n0, 512, tid, f);

  const int lane = tid & 31, wid = tid >> 5;
  const int wm = wid & 1, wn = wid >> 1;
  const int q2 = (lane & 3) * 2, r4 = lane >> 2;

#pragma unroll
  for (int mt = 0; mt < 2; mt++) {
#pragma unroll
    for (int h2 = 0; h2 < 2; h2++) {
      const int m = m0 + wm*32 + mt*16 + r4 + h2*8;
      float* dst = Y + m*256 + n0 + wn*32;
      const float* bop = bo + n0 + wn*32;
#pragma unroll
      for (int nt = 0; nt < 4; nt++) {
        int cc = nt*8 + q2;
        float2 v;
        v.x = f.c[mt][nt][h2*2+0] + bop[cc];
        v.y = f.c[mt][nt][h2*2+1] + bop[cc + 1];
        *(float2*)(dst + cc) = v;
      }
    }
  }
}

// ---------------------------------------------------------------------------
// Flash attention (R13 proven, unchanged)
// ---------------------------------------------------------------------------
__global__ __launch_bounds__(256, 2) void attn_flash_kernel(
    const float* __restrict__ bias)
{
  extern __shared__ uint16_t smbu[];
  uint16_t* Qh = smbu;
  uint16_t* Ql = smbu + ATILE;
  uint16_t* KV = smbu + 2*ATILE;

  const int tid = threadIdx.x;
  const int lane = tid & 31, wid = tid >> 5;
  const int wm = wid & 3, wn = wid >> 2;
  const int lrow = (lane & 7) + ((lane >> 3) & 1) * 8;
  const int lcol = (lane >> 4) * 8;
  const int r4 = lane >> 2, q2 = (lane & 3) * 2;
  const int it0 = blockIdx.x * 64;
  const int h = blockIdx.y, b = blockIdx.z;

  const int bh_off = (b*8 + h) * 512 * 64;
  const uint16_t* Khs = (const uint16_t*)(g_Kh + bh_off);
  const uint16_t* Kls = (const uint16_t*)(g_Kl + bh_off);
  const uint16_t* Vhs = (const uint16_t*)(g_Vh + bh_off);
  const uint16_t* Vls = (const uint16_t*)(g_Vl + bh_off);

  cpa_tile64(Qh, (const uint16_t*)(g_Qh + bh_off + it0*64), tid);
  cpa_tile64(Ql, (const uint16_t*)(g_Ql + bh_off + it0*64), tid);
  cpa_tile64(KV,           Khs, tid);
  cpa_tile64(KV + ATILE,   Kls, tid);
  cpa_tile64(KV + 2*ATILE, Vhs, tid);
  cpa_tile64(KV + 3*ATILE, Vls, tid);
  CP_COMMIT();

  const uint32_t qh_base = smem_u32(Qh) + ((wm*16 + lrow)*TSTRIDE + lcol)*2;
  const uint32_t ql_base = smem_u32(Ql) + ((wm*16 + lrow)*TSTRIDE + lcol)*2;
  uint32_t kb[2][2], vb[2][2];
#pragma unroll
  for (int s = 0; s < 2; s++) {
    uint16_t* st = KV + s*4*ATILE;
    kb[s][0] = smem_u32(st)           + ((wn*32 + lrow)*TSTRIDE + lcol)*2;
    kb[s][1] = smem_u32(st + ATILE)   + ((wn*32 + lrow)*TSTRIDE + lcol)*2;
    vb[s][0] = smem_u32(st + 2*ATILE) + ((wn*32 + lrow)*TSTRIDE + lcol)*2;
    vb[s][1] = smem_u32(st + 3*ATILE) + ((wn*32 + lrow)*TSTRIDE + lcol)*2;
  }

  const int row0 = wm*16 + r4;
  const int row1 = row0 + 8;
  const unsigned char* mrow = g_mask + b*512;
  const bool mi0 = mrow[it0 + row0] != 0;
  const bool mi1 = mrow[it0 + row1] != 0;
  const float* brow0 = bias + (h*512 + it0 + row0)*512;
  const float* brow1 = bias + (h*512 + it0 + row1)*512;

  float m0r = -FLT_MAX, m1r = -FLT_MAX, l0r = 0.f, l1r = 0.f;
  float o[8][4];
#pragma unroll
  for (int nf = 0; nf < 8; nf++)
#pragma unroll
    for (int q = 0; q < 4; q++) o[nf][q] = 0.f;

  for (int jt = 0; jt < 8; jt++) {
    if (jt < 7) {
      uint16_t* st = KV + ((jt+1)&1)*4*ATILE;
      const int co = (jt+1)*64*64;
      cpa_tile64(st,           Khs + co, tid);
      cpa_tile64(st + ATILE,   Kls + co, tid);
      cpa_tile64(st + 2*ATILE, Vhs + co, tid);
      cpa_tile64(st + 3*ATILE, Vls + co, tid);
      CP_COMMIT();
      CP_WAIT(1);
    } else {
      CP_WAIT(0);
    }
    __syncthreads();

    const int s = jt & 1;
    float c[4][4];
#pragma unroll
    for (int nf = 0; nf < 4; nf++)
#pragma unroll
      for (int q = 0; q < 4; q++) c[nf][q] = 0.f;

#pragma unroll
    for (int ks = 0; ks < 4; ks++) {
      uint32_t ah[4], al[4];
      ldsm_x4(qh_base + ks*32, ah[0], ah[1], ah[2], ah[3]);
      ldsm_x4(ql_base + ks*32, al[0], al[1], al[2], al[3]);
#pragma unroll
      for (int np = 0; np < 2; np++) {
        uint32_t off = (np*16*TSTRIDE + ks*16)*2;
        uint32_t r0, r1, r2, r3;
        ldsm_x4(kb[s][0] + off, r0, r1, r2, r3);
        uint32_t bh0[2] = {r0, r2}, bh1[2] = {r1, r3};
        ldsm_x4(kb[s][1] + off, r0, r1, r2, r3);
        uint32_t bl0[2] = {r0, r2}, bl1[2] = {r1, r3};
        mma_bf16(c[2*np],   ah, bh0); mma_bf16(c[2*np],   ah, bl0);
        mma_bf16(c[2*np],   al, bh0);
        mma_bf16(c[2*np+1], ah, bh1); mma_bf16(c[2*np+1], ah, bl1);
        mma_bf16(c[2*np+1], al, bh1);
      }
    }

    const int colbase = jt*64 + wn*32;
    float rm0 = -FLT_MAX, rm1 = -FLT_MAX;
#pragma unroll
    for (int nf = 0; nf < 4; nf++) {
      const int col = colbase + nf*8 + q2;
      float2 b0 = *(const float2*)&brow0[col];
      float2 b1 = *(const float2*)&brow1[col];
      bool mjA = mrow[col] != 0, mjB = mrow[col+1] != 0;
      c[nf][0] = (mi0 && mjA) ? c[nf][0]*SCALE_ + b0.x : -FLT_MAX;
      c[nf][1] = (mi0 && mjB) ? c[nf][1]*SCALE_ + b0.y : -FLT_MAX;
      c[nf][2] = (mi1 && mjA) ? c[nf][2]*SCALE_ + b1.x : -FLT_MAX;
      c[nf][3] = (mi1 && mjB) ? c[nf][3]*SCALE_ + b1.y : -FLT_MAX;
      rm0 = fmaxf(rm0, fmaxf(c[nf][0], c[nf][1]));
      rm1 = fmaxf(rm1, fmaxf(c[nf][2], c[nf][3]));
    }
    rm0 = fmaxf(rm0, __shfl_xor_sync(0xffffffffu, rm0, 1));
    rm0 = fmaxf(rm0, __shfl_xor_sync(0xffffffffu, rm0, 2));
    rm1 = fmaxf(rm1, __shfl_xor_sync(0xffffffffu, rm1, 1));
    rm1 = fmaxf(rm1, __shfl_xor_sync(0xffffffffu, rm1, 2));

    const float mn0 = fmaxf(m0r, rm0), mn1 = fmaxf(m1r, rm1);
    const float fs0 = __expf(m0r - mn0), fs1 = __expf(m1r - mn1);

    float ls0 = 0.f, ls1 = 0.f;
#pragma unroll
    for (int nf = 0; nf < 4; nf++) {
      c[nf][0] = __expf(c[nf][0] - mn0);
      c[nf][1] = __expf(c[nf][1] - mn0);
      c[nf][2] = __expf(c[nf][2] - mn1);
      c[nf][3] = __expf(c[nf][3] - mn1);
      ls0 += c[nf][0] + c[nf][1];
      ls1 += c[nf][2] + c[nf][3];
    }
    ls0 += __shfl_xor_sync(0xffffffffu, ls0, 1);
    ls0 += __shfl_xor_sync(0xffffffffu, ls0, 2);
    ls1 += __shfl_xor_sync(0xffffffffu, ls1, 1);
    ls1 += __shfl_xor_sync(0xffffffffu, ls1, 2);
    l0r = l0r*fs0 + ls0;
    l1r = l1r*fs1 + ls1;
    m0r = mn0; m1r = mn1;

#pragma unroll
    for (int nf = 0; nf < 8; nf++) {
      o[nf][0] *= fs0; o[nf][1] *= fs0;
      o[nf][2] *= fs1; o[nf][3] *= fs1;
    }
    uint32_t ap[2][4];
#pragma unroll
    for (int ks2 = 0; ks2 < 2; ks2++) {
      ap[ks2][0] = pack2f16(c[2*ks2][0],   c[2*ks2][1]);
      ap[ks2][1] = pack2f16(c[2*ks2][2],   c[2*ks2][3]);
      ap[ks2][2] = pack2f16(c[2*ks2+1][0], c[2*ks2+1][1]);
      ap[ks2][3] = pack2f16(c[2*ks2+1][2], c[2*ks2+1][3]);
    }

#pragma unroll
    for (int ks2 = 0; ks2 < 2; ks2++) {
      uint32_t bh[8][2], bl[8][2];
#pragma unroll
      for (int np = 0; np < 4; np++) {
        uint32_t off = (ks2*16*TSTRIDE + np*16)*2;
        uint32_t r0, r1, r2, r3;
        ldsm_x4_t(vb[s][0] + off, r0, r1, r2, r3);
        bh[2*np][0] = r0; bh[2*np][1] = r1; bh[2*np+1][0] = r2; bh[2*np+1][1] = r3;
        ldsm_x4_t(vb[s][1] + off, r0, r1, r2, r3);
        bl[2*np][0] = r0; bl[2*np][1] = r1; bl[2*np+1][0] = r2; bl[2*np+1][1] = r3;
      }
#pragma unroll
      for (int nf = 0; nf < 8; nf++) {
        mma_f16(o[nf], ap[ks2], bh[nf]);
        mma_f16(o[nf], ap[ks2], bl[nf]);
      }
    }
    __syncthreads();
  }

  // ---- cross-warp merge (wn=0 <- wn=1), gate, fp16-split store ----
  float* O1  = (float*)KV;          // [64][68]
  float* m1s = O1 + 64*68;          // [64]
  float* l1s = m1s + 64;            // [64]

  if (wn == 1) {
#pragma unroll
    for (int nf = 0; nf < 8; nf++) {
      const int d = nf*8 + q2;
      *(float2*)&O1[row0*68 + d] = make_float2(o[nf][0], o[nf][1]);
      *(float2*)&O1[row1*68 + d] = make_float2(o[nf][2], o[nf][3]);
    }
    if ((lane & 3) == 0) {
      m1s[row0] = m0r; l1s[row0] = l0r;
      m1s[row1] = m1r; l1s[row1] = l1r;
    }
  }
  __syncthreads();

  if (wn == 0) {
    const float mo0 = m1s[row0], lo0 = l1s[row0];
    const float mo1 = m1s[row1], lo1 = l1s[row1];
    const float mf0 = fmaxf(m0r, mo0), mf1 = fmaxf(m1r, mo1);
    const float a0 = __expf(m0r - mf0), b0s = __expf(mo0 - mf0);
    const float a1 = __expf(m1r - mf1), b1s = __expf(mo1 - mf1);
    const float inv0 = 1.0f / (l0r*a0 + lo0*b0s);
    const float inv1 = 1.0f / (l1r*a1 + lo1*b1s);

#pragma unroll
    for (int nf = 0; nf < 8; nf++) {
      const int d = nf*8 + q2;
      const int idx0 = (b*512 + it0 + row0)*512 + h*64 + d;
      const int idx1 = (b*512 + it0 + row1)*512 + h*64 + d;
      float2 p0 = *(float2*)&O1[row0*68 + d];
      float2 p1 = *(float2*)&O1[row1*68 + d];
      float2 gv0 = *(const float2*)(g_G + idx0);
      float2 gv1 = *(const float2*)(g_G + idx1);
      float e00 = (o[nf][0]*a0 + p0.x*b0s) * inv0 * gv0.x;
      float e01 = (o[nf][1]*a0 + p0.y*b0s) * inv0 * gv0.y;
      float e10 = (o[nf][2]*a1 + p1.x*b1s) * inv1 * gv1.x;
      float e11 = (o[nf][3]*a1 + p1.y*b1s) * inv1 * gv1.y;
      uint32_t ph, pl;
      split2packh(e00, e01, ph, pl);
      *(uint32_t*)(g_Eh + idx0) = ph;
      *(uint32_t*)(g_El + idx0) = pl;
      split2packh(e10, e11, ph, pl);
      *(uint32_t*)(g_Eh + idx1) = ph;
      *(uint32_t*)(g_El + idx1) = pl;
    }
  }
}

// ---------------------------------------------------------------------------
extern "C" void kernel_launch(void* const* d_in, const int* in_sizes, int n_in,
                              void* d_out, int out_size)
{
  const float* x   = (const float*)d_in[0];
  const void*  mask = d_in[1];
  const float* bias = (const float*)d_in[2];
  const float* Wq  = (const float*)d_in[3];
  const float* Wkv = (const float*)d_in[4];
  const float* Wo  = (const float*)d_in[5];
  const float* bo  = (const float*)d_in[6];
  const float* Wg  = (const float*)d_in[7];
  const float* bg  = (const float*)d_in[8];
  float* Y = (float*)d_out;

  const int SMEM_ATTN = 10*ATILE*2;               // 92160 B -> 2 CTAs/SM
  const int SMEM_MMA  = 2*GSTAGE*2;               // 73728 B -> 2 CTAs/SM
  cudaFuncSetAttribute(attn_flash_kernel, cudaFuncAttributeMaxDynamicSharedMemorySize,
                       SMEM_ATTN);
  cudaFuncSetAttribute(proj_mma_kernel, cudaFuncAttributeMaxDynamicSharedMemorySize,
                       SMEM_MMA);
  cudaFuncSetAttribute(out_mma_kernel, cudaFuncAttributeMaxDynamicSharedMemorySize,
                       SMEM_MMA);

  detect_mask_kernel<<<1, 256>>>((const unsigned int*)mask);
  convert_mask_kernel<<<128, 256>>>(mask);
  split_all_kernel<<<10752, 256>>>(x, Wq, Wkv, Wg, Wo);
  proj_mma_kernel<<<dim3(16, 512), 256, SMEM_MMA>>>(bg);
  attn_flash_kernel<<<dim3(8, 8, 64), 256, SMEM_ATTN>>>(bias);
  out_mma_kernel<<<dim3(2, 512), 256, SMEM_MMA>>>(bo, Y);
}

// round 15
// speedup vs baseline: 1.3604x; 1.0051x over previous
#include <cuda_runtime.h>
#include <cuda_bf16.h>
#include <cuda_fp16.h>
#include <cfloat>
#include <cstdint>

#define BB_   64
#define NN_   512
#define DIM_  256
#define HH_   8
#define DHH_  64
#define INNER_ 512
#define SCALE_ 0.125f

// ---------------------------------------------------------------------------
// Scratch
// ---------------------------------------------------------------------------
__device__ float g_G[BB_*NN_*INNER_];
__device__ unsigned char g_mask[BB_*NN_];
__device__ int g_mask_mode;

__device__ __half        g_xfh[BB_*NN_*DIM_];      // x fp16 split
__device__ __half        g_xfl[BB_*NN_*DIM_];
__device__ __half        g_Wcf[2048*DIM_];         // concat W^T fp16 single
__device__ __nv_bfloat16 g_Qh[BB_*HH_*NN_*DHH_];   // Q/K bf16 split (QK 3-term)
__device__ __nv_bfloat16 g_Ql[BB_*HH_*NN_*DHH_];
__device__ __nv_bfloat16 g_Kh[BB_*HH_*NN_*DHH_];
__device__ __nv_bfloat16 g_Kl[BB_*HH_*NN_*DHH_];
__device__ __half        g_Vh[BB_*HH_*NN_*DHH_];   // V fp16 split
__device__ __half        g_Vl[BB_*HH_*NN_*DHH_];
__device__ __half        g_Eh[BB_*NN_*INNER_];     // gated attn out fp16 split
__device__ __half        g_El[BB_*NN_*INNER_];
__device__ __half        g_Wof[DIM_*INNER_];       // Wo^T fp16 single

// ---------------------------------------------------------------------------
// Helpers
// ---------------------------------------------------------------------------
__device__ __forceinline__ uint32_t smem_u32(const void* p) {
  uint32_t a;
  asm("{ .reg .u64 t; cvta.to.shared.u64 t, %1; cvt.u32.u64 %0, t; }"
      : "=r"(a) : "l"(p));
  return a;
}
__device__ __forceinline__ void cp16(uint32_t saddr, const void* g) {
  asm volatile("cp.async.cg.shared.global [%0], [%1], 16;"
               :: "r"(saddr), "l"(g));
}
#define CP_COMMIT() asm volatile("cp.async.commit_group;" ::: "memory")
#define CP_WAIT(n)  asm volatile("cp.async.wait_group %0;" :: "n"(n) : "memory")

__device__ __forceinline__ void ldsm_x4(uint32_t addr, uint32_t& r0,
                                        uint32_t& r1, uint32_t& r2, uint32_t& r3) {
  asm volatile("ldmatrix.sync.aligned.m8n8.x4.shared.b16 {%0,%1,%2,%3}, [%4];"
               : "=r"(r0), "=r"(r1), "=r"(r2), "=r"(r3) : "r"(addr));
}
__device__ __forceinline__ void ldsm_x4_t(uint32_t addr, uint32_t& r0,
                                          uint32_t& r1, uint32_t& r2, uint32_t& r3) {
  asm volatile("ldmatrix.sync.aligned.m8n8.x4.trans.shared.b16 {%0,%1,%2,%3}, [%4];"
               : "=r"(r0), "=r"(r1), "=r"(r2), "=r"(r3) : "r"(addr));
}
__device__ __forceinline__ void mma_bf16(float* c, const uint32_t* a,
                                         const uint32_t* b) {
  asm volatile(
    "mma.sync.aligned.m16n8k16.row.col.f32.bf16.bf16.f32 "
    "{%0,%1,%2,%3}, {%4,%5,%6,%7}, {%8,%9}, {%0,%1,%2,%3};"
    : "+f"(c[0]), "+f"(c[1]), "+f"(c[2]), "+f"(c[3])
    : "r"(a[0]), "r"(a[1]), "r"(a[2]), "r"(a[3]), "r"(b[0]), "r"(b[1]));
}
__device__ __forceinline__ void mma_f16(float* c, const uint32_t* a,
                                        const uint32_t* b) {
  asm volatile(
    "mma.sync.aligned.m16n8k16.row.col.f32.f16.f16.f32 "
    "{%0,%1,%2,%3}, {%4,%5,%6,%7}, {%8,%9}, {%0,%1,%2,%3};"
    : "+f"(c[0]), "+f"(c[1]), "+f"(c[2]), "+f"(c[3])
    : "r"(a[0]), "r"(a[1]), "r"(a[2]), "r"(a[3]), "r"(b[0]), "r"(b[1]));
}
__device__ __forceinline__ void split2(float v, __nv_bfloat16& h, __nv_bfloat16& l) {
  h = __float2bfloat16(v);
  l = __float2bfloat16(v - __bfloat162float(h));
}
__device__ __forceinline__ uint32_t pack2(__nv_bfloat16 a, __nv_bfloat16 b) {
  return (uint32_t)*(uint16_t*)&a | ((uint32_t)*(uint16_t*)&b << 16);
}
__device__ __forceinline__ void split2pack(float v0, float v1,
                                           uint32_t& ph, uint32_t& pl) {
  __nv_bfloat16 h0, l0, h1, l1;
  split2(v0, h0, l0); split2(v1, h1, l1);
  ph = pack2(h0, h1); pl = pack2(l0, l1);
}
__device__ __forceinline__ void split2packh(float v0, float v1,
                                            uint32_t& ph, uint32_t& pl) {
  __half h0 = __float2half_rn(v0), h1 = __float2half_rn(v1);
  __half l0 = __float2half_rn(v0 - __half2float(h0));
  __half l1 = __float2half_rn(v1 - __half2float(h1));
  ph = (uint32_t)*(uint16_t*)&h0 | ((uint32_t)*(uint16_t*)&h1 << 16);
  pl = (uint32_t)*(uint16_t*)&l0 | ((uint32_t)*(uint16_t*)&l1 << 16);
}
__device__ __forceinline__ uint32_t pack2f16(float a, float b) {
  __half2 hh = __floats2half2_rn(a, b);
  return *(uint32_t*)&hh;
}

// ---------------------------------------------------------------------------
// Mask detection + conversion (proven)
// ---------------------------------------------------------------------------
__global__ void detect_mask_kernel(const unsigned int* __restrict__ m)
{
  __shared__ int s_not01, s_notf;
  if (threadIdx.x == 0) { s_not01 = 0; s_notf = 0; }
  __syncthreads();
  int a = 0, b = 0;
  for (int i = threadIdx.x; i < 8192; i += 256) {
    unsigned v = m[i];
    if (v != 0u && v != 1u) a = 1;
    if (v != 0u && v != 0x3F800000u) b = 1;
  }
  if (a) atomicOr(&s_not01, 1);
  if (b) atomicOr(&s_notf, 1);
  __syncthreads();
  if (threadIdx.x == 0)
    g_mask_mode = (!s_not01) ? 0 : ((!s_notf) ? 1 : 2);
}

__global__ void convert_mask_kernel(const void* __restrict__ m)
{
  int idx = blockIdx.x * blockDim.x + threadIdx.x;
  if (idx >= BB_*NN_) return;
  int mode = g_mask_mode;
  unsigned char r;
  if (mode == 0)      r = ((const int*)m)[idx] != 0;
  else if (mode == 1) r = ((const unsigned int*)m)[idx] != 0u;
  else                r = ((const unsigned char*)m)[idx] != 0;
  g_mask[idx] = r;
}

// ---------------------------------------------------------------------------
// Fused split conversions
// ---------------------------------------------------------------------------
__global__ void split_all_kernel(const float* __restrict__ x,
                                 const float* __restrict__ Wq,
                                 const float* __restrict__ Wkv,
                                 const float* __restrict__ Wg,
                                 const float* __restrict__ Wo)
{
  int bid = blockIdx.x;
  if (bid < 8192) {
    int i = (bid * 256 + threadIdx.x) * 4;
    float4 v = *(const float4*)(x + i);
    uint32_t h0, l0, h1, l1;
    split2packh(v.x, v.y, h0, l0);
    split2packh(v.z, v.w, h1, l1);
    *(uint2*)(g_xfh + i) = make_uint2(h0, h1);
    *(uint2*)(g_xfl + i) = make_uint2(l0, l1);
  } else if (bid < 10240) {
    int idx = (bid - 8192) * 256 + threadIdx.x;
    int k = idx & 255, n = idx >> 8;
    int seg = n >> 9, col = n & 511;
    float v;
    if (seg == 0)      v = Wq[k*512 + col];
    else if (seg == 1) v = Wkv[k*1024 + col];
    else if (seg == 2) v = Wkv[k*1024 + 512 + col];
    else               v = Wg[k*512 + col];
    g_Wcf[n*256 + k] = __float2half_rn(v);
  } else {
    int idx = (bid - 10240) * 256 + threadIdx.x;
    int n = idx >> 9, k = idx & 511;
    g_Wof[n*512 + k] = __float2half_rn(Wo[k*256 + n]);
  }
}

// ---------------------------------------------------------------------------
// Tile loaders
// ---------------------------------------------------------------------------
#define TSTRIDE 72
#define ATILE (64*TSTRIDE)
#define BTILE (128*TSTRIDE)
#define GSTAGE (3*BTILE)   // Ah + Al + B, all 128-row tiles = 27648 elems

// 128-row tile, 256 threads
__device__ __forceinline__ void cpa_t128(
    uint16_t* dst, const uint16_t* __restrict__ src, int ldk, int tid)
{
#pragma unroll
  for (int it = 0; it < 4; it++) {
    int u = it*256 + tid;
    int row = u >> 3, c8 = (u & 7) * 8;
    cp16(smem_u32(dst + row*TSTRIDE + c8), src + row*ldk + c8);
  }
}
// 64-row tile, 256 threads, ldk=64 (attention)
__device__ __forceinline__ void cpa_tile64(
    uint16_t* dst, const uint16_t* __restrict__ src, int tid)
{
#pragma unroll
  for (int it = 0; it < 2; it++) {
    int u = it*256 + tid;
    int row = u >> 3, c8 = (u & 7) * 8;
    cp16(smem_u32(dst + row*TSTRIDE + c8), src + row*64 + c8);
  }
}

// ---------------------------------------------------------------------------
// Dense GEMM core (fp16 2-term): block 128x128, 8 warps (4m x 2n),
// warp tile 32x64 (mma:ldsm = 4.0). 2-stage cp.async, R8-proven
// double-barrier structure. 110.6 KB smem -> 2 CTAs/SM.
// ---------------------------------------------------------------------------
struct FragC { float c[2][8][4]; };

template <int KCHUNKS>
__device__ __forceinline__ void gemm_core2(
    uint16_t* smb,
    const __half* gAh, const __half* gAl, const __half* gB,
    int m0, int n0blk, int ldk, int tid, FragC& f)
{
  const int lane = tid & 31, wid = tid >> 5;
  const int wm = wid & 3, wn = wid >> 2;      // wm 0..3, wn 0..1
  const int lrow = (lane & 7) + ((lane >> 3) & 1) * 8;
  const int lcol = (lane >> 4) * 8;

  uint32_t abase[2][2], bbase[2];
#pragma unroll
  for (int s = 0; s < 2; s++) {
    uint16_t* st = smb + s*GSTAGE;
    abase[s][0] = smem_u32(st)           + ((wm*32 + lrow)*TSTRIDE + lcol)*2;
    abase[s][1] = smem_u32(st + BTILE)   + ((wm*32 + lrow)*TSTRIDE + lcol)*2;
    bbase[s]    = smem_u32(st + 2*BTILE) + ((wn*64 + lrow)*TSTRIDE + lcol)*2;
  }

#pragma unroll
  for (int mt = 0; mt < 2; mt++)
#pragma unroll
    for (int nt = 0; nt < 8; nt++)
#pragma unroll
      for (int q = 0; q < 4; q++) f.c[mt][nt][q] = 0.f;

  // prefetch chunk 0 -> stage 0
  {
    uint16_t* st = smb;
    cpa_t128(st,           (const uint16_t*)gAh + m0*ldk,    ldk, tid);
    cpa_t128(st + BTILE,   (const uint16_t*)gAl + m0*ldk,    ldk, tid);
    cpa_t128(st + 2*BTILE, (const uint16_t*)gB  + n0blk*ldk, ldk, tid);
    CP_COMMIT();
  }

  for (int kc = 0; kc < KCHUNKS; kc++) {
    if (kc + 1 < KCHUNKS) {
      uint16_t* st = smb + ((kc+1)&1)*GSTAGE;
      int co = (kc+1)*64;
      cpa_t128(st,           (const uint16_t*)gAh + m0*ldk + co,    ldk, tid);
      cpa_t128(st + BTILE,   (const uint16_t*)gAl + m0*ldk + co,    ldk, tid);
      cpa_t128(st + 2*BTILE, (const uint16_t*)gB  + n0blk*ldk + co, ldk, tid);
      CP_COMMIT();
      CP_WAIT(1);
    } else {
      CP_WAIT(0);
    }
    __syncthreads();

    const int s = kc & 1;
#pragma unroll
    for (int ks = 0; ks < 4; ks++) {
      uint32_t ah[2][4], al[2][4];
#pragma unroll
      for (int mt = 0; mt < 2; mt++) {
        uint32_t off = (mt*16*TSTRIDE + ks*16)*2;
        ldsm_x4(abase[s][0] + off, ah[mt][0], ah[mt][1], ah[mt][2], ah[mt][3]);
        ldsm_x4(abase[s][1] + off, al[mt][0], al[mt][1], al[mt][2], al[mt][3]);
      }
      uint32_t bb[8][2];
#pragma unroll
      for (int np = 0; np < 4; np++) {
        uint32_t off = (np*16*TSTRIDE + ks*16)*2;
        uint32_t r0, r1, r2, r3;
        ldsm_x4(bbase[s] + off, r0, r1, r2, r3);
        bb[2*np][0] = r0; bb[2*np+1][0] = r1; bb[2*np][1] = r2; bb[2*np+1][1] = r3;
      }
#pragma unroll
      for (int mt = 0; mt < 2; mt++)
#pragma unroll
        for (int nt = 0; nt < 8; nt++) {
          mma_f16(f.c[mt][nt], ah[mt], bb[nt]);
          mma_f16(f.c[mt][nt], al[mt], bb[nt]);
        }
    }
    __syncthreads();
  }
}

// ---------------------------------------------------------------------------
// Projection GEMM (256 threads, block 128x128)
// ---------------------------------------------------------------------------
__global__ __launch_bounds__(256, 2) void proj_mma_kernel(const float* __restrict__ bg)
{
  extern __shared__ uint16_t smb[];
  const int tid = threadIdx.x;
  const int c0 = blockIdx.x * 128;
  const int m0 = blockIdx.y * 128;

  FragC f;
  gemm_core2<4>(smb, g_xfh, g_xfl, g_Wcf, m0, c0, 256, tid, f);

  const int lane = tid & 31, wid = tid >> 5;
  const int wm = wid & 3, wn = wid >> 2;
  const int q2 = (lane & 3) * 2, r4 = lane >> 2;
  const int seg = c0 >> 9;
  const int lbase = c0 - seg*512 + wn*64;      // warp spans one 64-col head

#pragma unroll
  for (int mt = 0; mt < 2; mt++) {
#pragma unroll
    for (int h2 = 0; h2 < 2; h2++) {
      const int m = m0 + wm*32 + mt*16 + r4 + h2*8;
      const int bidx = m >> 9, n = m & 511;
      if (seg == 3) {
        float* dst = g_G + m*512 + lbase;
#pragma unroll
        for (int nt = 0; nt < 8; nt++) {
          int cc = nt*8 + q2;
          float2 v;
          v.x = f.c[mt][nt][h2*2+0] + bg[lbase + cc];
          v.y = f.c[mt][nt][h2*2+1] + bg[lbase + cc + 1];
          *(float2*)(dst + cc) = v;
        }
      } else if (seg == 2) {
        const int hh = lbase >> 6;
        const int off = (((bidx*8 + hh)*512 + n)*64);
#pragma unroll
        for (int nt = 0; nt < 8; nt++) {
          int dd = nt*8 + q2;
          uint32_t ph, pl;
          split2packh(f.c[mt][nt][h2*2+0], f.c[mt][nt][h2*2+1], ph, pl);
          *(uint32_t*)(g_Vh + off + dd) = ph;
          *(uint32_t*)(g_Vl + off + dd) = pl;
        }
      } else {
        const int hh = lbase >> 6;
        __nv_bfloat16* bh_ = (seg == 0) ? g_Qh : g_Kh;
        __nv_bfloat16* bl_ = (seg == 0) ? g_Ql : g_Kl;
        const int off = (((bidx*8 + hh)*512 + n)*64);
#pragma unroll
        for (int nt = 0; nt < 8; nt++) {
          int dd = nt*8 + q2;
          uint32_t ph, pl;
          split2pack(f.c[mt][nt][h2*2+0], f.c[mt][nt][h2*2+1], ph, pl);
          *(uint32_t*)(bh_ + off + dd) = ph;
          *(uint32_t*)(bl_ + off + dd) = pl;
        }
      }
    }
  }
}

// ---------------------------------------------------------------------------
// Output GEMM (256 threads, block 128x128)
// ---------------------------------------------------------------------------
__global__ __launch_bounds__(256, 2) void out_mma_kernel(
    const float* __restrict__ bo, float* __restrict__ Y)
{
  extern __shared__ uint16_t smb[];
  const int tid = threadIdx.x;
  const int n0 = blockIdx.x * 128;
  const int m0 = blockIdx.y * 128;

  FragC f;
  gemm_core2<8>(smb, g_Eh, g_El, g_Wof, m0, n0, 512, tid, f);

  const int lane = tid & 31, wid = tid >> 5;
  const int wm = wid & 3, wn = wid >> 2;
  const int q2 = (lane & 3) * 2, r4 = lane >> 2;

#pragma unroll
  for (int mt = 0; mt < 2; mt++) {
#pragma unroll
    for (int h2 = 0; h2 < 2; h2++) {
      const int m = m0 + wm*32 + mt*16 + r4 + h2*8;
      float* dst = Y + m*256 + n0 + wn*64;
      const float* bop = bo + n0 + wn*64;
#pragma unroll
      for (int nt = 0; nt < 8; nt++) {
        int cc = nt*8 + q2;
        float2 v;
        v.x = f.c[mt][nt][h2*2+0] + bop[cc];
        v.y = f.c[mt][nt][h2*2+1] + bop[cc + 1];
        *(float2*)(dst + cc) = v;
      }
    }
  }
}

// ---------------------------------------------------------------------------
// Flash attention (R13 proven, unchanged)
// ---------------------------------------------------------------------------
__global__ __launch_bounds__(256, 2) void attn_flash_kernel(
    const float* __restrict__ bias)
{
  extern __shared__ uint16_t smbu[];
  uint16_t* Qh = smbu;
  uint16_t* Ql = smbu + ATILE;
  uint16_t* KV = smbu + 2*ATILE;

  const int tid = threadIdx.x;
  const int lane = tid & 31, wid = tid >> 5;
  const int wm = wid & 3, wn = wid >> 2;
  const int lrow = (lane & 7) + ((lane >> 3) & 1) * 8;
  const int lcol = (lane >> 4) * 8;
  const int r4 = lane >> 2, q2 = (lane & 3) * 2;
  const int it0 = blockIdx.x * 64;
  const int h = blockIdx.y, b = blockIdx.z;

  const int bh_off = (b*8 + h) * 512 * 64;
  const uint16_t* Khs = (const uint16_t*)(g_Kh + bh_off);
  const uint16_t* Kls = (const uint16_t*)(g_Kl + bh_off);
  const uint16_t* Vhs = (const uint16_t*)(g_Vh + bh_off);
  const uint16_t* Vls = (const uint16_t*)(g_Vl + bh_off);

  cpa_tile64(Qh, (const uint16_t*)(g_Qh + bh_off + it0*64), tid);
  cpa_tile64(Ql, (const uint16_t*)(g_Ql + bh_off + it0*64), tid);
  cpa_tile64(KV,           Khs, tid);
  cpa_tile64(KV + ATILE,   Kls, tid);
  cpa_tile64(KV + 2*ATILE, Vhs, tid);
  cpa_tile64(KV + 3*ATILE, Vls, tid);
  CP_COMMIT();

  const uint32_t qh_base = smem_u32(Qh) + ((wm*16 + lrow)*TSTRIDE + lcol)*2;
  const uint32_t ql_base = smem_u32(Ql) + ((wm*16 + lrow)*TSTRIDE + lcol)*2;
  uint32_t kb[2][2], vb[2][2];
#pragma unroll
  for (int s = 0; s < 2; s++) {
    uint16_t* st = KV + s*4*ATILE;
    kb[s][0] = smem_u32(st)           + ((wn*32 + lrow)*TSTRIDE + lcol)*2;
    kb[s][1] = smem_u32(st + ATILE)   + ((wn*32 + lrow)*TSTRIDE + lcol)*2;
    vb[s][0] = smem_u32(st + 2*ATILE) + ((wn*32 + lrow)*TSTRIDE + lcol)*2;
    vb[s][1] = smem_u32(st + 3*ATILE) + ((wn*32 + lrow)*TSTRIDE + lcol)*2;
  }

  const int row0 = wm*16 + r4;
  const int row1 = row0 + 8;
  const unsigned char* mrow = g_mask + b*512;
  const bool mi0 = mrow[it0 + row0] != 0;
  const bool mi1 = mrow[it0 + row1] != 0;
  const float* brow0 = bias + (h*512 + it0 + row0)*512;
  const float* brow1 = bias + (h*512 + it0 + row1)*512;

  float m0r = -FLT_MAX, m1r = -FLT_MAX, l0r = 0.f, l1r = 0.f;
  float o[8][4];
#pragma unroll
  for (int nf = 0; nf < 8; nf++)
#pragma unroll
    for (int q = 0; q < 4; q++) o[nf][q] = 0.f;

  for (int jt = 0; jt < 8; jt++) {
    if (jt < 7) {
      uint16_t* st = KV + ((jt+1)&1)*4*ATILE;
      const int co = (jt+1)*64*64;
      cpa_tile64(st,           Khs + co, tid);
      cpa_tile64(st + ATILE,   Kls + co, tid);
      cpa_tile64(st + 2*ATILE, Vhs + co, tid);
      cpa_tile64(st + 3*ATILE, Vls + co, tid);
      CP_COMMIT();
      CP_WAIT(1);
    } else {
      CP_WAIT(0);
    }
    __syncthreads();

    const int s = jt & 1;
    float c[4][4];
#pragma unroll
    for (int nf = 0; nf < 4; nf++)
#pragma unroll
      for (int q = 0; q < 4; q++) c[nf][q] = 0.f;

#pragma unroll
    for (int ks = 0; ks < 4; ks++) {
      uint32_t ah[4], al[4];
      ldsm_x4(qh_base + ks*32, ah[0], ah[1], ah[2], ah[3]);
      ldsm_x4(ql_base + ks*32, al[0], al[1], al[2], al[3]);
#pragma unroll
      for (int np = 0; np < 2; np++) {
        uint32_t off = (np*16*TSTRIDE + ks*16)*2;
        uint32_t r0, r1, r2, r3;
        ldsm_x4(kb[s][0] + off, r0, r1, r2, r3);
        uint32_t bh0[2] = {r0, r2}, bh1[2] = {r1, r3};
        ldsm_x4(kb[s][1] + off, r0, r1, r2, r3);
        uint32_t bl0[2] = {r0, r2}, bl1[2] = {r1, r3};
        mma_bf16(c[2*np],   ah, bh0); mma_bf16(c[2*np],   ah, bl0);
        mma_bf16(c[2*np],   al, bh0);
        mma_bf16(c[2*np+1], ah, bh1); mma_bf16(c[2*np+1], ah, bl1);
        mma_bf16(c[2*np+1], al, bh1);
      }
    }

    const int colbase = jt*64 + wn*32;
    float rm0 = -FLT_MAX, rm1 = -FLT_MAX;
#pragma unroll
    for (int nf = 0; nf < 4; nf++) {
      const int col = colbase + nf*8 + q2;
      float2 b0 = *(const float2*)&brow0[col];
      float2 b1 = *(const float2*)&brow1[col];
      bool mjA = mrow[col] != 0, mjB = mrow[col+1] != 0;
      c[nf][0] = (mi0 && mjA) ? c[nf][0]*SCALE_ + b0.x : -FLT_MAX;
      c[nf][1] = (mi0 && mjB) ? c[nf][1]*SCALE_ + b0.y : -FLT_MAX;
      c[nf][2] = (mi1 && mjA) ? c[nf][2]*SCALE_ + b1.x : -FLT_MAX;
      c[nf][3] = (mi1 && mjB) ? c[nf][3]*SCALE_ + b1.y : -FLT_MAX;
      rm0 = fmaxf(rm0, fmaxf(c[nf][0], c[nf][1]));
      rm1 = fmaxf(rm1, fmaxf(c[nf][2], c[nf][3]));
    }
    rm0 = fmaxf(rm0, __shfl_xor_sync(0xffffffffu, rm0, 1));
    rm0 = fmaxf(rm0, __shfl_xor_sync(0xffffffffu, rm0, 2));
    rm1 = fmaxf(rm1, __shfl_xor_sync(0xffffffffu, rm1, 1));
    rm1 = fmaxf(rm1, __shfl_xor_sync(0xffffffffu, rm1, 2));

    const float mn0 = fmaxf(m0r, rm0), mn1 = fmaxf(m1r, rm1);
    const float fs0 = __expf(m0r - mn0), fs1 = __expf(m1r - mn1);

    float ls0 = 0.f, ls1 = 0.f;
#pragma unroll
    for (int nf = 0; nf < 4; nf++) {
      c[nf][0] = __expf(c[nf][0] - mn0);
      c[nf][1] = __expf(c[nf][1] - mn0);
      c[nf][2] = __expf(c[nf][2] - mn1);
      c[nf][3] = __expf(c[nf][3] - mn1);
      ls0 += c[nf][0] + c[nf][1];
      ls1 += c[nf][2] + c[nf][3];
    }
    ls0 += __shfl_xor_sync(0xffffffffu, ls0, 1);
    ls0 += __shfl_xor_sync(0xffffffffu, ls0, 2);
    ls1 += __shfl_xor_sync(0xffffffffu, ls1, 1);
    ls1 += __shfl_xor_sync(0xffffffffu, ls1, 2);
    l0r = l0r*fs0 + ls0;
    l1r = l1r*fs1 + ls1;
    m0r = mn0; m1r = mn1;

#pragma unroll
    for (int nf = 0; nf < 8; nf++) {
      o[nf][0] *= fs0; o[nf][1] *= fs0;
      o[nf][2] *= fs1; o[nf][3] *= fs1;
    }
    uint32_t ap[2][4];
#pragma unroll
    for (int ks2 = 0; ks2 < 2; ks2++) {
      ap[ks2][0] = pack2f16(c[2*ks2][0],   c[2*ks2][1]);
      ap[ks2][1] = pack2f16(c[2*ks2][2],   c[2*ks2][3]);
      ap[ks2][2] = pack2f16(c[2*ks2+1][0], c[2*ks2+1][1]);
      ap[ks2][3] = pack2f16(c[2*ks2+1][2], c[2*ks2+1][3]);
    }

#pragma unroll
    for (int ks2 = 0; ks2 < 2; ks2++) {
      uint32_t bh[8][2], bl[8][2];
#pragma unroll
      for (int np = 0; np < 4; np++) {
        uint32_t off = (ks2*16*TSTRIDE + np*16)*2;
        uint32_t r0, r1, r2, r3;
        ldsm_x4_t(vb[s][0] + off, r0, r1, r2, r3);
        bh[2*np][0] = r0; bh[2*np][1] = r1; bh[2*np+1][0] = r2; bh[2*np+1][1] = r3;
        ldsm_x4_t(vb[s][1] + off, r0, r1, r2, r3);
        bl[2*np][0] = r0; bl[2*np][1] = r1; bl[2*np+1][0] = r2; bl[2*np+1][1] = r3;
      }
#pragma unroll
      for (int nf = 0; nf < 8; nf++) {
        mma_f16(o[nf], ap[ks2], bh[nf]);
        mma_f16(o[nf], ap[ks2], bl[nf]);
      }
    }
    __syncthreads();
  }

  // ---- cross-warp merge (wn=0 <- wn=1), gate, fp16-split store ----
  float* O1  = (float*)KV;          // [64][68]
  float* m1s = O1 + 64*68;          // [64]
  float* l1s = m1s + 64;            // [64]

  if (wn == 1) {
#pragma unroll
    for (int nf = 0; nf < 8; nf++) {
      const int d = nf*8 + q2;
      *(float2*)&O1[row0*68 + d] = make_float2(o[nf][0], o[nf][1]);
      *(float2*)&O1[row1*68 + d] = make_float2(o[nf][2], o[nf][3]);
    }
    if ((lane & 3) == 0) {
      m1s[row0] = m0r; l1s[row0] = l0r;
      m1s[row1] = m1r; l1s[row1] = l1r;
    }
  }
  __syncthreads();

  if (wn == 0) {
    const float mo0 = m1s[row0], lo0 = l1s[row0];
    const float mo1 = m1s[row1], lo1 = l1s[row1];
    const float mf0 = fmaxf(m0r, mo0), mf1 = fmaxf(m1r, mo1);
    const float a0 = __expf(m0r - mf0), b0s = __expf(mo0 - mf0);
    const float a1 = __expf(m1r - mf1), b1s = __expf(mo1 - mf1);
    const float inv0 = 1.0f / (l0r*a0 + lo0*b0s);
    const float inv1 = 1.0f / (l1r*a1 + lo1*b1s);

#pragma unroll
    for (int nf = 0; nf < 8; nf++) {
      const int d = nf*8 + q2;
      const int idx0 = (b*512 + it0 + row0)*512 + h*64 + d;
      const int idx1 = (b*512 + it0 + row1)*512 + h*64 + d;
      float2 p0 = *(float2*)&O1[row0*68 + d];
      float2 p1 = *(float2*)&O1[row1*68 + d];
      float2 gv0 = *(const float2*)(g_G + idx0);
      float2 gv1 = *(const float2*)(g_G + idx1);
      float e00 = (o[nf][0]*a0 + p0.x*b0s) * inv0 * gv0.x;
      float e01 = (o[nf][1]*a0 + p0.y*b0s) * inv0 * gv0.y;
      float e10 = (o[nf][2]*a1 + p1.x*b1s) * inv1 * gv1.x;
      float e11 = (o[nf][3]*a1 + p1.y*b1s) * inv1 * gv1.y;
      uint32_t ph, pl;
      split2packh(e00, e01, ph, pl);
      *(uint32_t*)(g_Eh + idx0) = ph;
      *(uint32_t*)(g_El + idx0) = pl;
      split2packh(e10, e11, ph, pl);
      *(uint32_t*)(g_Eh + idx1) = ph;
      *(uint32_t*)(g_El + idx1) = pl;
    }
  }
}

// ---------------------------------------------------------------------------
extern "C" void kernel_launch(void* const* d_in, const int* in_sizes, int n_in,
                              void* d_out, int out_size)
{
  const float* x   = (const float*)d_in[0];
  const void*  mask = d_in[1];
  const float* bias = (const float*)d_in[2];
  const float* Wq  = (const float*)d_in[3];
  const float* Wkv = (const float*)d_in[4];
  const float* Wo  = (const float*)d_in[5];
  const float* bo  = (const float*)d_in[6];
  const float* Wg  = (const float*)d_in[7];
  const float* bg  = (const float*)d_in[8];
  float* Y = (float*)d_out;

  const int SMEM_ATTN = 10*ATILE*2;               // 92160 B -> 2 CTAs/SM
  const int SMEM_MMA  = 2*GSTAGE*2;               // 110592 B -> 2 CTAs/SM
  cudaFuncSetAttribute(attn_flash_kernel, cudaFuncAttributeMaxDynamicSharedMemorySize,
                       SMEM_ATTN);
  cudaFuncSetAttribute(proj_mma_kernel, cudaFuncAttributeMaxDynamicSharedMemorySize,
                       SMEM_MMA);
  cudaFuncSetAttribute(out_mma_kernel, cudaFuncAttributeMaxDynamicSharedMemorySize,
                       SMEM_MMA);

  detect_mask_kernel<<<1, 256>>>((const unsigned int*)mask);
  convert_mask_kernel<<<128, 256>>>(mask);
  split_all_kernel<<<10752, 256>>>(x, Wq, Wkv, Wg, Wo);
  proj_mma_kernel<<<dim3(16, 256), 256, SMEM_MMA>>>(bg);
  attn_flash_kernel<<<dim3(8, 8, 64), 256, SMEM_ATTN>>>(bias);
  out_mma_kernel<<<dim3(2, 256), 256, SMEM_MMA>>>(bo, Y);
}

// round 16
// speedup vs baseline: 1.4987x; 1.1017x over previous
#include <cuda_runtime.h>
#include <cuda_bf16.h>
#include <cuda_fp16.h>
#include <cfloat>
#include <cstdint>

#define BB_   64
#define NN_   512
#define DIM_  256
#define HH_   8
#define DHH_  64
#define INNER_ 512
#define SCALE_ 0.125f

// ---------------------------------------------------------------------------
// Scratch
// ---------------------------------------------------------------------------
__device__ float g_G[BB_*NN_*INNER_];
__device__ unsigned char g_mask[BB_*NN_];
__device__ int g_mask_mode;

__device__ __half g_xfh[BB_*NN_*DIM_];      // x fp16 split
__device__ __half g_xfl[BB_*NN_*DIM_];
__device__ __half g_Wcf[2048*DIM_];         // concat W^T fp16 single
__device__ __half g_Qh[BB_*HH_*NN_*DHH_];   // Q fp16 split
__device__ __half g_Ql[BB_*HH_*NN_*DHH_];
__device__ __half g_K [BB_*HH_*NN_*DHH_];   // K fp16 single
__device__ __half g_Vh[BB_*HH_*NN_*DHH_];   // V fp16 split
__device__ __half g_Vl[BB_*HH_*NN_*DHH_];
__device__ __half g_Eh[BB_*NN_*INNER_];     // gated attn out fp16 split
__device__ __half g_El[BB_*NN_*INNER_];
__device__ __half g_Wof[DIM_*INNER_];       // Wo^T fp16 single

// ---------------------------------------------------------------------------
// Helpers
// ---------------------------------------------------------------------------
__device__ __forceinline__ uint32_t smem_u32(const void* p) {
  uint32_t a;
  asm("{ .reg .u64 t; cvta.to.shared.u64 t, %1; cvt.u32.u64 %0, t; }"
      : "=r"(a) : "l"(p));
  return a;
}
__device__ __forceinline__ void cp16(uint32_t saddr, const void* g) {
  asm volatile("cp.async.cg.shared.global [%0], [%1], 16;"
               :: "r"(saddr), "l"(g));
}
#define CP_COMMIT() asm volatile("cp.async.commit_group;" ::: "memory")
#define CP_WAIT(n)  asm volatile("cp.async.wait_group %0;" :: "n"(n) : "memory")

__device__ __forceinline__ void ldsm_x4(uint32_t addr, uint32_t& r0,
                                        uint32_t& r1, uint32_t& r2, uint32_t& r3) {
  asm volatile("ldmatrix.sync.aligned.m8n8.x4.shared.b16 {%0,%1,%2,%3}, [%4];"
               : "=r"(r0), "=r"(r1), "=r"(r2), "=r"(r3) : "r"(addr));
}
__device__ __forceinline__ void ldsm_x4_t(uint32_t addr, uint32_t& r0,
                                          uint32_t& r1, uint32_t& r2, uint32_t& r3) {
  asm volatile("ldmatrix.sync.aligned.m8n8.x4.trans.shared.b16 {%0,%1,%2,%3}, [%4];"
               : "=r"(r0), "=r"(r1), "=r"(r2), "=r"(r3) : "r"(addr));
}
__device__ __forceinline__ void mma_f16(float* c, const uint32_t* a,
                                        const uint32_t* b) {
  asm volatile(
    "mma.sync.aligned.m16n8k16.row.col.f32.f16.f16.f32 "
    "{%0,%1,%2,%3}, {%4,%5,%6,%7}, {%8,%9}, {%0,%1,%2,%3};"
    : "+f"(c[0]), "+f"(c[1]), "+f"(c[2]), "+f"(c[3])
    : "r"(a[0]), "r"(a[1]), "r"(a[2]), "r"(a[3]), "r"(b[0]), "r"(b[1]));
}
__device__ __forceinline__ void split2packh(float v0, float v1,
                                            uint32_t& ph, uint32_t& pl) {
  __half h0 = __float2half_rn(v0), h1 = __float2half_rn(v1);
  __half l0 = __float2half_rn(v0 - __half2float(h0));
  __half l1 = __float2half_rn(v1 - __half2float(h1));
  ph = (uint32_t)*(uint16_t*)&h0 | ((uint32_t)*(uint16_t*)&h1 << 16);
  pl = (uint32_t)*(uint16_t*)&l0 | ((uint32_t)*(uint16_t*)&l1 << 16);
}
__device__ __forceinline__ uint32_t pack2f16(float a, float b) {
  __half2 hh = __floats2half2_rn(a, b);
  return *(uint32_t*)&hh;
}

// ---------------------------------------------------------------------------
// Mask detection + conversion (proven)
// ---------------------------------------------------------------------------
__global__ void detect_mask_kernel(const unsigned int* __restrict__ m)
{
  __shared__ int s_not01, s_notf;
  if (threadIdx.x == 0) { s_not01 = 0; s_notf = 0; }
  __syncthreads();
  int a = 0, b = 0;
  for (int i = threadIdx.x; i < 8192; i += 256) {
    unsigned v = m[i];
    if (v != 0u && v != 1u) a = 1;
    if (v != 0u && v != 0x3F800000u) b = 1;
  }
  if (a) atomicOr(&s_not01, 1);
  if (b) atomicOr(&s_notf, 1);
  __syncthreads();
  if (threadIdx.x == 0)
    g_mask_mode = (!s_not01) ? 0 : ((!s_notf) ? 1 : 2);
}

__global__ void convert_mask_kernel(const void* __restrict__ m)
{
  int idx = blockIdx.x * blockDim.x + threadIdx.x;
  if (idx >= BB_*NN_) return;
  int mode = g_mask_mode;
  unsigned char r;
  if (mode == 0)      r = ((const int*)m)[idx] != 0;
  else if (mode == 1) r = ((const unsigned int*)m)[idx] != 0u;
  else                r = ((const unsigned char*)m)[idx] != 0;
  g_mask[idx] = r;
}

// ---------------------------------------------------------------------------
// Fused split conversions
// ---------------------------------------------------------------------------
__global__ void split_all_kernel(const float* __restrict__ x,
                                 const float* __restrict__ Wq,
                                 const float* __restrict__ Wkv,
                                 const float* __restrict__ Wg,
                                 const float* __restrict__ Wo)
{
  int bid = blockIdx.x;
  if (bid < 8192) {
    int i = (bid * 256 + threadIdx.x) * 4;
    float4 v = *(const float4*)(x + i);
    uint32_t h0, l0, h1, l1;
    split2packh(v.x, v.y, h0, l0);
    split2packh(v.z, v.w, h1, l1);
    *(uint2*)(g_xfh + i) = make_uint2(h0, h1);
    *(uint2*)(g_xfl + i) = make_uint2(l0, l1);
  } else if (bid < 10240) {
    int idx = (bid - 8192) * 256 + threadIdx.x;
    int k = idx & 255, n = idx >> 8;
    int seg = n >> 9, col = n & 511;
    float v;
    if (seg == 0)      v = Wq[k*512 + col];
    else if (seg == 1) v = Wkv[k*1024 + col];
    else if (seg == 2) v = Wkv[k*1024 + 512 + col];
    else               v = Wg[k*512 + col];
    g_Wcf[n*256 + k] = __float2half_rn(v);
  } else {
    int idx = (bid - 10240) * 256 + threadIdx.x;
    int n = idx >> 9, k = idx & 511;
    g_Wof[n*512 + k] = __float2half_rn(Wo[k*256 + n]);
  }
}

// ---------------------------------------------------------------------------
// Tile loaders
// ---------------------------------------------------------------------------
#define TSTRIDE 72
#define ATILE (64*TSTRIDE)
#define BTILE (128*TSTRIDE)
#define GSTAGE (3*BTILE)

__device__ __forceinline__ void cpa_t128(
    uint16_t* dst, const uint16_t* __restrict__ src, int ldk, int tid)
{
#pragma unroll
  for (int it = 0; it < 4; it++) {
    int u = it*256 + tid;
    int row = u >> 3, c8 = (u & 7) * 8;
    cp16(smem_u32(dst + row*TSTRIDE + c8), src + row*ldk + c8);
  }
}
__device__ __forceinline__ void cpa_tile64(
    uint16_t* dst, const uint16_t* __restrict__ src, int tid)
{
#pragma unroll
  for (int it = 0; it < 2; it++) {
    int u = it*256 + tid;
    int row = u >> 3, c8 = (u & 7) * 8;
    cp16(smem_u32(dst + row*TSTRIDE + c8), src + row*64 + c8);
  }
}

// ---------------------------------------------------------------------------
// Dense GEMM core (fp16 2-term, R15 proven): block 128x128, 8 warps (4m x 2n)
// ---------------------------------------------------------------------------
struct FragC { float c[2][8][4]; };

template <int KCHUNKS>
__device__ __forceinline__ void gemm_core2(
    uint16_t* smb,
    const __half* gAh, const __half* gAl, const __half* gB,
    int m0, int n0blk, int ldk, int tid, FragC& f)
{
  const int lane = tid & 31, wid = tid >> 5;
  const int wm = wid & 3, wn = wid >> 2;
  const int lrow = (lane & 7) + ((lane >> 3) & 1) * 8;
  const int lcol = (lane >> 4) * 8;

  uint32_t abase[2][2], bbase[2];
#pragma unroll
  for (int s = 0; s < 2; s++) {
    uint16_t* st = smb + s*GSTAGE;
    abase[s][0] = smem_u32(st)           + ((wm*32 + lrow)*TSTRIDE + lcol)*2;
    abase[s][1] = smem_u32(st + BTILE)   + ((wm*32 + lrow)*TSTRIDE + lcol)*2;
    bbase[s]    = smem_u32(st + 2*BTILE) + ((wn*64 + lrow)*TSTRIDE + lcol)*2;
  }

#pragma unroll
  for (int mt = 0; mt < 2; mt++)
#pragma unroll
    for (int nt = 0; nt < 8; nt++)
#pragma unroll
      for (int q = 0; q < 4; q++) f.c[mt][nt][q] = 0.f;

  {
    uint16_t* st = smb;
    cpa_t128(st,           (const uint16_t*)gAh + m0*ldk,    ldk, tid);
    cpa_t128(st + BTILE,   (const uint16_t*)gAl + m0*ldk,    ldk, tid);
    cpa_t128(st + 2*BTILE, (const uint16_t*)gB  + n0blk*ldk, ldk, tid);
    CP_COMMIT();
  }

  for (int kc = 0; kc < KCHUNKS; kc++) {
    if (kc + 1 < KCHUNKS) {
      uint16_t* st = smb + ((kc+1)&1)*GSTAGE;
      int co = (kc+1)*64;
      cpa_t128(st,           (const uint16_t*)gAh + m0*ldk + co,    ldk, tid);
      cpa_t128(st + BTILE,   (const uint16_t*)gAl + m0*ldk + co,    ldk, tid);
      cpa_t128(st + 2*BTILE, (const uint16_t*)gB  + n0blk*ldk + co, ldk, tid);
      CP_COMMIT();
      CP_WAIT(1);
    } else {
      CP_WAIT(0);
    }
    __syncthreads();

    const int s = kc & 1;
#pragma unroll
    for (int ks = 0; ks < 4; ks++) {
      uint32_t ah[2][4], al[2][4];
#pragma unroll
      for (int mt = 0; mt < 2; mt++) {
        uint32_t off = (mt*16*TSTRIDE + ks*16)*2;
        ldsm_x4(abase[s][0] + off, ah[mt][0], ah[mt][1], ah[mt][2], ah[mt][3]);
        ldsm_x4(abase[s][1] + off, al[mt][0], al[mt][1], al[mt][2], al[mt][3]);
      }
      uint32_t bb[8][2];
#pragma unroll
      for (int np = 0; np < 4; np++) {
        uint32_t off = (np*16*TSTRIDE + ks*16)*2;
        uint32_t r0, r1, r2, r3;
        ldsm_x4(bbase[s] + off, r0, r1, r2, r3);
        bb[2*np][0] = r0; bb[2*np+1][0] = r1; bb[2*np][1] = r2; bb[2*np+1][1] = r3;
      }
#pragma unroll
      for (int mt = 0; mt < 2; mt++)
#pragma unroll
        for (int nt = 0; nt < 8; nt++) {
          mma_f16(f.c[mt][nt], ah[mt], bb[nt]);
          mma_f16(f.c[mt][nt], al[mt], bb[nt]);
        }
    }
    __syncthreads();
  }
}

// ---------------------------------------------------------------------------
// Projection GEMM (256 threads, block 128x128)
// ---------------------------------------------------------------------------
__global__ __launch_bounds__(256, 2) void proj_mma_kernel(const float* __restrict__ bg)
{
  extern __shared__ uint16_t smb[];
  const int tid = threadIdx.x;
  const int c0 = blockIdx.x * 128;
  const int m0 = blockIdx.y * 128;

  FragC f;
  gemm_core2<4>(smb, g_xfh, g_xfl, g_Wcf, m0, c0, 256, tid, f);

  const int lane = tid & 31, wid = tid >> 5;
  const int wm = wid & 3, wn = wid >> 2;
  const int q2 = (lane & 3) * 2, r4 = lane >> 2;
  const int seg = c0 >> 9;
  const int lbase = c0 - seg*512 + wn*64;      // warp spans one 64-col head

#pragma unroll
  for (int mt = 0; mt < 2; mt++) {
#pragma unroll
    for (int h2 = 0; h2 < 2; h2++) {
      const int m = m0 + wm*32 + mt*16 + r4 + h2*8;
      const int bidx = m >> 9, n = m & 511;
      if (seg == 3) {
        float* dst = g_G + m*512 + lbase;
#pragma unroll
        for (int nt = 0; nt < 8; nt++) {
          int cc = nt*8 + q2;
          float2 v;
          v.x = f.c[mt][nt][h2*2+0] + bg[lbase + cc];
          v.y = f.c[mt][nt][h2*2+1] + bg[lbase + cc + 1];
          *(float2*)(dst + cc) = v;
        }
      } else if (seg == 1) {
        // K: fp16 single
        const int hh = lbase >> 6;
        const int off = (((bidx*8 + hh)*512 + n)*64);
#pragma unroll
        for (int nt = 0; nt < 8; nt++) {
          int dd = nt*8 + q2;
          *(uint32_t*)(g_K + off + dd) =
              pack2f16(f.c[mt][nt][h2*2+0], f.c[mt][nt][h2*2+1]);
        }
      } else {
        // Q (seg 0) or V (seg 2): fp16 split
        const int hh = lbase >> 6;
        __half* bh_ = (seg == 0) ? g_Qh : g_Vh;
        __half* bl_ = (seg == 0) ? g_Ql : g_Vl;
        const int off = (((bidx*8 + hh)*512 + n)*64);
#pragma unroll
        for (int nt = 0; nt < 8; nt++) {
          int dd = nt*8 + q2;
          uint32_t ph, pl;
          split2packh(f.c[mt][nt][h2*2+0], f.c[mt][nt][h2*2+1], ph, pl);
          *(uint32_t*)(bh_ + off + dd) = ph;
          *(uint32_t*)(bl_ + off + dd) = pl;
        }
      }
    }
  }
}

// ---------------------------------------------------------------------------
// Output GEMM (256 threads, block 128x128)
// ---------------------------------------------------------------------------
__global__ __launch_bounds__(256, 2) void out_mma_kernel(
    const float* __restrict__ bo, float* __restrict__ Y)
{
  extern __shared__ uint16_t smb[];
  const int tid = threadIdx.x;
  const int n0 = blockIdx.x * 128;
  const int m0 = blockIdx.y * 128;

  FragC f;
  gemm_core2<8>(smb, g_Eh, g_El, g_Wof, m0, n0, 512, tid, f);

  const int lane = tid & 31, wid = tid >> 5;
  const int wm = wid & 3, wn = wid >> 2;
  const int q2 = (lane & 3) * 2, r4 = lane >> 2;

#pragma unroll
  for (int mt = 0; mt < 2; mt++) {
#pragma unroll
    for (int h2 = 0; h2 < 2; h2++) {
      const int m = m0 + wm*32 + mt*16 + r4 + h2*8;
      float* dst = Y + m*256 + n0 + wn*64;
      const float* bop = bo + n0 + wn*64;
#pragma unroll
      for (int nt = 0; nt < 8; nt++) {
        int cc = nt*8 + q2;
        float2 v;
        v.x = f.c[mt][nt][h2*2+0] + bop[cc];
        v.y = f.c[mt][nt][h2*2+1] + bop[cc + 1];
        *(float2*)(dst + cc) = v;
      }
    }
  }
}

// ---------------------------------------------------------------------------
// Flash attention: QK fp16 (Q 2-term split x K single), PV fp16 2-product.
// smem: Qh@0, Ql@ATILE; stage s at (2+s*3)*ATILE: [K, Vh, Vl]. 8 ATILE total.
// ---------------------------------------------------------------------------
__global__ __launch_bounds__(256, 2) void attn_flash_kernel(
    const float* __restrict__ bias)
{
  extern __shared__ uint16_t smbu[];
  uint16_t* Qh = smbu;
  uint16_t* Ql = smbu + ATILE;
  uint16_t* KV = smbu + 2*ATILE;

  const int tid = threadIdx.x;
  const int lane = tid & 31, wid = tid >> 5;
  const int wm = wid & 3, wn = wid >> 2;
  const int lrow = (lane & 7) + ((lane >> 3) & 1) * 8;
  const int lcol = (lane >> 4) * 8;
  const int r4 = lane >> 2, q2 = (lane & 3) * 2;
  const int it0 = blockIdx.x * 64;
  const int h = blockIdx.y, b = blockIdx.z;

  const int bh_off = (b*8 + h) * 512 * 64;
  const uint16_t* Ks  = (const uint16_t*)(g_K  + bh_off);
  const uint16_t* Vhs = (const uint16_t*)(g_Vh + bh_off);
  const uint16_t* Vls = (const uint16_t*)(g_Vl + bh_off);

  cpa_tile64(Qh, (const uint16_t*)(g_Qh + bh_off + it0*64), tid);
  cpa_tile64(Ql, (const uint16_t*)(g_Ql + bh_off + it0*64), tid);
  cpa_tile64(KV,           Ks,  tid);
  cpa_tile64(KV + ATILE,   Vhs, tid);
  cpa_tile64(KV + 2*ATILE, Vls, tid);
  CP_COMMIT();

  const uint32_t qh_base = smem_u32(Qh) + ((wm*16 + lrow)*TSTRIDE + lcol)*2;
  const uint32_t ql_base = smem_u32(Ql) + ((wm*16 + lrow)*TSTRIDE + lcol)*2;
  uint32_t kb[2], vb[2][2];
#pragma unroll
  for (int s = 0; s < 2; s++) {
    uint16_t* st = KV + s*3*ATILE;
    kb[s]    = smem_u32(st)           + ((wn*32 + lrow)*TSTRIDE + lcol)*2;
    vb[s][0] = smem_u32(st + ATILE)   + ((wn*32 + lrow)*TSTRIDE + lcol)*2;
    vb[s][1] = smem_u32(st + 2*ATILE) + ((wn*32 + lrow)*TSTRIDE + lcol)*2;
  }

  const int row0 = wm*16 + r4;
  const int row1 = row0 + 8;
  const unsigned char* mrow = g_mask + b*512;
  const bool mi0 = mrow[it0 + row0] != 0;
  const bool mi1 = mrow[it0 + row1] != 0;
  const float* brow0 = bias + (h*512 + it0 + row0)*512;
  const float* brow1 = bias + (h*512 + it0 + row1)*512;

  float m0r = -FLT_MAX, m1r = -FLT_MAX, l0r = 0.f, l1r = 0.f;
  float o[8][4];
#pragma unroll
  for (int nf = 0; nf < 8; nf++)
#pragma unroll
    for (int q = 0; q < 4; q++) o[nf][q] = 0.f;

  for (int jt = 0; jt < 8; jt++) {
    if (jt < 7) {
      uint16_t* st = KV + ((jt+1)&1)*3*ATILE;
      const int co = (jt+1)*64*64;
      cpa_tile64(st,           Ks  + co, tid);
      cpa_tile64(st + ATILE,   Vhs + co, tid);
      cpa_tile64(st + 2*ATILE, Vls + co, tid);
      CP_COMMIT();
      CP_WAIT(1);
    } else {
      CP_WAIT(0);
    }
    __syncthreads();

    const int s = jt & 1;
    // ---- S = Q K^T chunk (fp16: Qh/Ql x K) ----
    float c[4][4];
#pragma unroll
    for (int nf = 0; nf < 4; nf++)
#pragma unroll
      for (int q = 0; q < 4; q++) c[nf][q] = 0.f;

#pragma unroll
    for (int ks = 0; ks < 4; ks++) {
      uint32_t ah[4], al[4];
      ldsm_x4(qh_base + ks*32, ah[0], ah[1], ah[2], ah[3]);
      ldsm_x4(ql_base + ks*32, al[0], al[1], al[2], al[3]);
#pragma unroll
      for (int np = 0; np < 2; np++) {
        uint32_t off = (np*16*TSTRIDE + ks*16)*2;
        uint32_t r0, r1, r2, r3;
        ldsm_x4(kb[s] + off, r0, r1, r2, r3);
        uint32_t b0[2] = {r0, r2}, b1[2] = {r1, r3};
        mma_f16(c[2*np],   ah, b0); mma_f16(c[2*np],   al, b0);
        mma_f16(c[2*np+1], ah, b1); mma_f16(c[2*np+1], al, b1);
      }
    }

    // ---- scale + bias + mask; per-warp row max ----
    const int colbase = jt*64 + wn*32;
    float rm0 = -FLT_MAX, rm1 = -FLT_MAX;
#pragma unroll
    for (int nf = 0; nf < 4; nf++) {
      const int col = colbase + nf*8 + q2;
      float2 b0 = *(const float2*)&brow0[col];
      float2 b1 = *(const float2*)&brow1[col];
      bool mjA = mrow[col] != 0, mjB = mrow[col+1] != 0;
      c[nf][0] = (mi0 && mjA) ? c[nf][0]*SCALE_ + b0.x : -FLT_MAX;
      c[nf][1] = (mi0 && mjB) ? c[nf][1]*SCALE_ + b0.y : -FLT_MAX;
      c[nf][2] = (mi1 && mjA) ? c[nf][2]*SCALE_ + b1.x : -FLT_MAX;
      c[nf][3] = (mi1 && mjB) ? c[nf][3]*SCALE_ + b1.y : -FLT_MAX;
      rm0 = fmaxf(rm0, fmaxf(c[nf][0], c[nf][1]));
      rm1 = fmaxf(rm1, fmaxf(c[nf][2], c[nf][3]));
    }
    rm0 = fmaxf(rm0, __shfl_xor_sync(0xffffffffu, rm0, 1));
    rm0 = fmaxf(rm0, __shfl_xor_sync(0xffffffffu, rm0, 2));
    rm1 = fmaxf(rm1, __shfl_xor_sync(0xffffffffu, rm1, 1));
    rm1 = fmaxf(rm1, __shfl_xor_sync(0xffffffffu, rm1, 2));

    const float mn0 = fmaxf(m0r, rm0), mn1 = fmaxf(m1r, rm1);
    const float fs0 = __expf(m0r - mn0), fs1 = __expf(m1r - mn1);

    float ls0 = 0.f, ls1 = 0.f;
#pragma unroll
    for (int nf = 0; nf < 4; nf++) {
      c[nf][0] = __expf(c[nf][0] - mn0);
      c[nf][1] = __expf(c[nf][1] - mn0);
      c[nf][2] = __expf(c[nf][2] - mn1);
      c[nf][3] = __expf(c[nf][3] - mn1);
      ls0 += c[nf][0] + c[nf][1];
      ls1 += c[nf][2] + c[nf][3];
    }
    ls0 += __shfl_xor_sync(0xffffffffu, ls0, 1);
    ls0 += __shfl_xor_sync(0xffffffffu, ls0, 2);
    ls1 += __shfl_xor_sync(0xffffffffu, ls1, 1);
    ls1 += __shfl_xor_sync(0xffffffffu, ls1, 2);
    l0r = l0r*fs0 + ls0;
    l1r = l1r*fs1 + ls1;
    m0r = mn0; m1r = mn1;

    // ---- rescale O; pack P into fp16 A-fragments ----
#pragma unroll
    for (int nf = 0; nf < 8; nf++) {
      o[nf][0] *= fs0; o[nf][1] *= fs0;
      o[nf][2] *= fs1; o[nf][3] *= fs1;
    }
    uint32_t ap[2][4];
#pragma unroll
    for (int ks2 = 0; ks2 < 2; ks2++) {
      ap[ks2][0] = pack2f16(c[2*ks2][0],   c[2*ks2][1]);
      ap[ks2][1] = pack2f16(c[2*ks2][2],   c[2*ks2][3]);
      ap[ks2][2] = pack2f16(c[2*ks2+1][0], c[2*ks2+1][1]);
      ap[ks2][3] = pack2f16(c[2*ks2+1][2], c[2*ks2+1][3]);
    }

    // ---- O += P V (fp16 2-product) ----
#pragma unroll
    for (int ks2 = 0; ks2 < 2; ks2++) {
      uint32_t bh[8][2], bl[8][2];
#pragma unroll
      for (int np = 0; np < 4; np++) {
        uint32_t off = (ks2*16*TSTRIDE + np*16)*2;
        uint32_t r0, r1, r2, r3;
        ldsm_x4_t(vb[s][0] + off, r0, r1, r2, r3);
        bh[2*np][0] = r0; bh[2*np][1] = r1; bh[2*np+1][0] = r2; bh[2*np+1][1] = r3;
        ldsm_x4_t(vb[s][1] + off, r0, r1, r2, r3);
        bl[2*np][0] = r0; bl[2*np][1] = r1; bl[2*np+1][0] = r2; bl[2*np+1][1] = r3;
      }
#pragma unroll
      for (int nf = 0; nf < 8; nf++) {
        mma_f16(o[nf], ap[ks2], bh[nf]);
        mma_f16(o[nf], ap[ks2], bl[nf]);
      }
    }
    __syncthreads();
  }

  // ---- cross-warp merge (wn=0 <- wn=1), gate, fp16-split store ----
  float* O1  = (float*)KV;          // [64][68]
  float* m1s = O1 + 64*68;          // [64]
  float* l1s = m1s + 64;            // [64]

  if (wn == 1) {
#pragma unroll
    for (int nf = 0; nf < 8; nf++) {
      const int d = nf*8 + q2;
      *(float2*)&O1[row0*68 + d] = make_float2(o[nf][0], o[nf][1]);
      *(float2*)&O1[row1*68 + d] = make_float2(o[nf][2], o[nf][3]);
    }
    if ((lane & 3) == 0) {
      m1s[row0] = m0r; l1s[row0] = l0r;
      m1s[row1] = m1r; l1s[row1] = l1r;
    }
  }
  __syncthreads();

  if (wn == 0) {
    const float mo0 = m1s[row0], lo0 = l1s[row0];
    const float mo1 = m1s[row1], lo1 = l1s[row1];
    const float mf0 = fmaxf(m0r, mo0), mf1 = fmaxf(m1r, mo1);
    const float a0 = __expf(m0r - mf0), b0s = __expf(mo0 - mf0);
    const float a1 = __expf(m1r - mf1), b1s = __expf(mo1 - mf1);
    const float inv0 = 1.0f / (l0r*a0 + lo0*b0s);
    const float inv1 = 1.0f / (l1r*a1 + lo1*b1s);

#pragma unroll
    for (int nf = 0; nf < 8; nf++) {
      const int d = nf*8 + q2;
      const int idx0 = (b*512 + it0 + row0)*512 + h*64 + d;
      const int idx1 = (b*512 + it0 + row1)*512 + h*64 + d;
      float2 p0 = *(float2*)&O1[row0*68 + d];
      float2 p1 = *(float2*)&O1[row1*68 + d];
      float2 gv0 = *(const float2*)(g_G + idx0);
      float2 gv1 = *(const float2*)(g_G + idx1);
      float e00 = (o[nf][0]*a0 + p0.x*b0s) * inv0 * gv0.x;
      float e01 = (o[nf][1]*a0 + p0.y*b0s) * inv0 * gv0.y;
      float e10 = (o[nf][2]*a1 + p1.x*b1s) * inv1 * gv1.x;
      float e11 = (o[nf][3]*a1 + p1.y*b1s) * inv1 * gv1.y;
      uint32_t ph, pl;
      split2packh(e00, e01, ph, pl);
      *(uint32_t*)(g_Eh + idx0) = ph;
      *(uint32_t*)(g_El + idx0) = pl;
      split2packh(e10, e11, ph, pl);
      *(uint32_t*)(g_Eh + idx1) = ph;
      *(uint32_t*)(g_El + idx1) = pl;
    }
  }
}

// ---------------------------------------------------------------------------
extern "C" void kernel_launch(void* const* d_in, const int* in_sizes, int n_in,
                              void* d_out, int out_size)
{
  const float* x   = (const float*)d_in[0];
  const void*  mask = d_in[1];
  const float* bias = (const float*)d_in[2];
  const float* Wq  = (const float*)d_in[3];
  const float* Wkv = (const float*)d_in[4];
  const float* Wo  = (const float*)d_in[5];
  const float* bo  = (const float*)d_in[6];
  const float* Wg  = (const float*)d_in[7];
  const float* bg  = (const float*)d_in[8];
  float* Y = (float*)d_out;

  const int SMEM_ATTN = 8*ATILE*2;                // 73728 B -> 2 CTAs/SM
  const int SMEM_MMA  = 2*GSTAGE*2;               // 110592 B -> 2 CTAs/SM
  cudaFuncSetAttribute(attn_flash_kernel, cudaFuncAttributeMaxDynamicSharedMemorySize,
                       SMEM_ATTN);
  cudaFuncSetAttribute(proj_mma_kernel, cudaFuncAttributeMaxDynamicSharedMemorySize,
                       SMEM_MMA);
  cudaFuncSetAttribute(out_mma_kernel, cudaFuncAttributeMaxDynamicSharedMemorySize,
                       SMEM_MMA);

  detect_mask_kernel<<<1, 256>>>((const unsigned int*)mask);
  convert_mask_kernel<<<128, 256>>>(mask);
  split_all_kernel<<<10752, 256>>>(x, Wq, Wkv, Wg, Wo);
  proj_mma_kernel<<<dim3(16, 256), 256, SMEM_MMA>>>(bg);
  attn_flash_kernel<<<dim3(8, 8, 64), 256, SMEM_ATTN>>>(bias);
  out_mma_kernel<<<dim3(2, 256), 256, SMEM_MMA>>>(bo, Y);
}

// round 17
// speedup vs baseline: 1.7159x; 1.1449x over previous
#include <cuda_runtime.h>
#include <cuda_bf16.h>
#include <cuda_fp16.h>
#include <cfloat>
#include <cstdint>

#define BB_   64
#define NN_   512
#define DIM_  256
#define HH_   8
#define DHH_  64
#define INNER_ 512
#define SCALE_ 0.125f

// ---------------------------------------------------------------------------
// Scratch
// ---------------------------------------------------------------------------
__device__ float g_G[BB_*NN_*INNER_];
__device__ unsigned char g_mask[BB_*NN_];
__device__ int g_mask_mode;

__device__ __half g_xfh[BB_*NN_*DIM_];      // x fp16 split
__device__ __half g_xfl[BB_*NN_*DIM_];
__device__ __half g_Wcf[2048*DIM_];         // concat W^T fp16 single
__device__ __half g_Qh[BB_*HH_*NN_*DHH_];   // Q fp16 split
__device__ __half g_Ql[BB_*HH_*NN_*DHH_];
__device__ __half g_K [BB_*HH_*NN_*DHH_];   // K fp16 single
__device__ __half g_V [BB_*HH_*NN_*DHH_];   // V fp16 single
__device__ __half g_E [BB_*NN_*INNER_];     // gated attn out fp16 single
__device__ __half g_Wof[DIM_*INNER_];       // Wo^T fp16 single

// ---------------------------------------------------------------------------
// Helpers
// ---------------------------------------------------------------------------
__device__ __forceinline__ uint32_t smem_u32(const void* p) {
  uint32_t a;
  asm("{ .reg .u64 t; cvta.to.shared.u64 t, %1; cvt.u32.u64 %0, t; }"
      : "=r"(a) : "l"(p));
  return a;
}
__device__ __forceinline__ void cp16(uint32_t saddr, const void* g) {
  asm volatile("cp.async.cg.shared.global [%0], [%1], 16;"
               :: "r"(saddr), "l"(g));
}
#define CP_COMMIT() asm volatile("cp.async.commit_group;" ::: "memory")
#define CP_WAIT(n)  asm volatile("cp.async.wait_group %0;" :: "n"(n) : "memory")

__device__ __forceinline__ void ldsm_x4(uint32_t addr, uint32_t& r0,
                                        uint32_t& r1, uint32_t& r2, uint32_t& r3) {
  asm volatile("ldmatrix.sync.aligned.m8n8.x4.shared.b16 {%0,%1,%2,%3}, [%4];"
               : "=r"(r0), "=r"(r1), "=r"(r2), "=r"(r3) : "r"(addr));
}
__device__ __forceinline__ void ldsm_x4_t(uint32_t addr, uint32_t& r0,
                                          uint32_t& r1, uint32_t& r2, uint32_t& r3) {
  asm volatile("ldmatrix.sync.aligned.m8n8.x4.trans.shared.b16 {%0,%1,%2,%3}, [%4];"
               : "=r"(r0), "=r"(r1), "=r"(r2), "=r"(r3) : "r"(addr));
}
__device__ __forceinline__ void mma_f16(float* c, const uint32_t* a,
                                        const uint32_t* b) {
  asm volatile(
    "mma.sync.aligned.m16n8k16.row.col.f32.f16.f16.f32 "
    "{%0,%1,%2,%3}, {%4,%5,%6,%7}, {%8,%9}, {%0,%1,%2,%3};"
    : "+f"(c[0]), "+f"(c[1]), "+f"(c[2]), "+f"(c[3])
    : "r"(a[0]), "r"(a[1]), "r"(a[2]), "r"(a[3]), "r"(b[0]), "r"(b[1]));
}
__device__ __forceinline__ void split2packh(float v0, float v1,
                                            uint32_t& ph, uint32_t& pl) {
  __half h0 = __float2half_rn(v0), h1 = __float2half_rn(v1);
  __half l0 = __float2half_rn(v0 - __half2float(h0));
  __half l1 = __float2half_rn(v1 - __half2float(h1));
  ph = (uint32_t)*(uint16_t*)&h0 | ((uint32_t)*(uint16_t*)&h1 << 16);
  pl = (uint32_t)*(uint16_t*)&l0 | ((uint32_t)*(uint16_t*)&l1 << 16);
}
__device__ __forceinline__ uint32_t pack2f16(float a, float b) {
  __half2 hh = __floats2half2_rn(a, b);
  return *(uint32_t*)&hh;
}

// ---------------------------------------------------------------------------
// Mask detection + conversion (proven)
// ---------------------------------------------------------------------------
__global__ void detect_mask_kernel(const unsigned int* __restrict__ m)
{
  __shared__ int s_not01, s_notf;
  if (threadIdx.x == 0) { s_not01 = 0; s_notf = 0; }
  __syncthreads();
  int a = 0, b = 0;
  for (int i = threadIdx.x; i < 8192; i += 256) {
    unsigned v = m[i];
    if (v != 0u && v != 1u) a = 1;
    if (v != 0u && v != 0x3F800000u) b = 1;
  }
  if (a) atomicOr(&s_not01, 1);
  if (b) atomicOr(&s_notf, 1);
  __syncthreads();
  if (threadIdx.x == 0)
    g_mask_mode = (!s_not01) ? 0 : ((!s_notf) ? 1 : 2);
}

__global__ void convert_mask_kernel(const void* __restrict__ m)
{
  int idx = blockIdx.x * blockDim.x + threadIdx.x;
  if (idx >= BB_*NN_) return;
  int mode = g_mask_mode;
  unsigned char r;
  if (mode == 0)      r = ((const int*)m)[idx] != 0;
  else if (mode == 1) r = ((const unsigned int*)m)[idx] != 0u;
  else                r = ((const unsigned char*)m)[idx] != 0;
  g_mask[idx] = r;
}

// ---------------------------------------------------------------------------
// Fused split conversions
// ---------------------------------------------------------------------------
__global__ void split_all_kernel(const float* __restrict__ x,
                                 const float* __restrict__ Wq,
                                 const float* __restrict__ Wkv,
                                 const float* __restrict__ Wg,
                                 const float* __restrict__ Wo)
{
  int bid = blockIdx.x;
  if (bid < 8192) {
    int i = (bid * 256 + threadIdx.x) * 4;
    float4 v = *(const float4*)(x + i);
    uint32_t h0, l0, h1, l1;
    split2packh(v.x, v.y, h0, l0);
    split2packh(v.z, v.w, h1, l1);
    *(uint2*)(g_xfh + i) = make_uint2(h0, h1);
    *(uint2*)(g_xfl + i) = make_uint2(l0, l1);
  } else if (bid < 10240) {
    int idx = (bid - 8192) * 256 + threadIdx.x;
    int k = idx & 255, n = idx >> 8;
    int seg = n >> 9, col = n & 511;
    float v;
    if (seg == 0)      v = Wq[k*512 + col];
    else if (seg == 1) v = Wkv[k*1024 + col];
    else if (seg == 2) v = Wkv[k*1024 + 512 + col];
    else               v = Wg[k*512 + col];
    g_Wcf[n*256 + k] = __float2half_rn(v);
  } else {
    int idx = (bid - 10240) * 256 + threadIdx.x;
    int n = idx >> 9, k = idx & 511;
    g_Wof[n*512 + k] = __float2half_rn(Wo[k*256 + n]);
  }
}

// ---------------------------------------------------------------------------
// Tile loaders
// ---------------------------------------------------------------------------
#define TSTRIDE 72
#define ATILE (64*TSTRIDE)
#define BTILE (128*TSTRIDE)
#define GSTAGE (3*BTILE)   // proj stage: Ah + Al + B
#define OSTAGE (2*BTILE)   // out stage: A + B

__device__ __forceinline__ void cpa_t128(
    uint16_t* dst, const uint16_t* __restrict__ src, int ldk, int tid)
{
#pragma unroll
  for (int it = 0; it < 4; it++) {
    int u = it*256 + tid;
    int row = u >> 3, c8 = (u & 7) * 8;
    cp16(smem_u32(dst + row*TSTRIDE + c8), src + row*ldk + c8);
  }
}
__device__ __forceinline__ void cpa_tile64(
    uint16_t* dst, const uint16_t* __restrict__ src, int tid)
{
#pragma unroll
  for (int it = 0; it < 2; it++) {
    int u = it*256 + tid;
    int row = u >> 3, c8 = (u & 7) * 8;
    cp16(smem_u32(dst + row*TSTRIDE + c8), src + row*64 + c8);
  }
}

// ---------------------------------------------------------------------------
// Dense GEMM cores: block 128x128, 8 warps (4m x 2n), warp tile 32x64.
// gemm_core2: A split 2-term; gemm_core1: A single 1-term.
// ---------------------------------------------------------------------------
struct FragC { float c[2][8][4]; };

template <int KCHUNKS>
__device__ __forceinline__ void gemm_core2(
    uint16_t* smb,
    const __half* gAh, const __half* gAl, const __half* gB,
    int m0, int n0blk, int ldk, int tid, FragC& f)
{
  const int lane = tid & 31, wid = tid >> 5;
  const int wm = wid & 3, wn = wid >> 2;
  const int lrow = (lane & 7) + ((lane >> 3) & 1) * 8;
  const int lcol = (lane >> 4) * 8;

  uint32_t abase[2][2], bbase[2];
#pragma unroll
  for (int s = 0; s < 2; s++) {
    uint16_t* st = smb + s*GSTAGE;
    abase[s][0] = smem_u32(st)           + ((wm*32 + lrow)*TSTRIDE + lcol)*2;
    abase[s][1] = smem_u32(st + BTILE)   + ((wm*32 + lrow)*TSTRIDE + lcol)*2;
    bbase[s]    = smem_u32(st + 2*BTILE) + ((wn*64 + lrow)*TSTRIDE + lcol)*2;
  }

#pragma unroll
  for (int mt = 0; mt < 2; mt++)
#pragma unroll
    for (int nt = 0; nt < 8; nt++)
#pragma unroll
      for (int q = 0; q < 4; q++) f.c[mt][nt][q] = 0.f;

  {
    uint16_t* st = smb;
    cpa_t128(st,           (const uint16_t*)gAh + m0*ldk,    ldk, tid);
    cpa_t128(st + BTILE,   (const uint16_t*)gAl + m0*ldk,    ldk, tid);
    cpa_t128(st + 2*BTILE, (const uint16_t*)gB  + n0blk*ldk, ldk, tid);
    CP_COMMIT();
  }

  for (int kc = 0; kc < KCHUNKS; kc++) {
    if (kc + 1 < KCHUNKS) {
      uint16_t* st = smb + ((kc+1)&1)*GSTAGE;
      int co = (kc+1)*64;
      cpa_t128(st,           (const uint16_t*)gAh + m0*ldk + co,    ldk, tid);
      cpa_t128(st + BTILE,   (const uint16_t*)gAl + m0*ldk + co,    ldk, tid);
      cpa_t128(st + 2*BTILE, (const uint16_t*)gB  + n0blk*ldk + co, ldk, tid);
      CP_COMMIT();
      CP_WAIT(1);
    } else {
      CP_WAIT(0);
    }
    __syncthreads();

    const int s = kc & 1;
#pragma unroll
    for (int ks = 0; ks < 4; ks++) {
      uint32_t ah[2][4], al[2][4];
#pragma unroll
      for (int mt = 0; mt < 2; mt++) {
        uint32_t off = (mt*16*TSTRIDE + ks*16)*2;
        ldsm_x4(abase[s][0] + off, ah[mt][0], ah[mt][1], ah[mt][2], ah[mt][3]);
        ldsm_x4(abase[s][1] + off, al[mt][0], al[mt][1], al[mt][2], al[mt][3]);
      }
      uint32_t bb[8][2];
#pragma unroll
      for (int np = 0; np < 4; np++) {
        uint32_t off = (np*16*TSTRIDE + ks*16)*2;
        uint32_t r0, r1, r2, r3;
        ldsm_x4(bbase[s] + off, r0, r1, r2, r3);
        bb[2*np][0] = r0; bb[2*np+1][0] = r1; bb[2*np][1] = r2; bb[2*np+1][1] = r3;
      }
#pragma unroll
      for (int mt = 0; mt < 2; mt++)
#pragma unroll
        for (int nt = 0; nt < 8; nt++) {
          mma_f16(f.c[mt][nt], ah[mt], bb[nt]);
          mma_f16(f.c[mt][nt], al[mt], bb[nt]);
        }
    }
    __syncthreads();
  }
}

template <int KCHUNKS>
__device__ __forceinline__ void gemm_core1(
    uint16_t* smb,
    const __half* gA, const __half* gB,
    int m0, int n0blk, int ldk, int tid, FragC& f)
{
  const int lane = tid & 31, wid = tid >> 5;
  const int wm = wid & 3, wn = wid >> 2;
  const int lrow = (lane & 7) + ((lane >> 3) & 1) * 8;
  const int lcol = (lane >> 4) * 8;

  uint32_t abase[2], bbase[2];
#pragma unroll
  for (int s = 0; s < 2; s++) {
    uint16_t* st = smb + s*OSTAGE;
    abase[s] = smem_u32(st)         + ((wm*32 + lrow)*TSTRIDE + lcol)*2;
    bbase[s] = smem_u32(st + BTILE) + ((wn*64 + lrow)*TSTRIDE + lcol)*2;
  }

#pragma unroll
  for (int mt = 0; mt < 2; mt++)
#pragma unroll
    for (int nt = 0; nt < 8; nt++)
#pragma unroll
      for (int q = 0; q < 4; q++) f.c[mt][nt][q] = 0.f;

  {
    uint16_t* st = smb;
    cpa_t128(st,         (const uint16_t*)gA + m0*ldk,    ldk, tid);
    cpa_t128(st + BTILE, (const uint16_t*)gB + n0blk*ldk, ldk, tid);
    CP_COMMIT();
  }

  for (int kc = 0; kc < KCHUNKS; kc++) {
    if (kc + 1 < KCHUNKS) {
      uint16_t* st = smb + ((kc+1)&1)*OSTAGE;
      int co = (kc+1)*64;
      cpa_t128(st,         (const uint16_t*)gA + m0*ldk + co,    ldk, tid);
      cpa_t128(st + BTILE, (const uint16_t*)gB + n0blk*ldk + co, ldk, tid);
      CP_COMMIT();
      CP_WAIT(1);
    } else {
      CP_WAIT(0);
    }
    __syncthreads();

    const int s = kc & 1;
#pragma unroll
    for (int ks = 0; ks < 4; ks++) {
      uint32_t aa[2][4];
#pragma unroll
      for (int mt = 0; mt < 2; mt++) {
        uint32_t off = (mt*16*TSTRIDE + ks*16)*2;
        ldsm_x4(abase[s] + off, aa[mt][0], aa[mt][1], aa[mt][2], aa[mt][3]);
      }
      uint32_t bb[8][2];
#pragma unroll
      for (int np = 0; np < 4; np++) {
        uint32_t off = (np*16*TSTRIDE + ks*16)*2;
        uint32_t r0, r1, r2, r3;
        ldsm_x4(bbase[s] + off, r0, r1, r2, r3);
        bb[2*np][0] = r0; bb[2*np+1][0] = r1; bb[2*np][1] = r2; bb[2*np+1][1] = r3;
      }
#pragma unroll
      for (int mt = 0; mt < 2; mt++)
#pragma unroll
        for (int nt = 0; nt < 8; nt++)
          mma_f16(f.c[mt][nt], aa[mt], bb[nt]);
    }
    __syncthreads();
  }
}

// ---------------------------------------------------------------------------
// Projection GEMM (256 threads, block 128x128)
// ---------------------------------------------------------------------------
__global__ __launch_bounds__(256, 2) void proj_mma_kernel(const float* __restrict__ bg)
{
  extern __shared__ uint16_t smb[];
  const int tid = threadIdx.x;
  const int c0 = blockIdx.x * 128;
  const int m0 = blockIdx.y * 128;

  FragC f;
  gemm_core2<4>(smb, g_xfh, g_xfl, g_Wcf, m0, c0, 256, tid, f);

  const int lane = tid & 31, wid = tid >> 5;
  const int wm = wid & 3, wn = wid >> 2;
  const int q2 = (lane & 3) * 2, r4 = lane >> 2;
  const int seg = c0 >> 9;
  const int lbase = c0 - seg*512 + wn*64;

#pragma unroll
  for (int mt = 0; mt < 2; mt++) {
#pragma unroll
    for (int h2 = 0; h2 < 2; h2++) {
      const int m = m0 + wm*32 + mt*16 + r4 + h2*8;
      const int bidx = m >> 9, n = m & 511;
      if (seg == 3) {
        float* dst = g_G + m*512 + lbase;
#pragma unroll
        for (int nt = 0; nt < 8; nt++) {
          int cc = nt*8 + q2;
          float2 v;
          v.x = f.c[mt][nt][h2*2+0] + bg[lbase + cc];
          v.y = f.c[mt][nt][h2*2+1] + bg[lbase + cc + 1];
          *(float2*)(dst + cc) = v;
        }
      } else if (seg == 0) {
        // Q: fp16 split
        const int hh = lbase >> 6;
        const int off = (((bidx*8 + hh)*512 + n)*64);
#pragma unroll
        for (int nt = 0; nt < 8; nt++) {
          int dd = nt*8 + q2;
          uint32_t ph, pl;
          split2packh(f.c[mt][nt][h2*2+0], f.c[mt][nt][h2*2+1], ph, pl);
          *(uint32_t*)(g_Qh + off + dd) = ph;
          *(uint32_t*)(g_Ql + off + dd) = pl;
        }
      } else {
        // K (seg 1) or V (seg 2): fp16 single
        const int hh = lbase >> 6;
        __half* dst = (seg == 1) ? g_K : g_V;
        const int off = (((bidx*8 + hh)*512 + n)*64);
#pragma unroll
        for (int nt = 0; nt < 8; nt++) {
          int dd = nt*8 + q2;
          *(uint32_t*)(dst + off + dd) =
              pack2f16(f.c[mt][nt][h2*2+0], f.c[mt][nt][h2*2+1]);
        }
      }
    }
  }
}

// ---------------------------------------------------------------------------
// Output GEMM (256 threads, block 128x128, 1-term)
// ---------------------------------------------------------------------------
__global__ __launch_bounds__(256, 2) void out_mma_kernel(
    const float* __restrict__ bo, float* __restrict__ Y)
{
  extern __shared__ uint16_t smb[];
  const int tid = threadIdx.x;
  const int n0 = blockIdx.x * 128;
  const int m0 = blockIdx.y * 128;

  FragC f;
  gemm_core1<8>(smb, g_E, g_Wof, m0, n0, 512, tid, f);

  const int lane = tid & 31, wid = tid >> 5;
  const int wm = wid & 3, wn = wid >> 2;
  const int q2 = (lane & 3) * 2, r4 = lane >> 2;

#pragma unroll
  for (int mt = 0; mt < 2; mt++) {
#pragma unroll
    for (int h2 = 0; h2 < 2; h2++) {
      const int m = m0 + wm*32 + mt*16 + r4 + h2*8;
      float* dst = Y + m*256 + n0 + wn*64;
      const float* bop = bo + n0 + wn*64;
#pragma unroll
      for (int nt = 0; nt < 8; nt++) {
        int cc = nt*8 + q2;
        float2 v;
        v.x = f.c[mt][nt][h2*2+0] + bop[cc];
        v.y = f.c[mt][nt][h2*2+1] + bop[cc + 1];
        *(float2*)(dst + cc) = v;
      }
    }
  }
}

// ---------------------------------------------------------------------------
// Flash attention: QK fp16 (Q split x K single), PV fp16 1-product (V single).
// smem: Qh@0, Ql@ATILE; stage s at (2+s*2)*ATILE: [K, V]. 6 ATILE total.
// ---------------------------------------------------------------------------
__global__ __launch_bounds__(256, 2) void attn_flash_kernel(
    const float* __restrict__ bias)
{
  extern __shared__ uint16_t smbu[];
  uint16_t* Qh = smbu;
  uint16_t* Ql = smbu + ATILE;
  uint16_t* KV = smbu + 2*ATILE;

  const int tid = threadIdx.x;
  const int lane = tid & 31, wid = tid >> 5;
  const int wm = wid & 3, wn = wid >> 2;
  const int lrow = (lane & 7) + ((lane >> 3) & 1) * 8;
  const int lcol = (lane >> 4) * 8;
  const int r4 = lane >> 2, q2 = (lane & 3) * 2;
  const int it0 = blockIdx.x * 64;
  const int h = blockIdx.y, b = blockIdx.z;

  const int bh_off = (b*8 + h) * 512 * 64;
  const uint16_t* Ks = (const uint16_t*)(g_K + bh_off);
  const uint16_t* Vs = (const uint16_t*)(g_V + bh_off);

  cpa_tile64(Qh, (const uint16_t*)(g_Qh + bh_off + it0*64), tid);
  cpa_tile64(Ql, (const uint16_t*)(g_Ql + bh_off + it0*64), tid);
  cpa_tile64(KV,         Ks, tid);
  cpa_tile64(KV + ATILE, Vs, tid);
  CP_COMMIT();

  const uint32_t qh_base = smem_u32(Qh) + ((wm*16 + lrow)*TSTRIDE + lcol)*2;
  const uint32_t ql_base = smem_u32(Ql) + ((wm*16 + lrow)*TSTRIDE + lcol)*2;
  uint32_t kb[2], vb[2];
#pragma unroll
  for (int s = 0; s < 2; s++) {
    uint16_t* st = KV + s*2*ATILE;
    kb[s] = smem_u32(st)         + ((wn*32 + lrow)*TSTRIDE + lcol)*2;
    vb[s] = smem_u32(st + ATILE) + ((wn*32 + lrow)*TSTRIDE + lcol)*2;
  }

  const int row0 = wm*16 + r4;
  const int row1 = row0 + 8;
  const unsigned char* mrow = g_mask + b*512;
  const bool mi0 = mrow[it0 + row0] != 0;
  const bool mi1 = mrow[it0 + row1] != 0;
  const float* brow0 = bias + (h*512 + it0 + row0)*512;
  const float* brow1 = bias + (h*512 + it0 + row1)*512;

  float m0r = -FLT_MAX, m1r = -FLT_MAX, l0r = 0.f, l1r = 0.f;
  float o[8][4];
#pragma unroll
  for (int nf = 0; nf < 8; nf++)
#pragma unroll
    for (int q = 0; q < 4; q++) o[nf][q] = 0.f;

  for (int jt = 0; jt < 8; jt++) {
    if (jt < 7) {
      uint16_t* st = KV + ((jt+1)&1)*2*ATILE;
      const int co = (jt+1)*64*64;
      cpa_tile64(st,         Ks + co, tid);
      cpa_tile64(st + ATILE, Vs + co, tid);
      CP_COMMIT();
      CP_WAIT(1);
    } else {
      CP_WAIT(0);
    }
    __syncthreads();

    const int s = jt & 1;
    // ---- S = Q K^T chunk ----
    float c[4][4];
#pragma unroll
    for (int nf = 0; nf < 4; nf++)
#pragma unroll
      for (int q = 0; q < 4; q++) c[nf][q] = 0.f;

#pragma unroll
    for (int ks = 0; ks < 4; ks++) {
      uint32_t ah[4], al[4];
      ldsm_x4(qh_base + ks*32, ah[0], ah[1], ah[2], ah[3]);
      ldsm_x4(ql_base + ks*32, al[0], al[1], al[2], al[3]);
#pragma unroll
      for (int np = 0; np < 2; np++) {
        uint32_t off = (np*16*TSTRIDE + ks*16)*2;
        uint32_t r0, r1, r2, r3;
        ldsm_x4(kb[s] + off, r0, r1, r2, r3);
        uint32_t b0[2] = {r0, r2}, b1[2] = {r1, r3};
        mma_f16(c[2*np],   ah, b0); mma_f16(c[2*np],   al, b0);
        mma_f16(c[2*np+1], ah, b1); mma_f16(c[2*np+1], al, b1);
      }
    }

    // ---- scale + bias + mask; per-warp row max ----
    const int colbase = jt*64 + wn*32;
    float rm0 = -FLT_MAX, rm1 = -FLT_MAX;
#pragma unroll
    for (int nf = 0; nf < 4; nf++) {
      const int col = colbase + nf*8 + q2;
      float2 b0 = *(const float2*)&brow0[col];
      float2 b1 = *(const float2*)&brow1[col];
      bool mjA = mrow[col] != 0, mjB = mrow[col+1] != 0;
      c[nf][0] = (mi0 && mjA) ? c[nf][0]*SCALE_ + b0.x : -FLT_MAX;
      c[nf][1] = (mi0 && mjB) ? c[nf][1]*SCALE_ + b0.y : -FLT_MAX;
      c[nf][2] = (mi1 && mjA) ? c[nf][2]*SCALE_ + b1.x : -FLT_MAX;
      c[nf][3] = (mi1 && mjB) ? c[nf][3]*SCALE_ + b1.y : -FLT_MAX;
      rm0 = fmaxf(rm0, fmaxf(c[nf][0], c[nf][1]));
      rm1 = fmaxf(rm1, fmaxf(c[nf][2], c[nf][3]));
    }
    rm0 = fmaxf(rm0, __shfl_xor_sync(0xffffffffu, rm0, 1));
    rm0 = fmaxf(rm0, __shfl_xor_sync(0xffffffffu, rm0, 2));
    rm1 = fmaxf(rm1, __shfl_xor_sync(0xffffffffu, rm1, 1));
    rm1 = fmaxf(rm1, __shfl_xor_sync(0xffffffffu, rm1, 2));

    const float mn0 = fmaxf(m0r, rm0), mn1 = fmaxf(m1r, rm1);
    const float fs0 = __expf(m0r - mn0), fs1 = __expf(m1r - mn1);

    float ls0 = 0.f, ls1 = 0.f;
#pragma unroll
    for (int nf = 0; nf < 4; nf++) {
      c[nf][0] = __expf(c[nf][0] - mn0);
      c[nf][1] = __expf(c[nf][1] - mn0);
      c[nf][2] = __expf(c[nf][2] - mn1);
      c[nf][3] = __expf(c[nf][3] - mn1);
      ls0 += c[nf][0] + c[nf][1];
      ls1 += c[nf][2] + c[nf][3];
    }
    ls0 += __shfl_xor_sync(0xffffffffu, ls0, 1);
    ls0 += __shfl_xor_sync(0xffffffffu, ls0, 2);
    ls1 += __shfl_xor_sync(0xffffffffu, ls1, 1);
    ls1 += __shfl_xor_sync(0xffffffffu, ls1, 2);
    l0r = l0r*fs0 + ls0;
    l1r = l1r*fs1 + ls1;
    m0r = mn0; m1r = mn1;

    // ---- rescale O; pack P into fp16 A-fragments ----
#pragma unroll
    for (int nf = 0; nf < 8; nf++) {
      o[nf][0] *= fs0; o[nf][1] *= fs0;
      o[nf][2] *= fs1; o[nf][3] *= fs1;
    }
    uint32_t ap[2][4];
#pragma unroll
    for (int ks2 = 0; ks2 < 2; ks2++) {
      ap[ks2][0] = pack2f16(c[2*ks2][0],   c[2*ks2][1]);
      ap[ks2][1] = pack2f16(c[2*ks2][2],   c[2*ks2][3]);
      ap[ks2][2] = pack2f16(c[2*ks2+1][0], c[2*ks2+1][1]);
      ap[ks2][3] = pack2f16(c[2*ks2+1][2], c[2*ks2+1][3]);
    }

    // ---- O += P V (fp16 1-product) ----
#pragma unroll
    for (int ks2 = 0; ks2 < 2; ks2++) {
      uint32_t bv[8][2];
#pragma unroll
      for (int np = 0; np < 4; np++) {
        uint32_t off = (ks2*16*TSTRIDE + np*16)*2;
        uint32_t r0, r1, r2, r3;
        ldsm_x4_t(vb[s] + off, r0, r1, r2, r3);
        bv[2*np][0] = r0; bv[2*np][1] = r1; bv[2*np+1][0] = r2; bv[2*np+1][1] = r3;
      }
#pragma unroll
      for (int nf = 0; nf < 8; nf++)
        mma_f16(o[nf], ap[ks2], bv[nf]);
    }
    __syncthreads();
  }

  // ---- cross-warp merge (wn=0 <- wn=1), gate, fp16 store ----
  float* O1  = (float*)KV;          // [64][68]
  float* m1s = O1 + 64*68;          // [64]
  float* l1s = m1s + 64;            // [64]

  if (wn == 1) {
#pragma unroll
    for (int nf = 0; nf < 8; nf++) {
      const int d = nf*8 + q2;
      *(float2*)&O1[row0*68 + d] = make_float2(o[nf][0], o[nf][1]);
      *(float2*)&O1[row1*68 + d] = make_float2(o[nf][2], o[nf][3]);
    }
    if ((lane & 3) == 0) {
      m1s[row0] = m0r; l1s[row0] = l0r;
      m1s[row1] = m1r; l1s[row1] = l1r;
    }
  }
  __syncthreads();

  if (wn == 0) {
    const float mo0 = m1s[row0], lo0 = l1s[row0];
    const float mo1 = m1s[row1], lo1 = l1s[row1];
    const float mf0 = fmaxf(m0r, mo0), mf1 = fmaxf(m1r, mo1);
    const float a0 = __expf(m0r - mf0), b0s = __expf(mo0 - mf0);
    const float a1 = __expf(m1r - mf1), b1s = __expf(mo1 - mf1);
    const float inv0 = 1.0f / (l0r*a0 + lo0*b0s);
    const float inv1 = 1.0f / (l1r*a1 + lo1*b1s);

#pragma unroll
    for (int nf = 0; nf < 8; nf++) {
      const int d = nf*8 + q2;
      const int idx0 = (b*512 + it0 + row0)*512 + h*64 + d;
      const int idx1 = (b*512 + it0 + row1)*512 + h*64 + d;
      float2 p0 = *(float2*)&O1[row0*68 + d];
      float2 p1 = *(float2*)&O1[row1*68 + d];
      float2 gv0 = *(const float2*)(g_G + idx0);
      float2 gv1 = *(const float2*)(g_G + idx1);
      float e00 = (o[nf][0]*a0 + p0.x*b0s) * inv0 * gv0.x;
      float e01 = (o[nf][1]*a0 + p0.y*b0s) * inv0 * gv0.y;
      float e10 = (o[nf][2]*a1 + p1.x*b1s) * inv1 * gv1.x;
      float e11 = (o[nf][3]*a1 + p1.y*b1s) * inv1 * gv1.y;
      *(uint32_t*)(g_E + idx0) = pack2f16(e00, e01);
      *(uint32_t*)(g_E + idx1) = pack2f16(e10, e11);
    }
  }
}

// ---------------------------------------------------------------------------
extern "C" void kernel_launch(void* const* d_in, const int* in_sizes, int n_in,
                              void* d_out, int out_size)
{
  const float* x   = (const float*)d_in[0];
  const void*  mask = d_in[1];
  const float* bias = (const float*)d_in[2];
  const float* Wq  = (const float*)d_in[3];
  const float* Wkv = (const float*)d_in[4];
  const float* Wo  = (const float*)d_in[5];
  const float* bo  = (const float*)d_in[6];
  const float* Wg  = (const float*)d_in[7];
  const float* bg  = (const float*)d_in[8];
  float* Y = (float*)d_out;

  const int SMEM_ATTN = 6*ATILE*2;                // 55296 B -> 2 CTAs/SM
  const int SMEM_MMA  = 2*GSTAGE*2;               // 110592 B (proj)
  const int SMEM_OUT  = 2*OSTAGE*2;               // 73728 B (out)
  cudaFuncSetAttribute(attn_flash_kernel, cudaFuncAttributeMaxDynamicSharedMemorySize,
                       SMEM_ATTN);
  cudaFuncSetAttribute(proj_mma_kernel, cudaFuncAttributeMaxDynamicSharedMemorySize,
                       SMEM_MMA);
  cudaFuncSetAttribute(out_mma_kernel, cudaFuncAttributeMaxDynamicSharedMemorySize,
                       SMEM_OUT);

  detect_mask_kernel<<<1, 256>>>((const unsigned int*)mask);
  convert_mask_kernel<<<128, 256>>>(mask);
  split_all_kernel<<<10752, 256>>>(x, Wq, Wkv, Wg, Wo);
  proj_mma_kernel<<<dim3(16, 256), 256, SMEM_MMA>>>(bg);
  attn_flash_kernel<<<dim3(8, 8, 64), 256, SMEM_ATTN>>>(bias);
  out_mma_kernel<<<dim3(2, 256), 256, SMEM_OUT>>>(bo, Y);
}